// round 1
// baseline (speedup 1.0000x reference)
#include <cuda_runtime.h>
#include <cuda_bf16.h>
#include <math.h>

// Problem constants
#define BB   2
#define SS   4096
#define HID  768
#define NL   4
#define NH   12
#define HD   64
#define AW   128          // one-sided window
#define ROWS (BB*SS)      // 8192

// ---------------------------------------------------------------------------
// Scratch (single device global, ~226 MB)
//   h   : ROWS*HID
//   q   : ROWS*HID
//   k   : ROWS*HID
//   v   : ROWS*HID
//   a   : ROWS*HID
//   ffn : ROWS*4*HID
// ---------------------------------------------------------------------------
#define ACT (ROWS*HID)                 // 6291456
__device__ float g_scratch[5*ACT + ROWS*4*HID];

// ---------------------------------------------------------------------------
// Embedding + LayerNorm:  h = LN(emb + pos[s+1] + tok[0]) * g + b
// one block per row, 256 threads, 3 cols/thread
// ---------------------------------------------------------------------------
__global__ __launch_bounds__(256)
void embed_ln_kernel(const float* __restrict__ emb, const float* __restrict__ pos,
                     const float* __restrict__ tok, const float* __restrict__ gam,
                     const float* __restrict__ bet, float* __restrict__ h)
{
    int r = blockIdx.x;
    int s = r & (SS-1);
    __shared__ float xs[HID];
    __shared__ float red[8];
    int t = threadIdx.x;

    float sum = 0.f;
#pragma unroll
    for (int i = 0; i < 3; i++) {
        int c = t + i*256;
        float x = emb[(size_t)r*HID + c] + pos[(size_t)(s+1)*HID + c] + tok[c];
        xs[c] = x; sum += x;
    }
#pragma unroll
    for (int o = 16; o > 0; o >>= 1) sum += __shfl_xor_sync(~0u, sum, o);
    if ((t & 31) == 0) red[t>>5] = sum;
    __syncthreads();
    float tot = 0.f;
#pragma unroll
    for (int i = 0; i < 8; i++) tot += red[i];
    float mean = tot * (1.f/HID);

    float vs = 0.f;
#pragma unroll
    for (int i = 0; i < 3; i++) {
        int c = t + i*256;
        float d = xs[c] - mean; vs += d*d;
    }
    __syncthreads();
#pragma unroll
    for (int o = 16; o > 0; o >>= 1) vs += __shfl_xor_sync(~0u, vs, o);
    if ((t & 31) == 0) red[t>>5] = vs;
    __syncthreads();
    float vtot = 0.f;
#pragma unroll
    for (int i = 0; i < 8; i++) vtot += red[i];
    float inv = rsqrtf(vtot * (1.f/HID) + 1e-12f);

#pragma unroll
    for (int i = 0; i < 3; i++) {
        int c = t + i*256;
        h[(size_t)r*HID + c] = (xs[c] - mean) * inv * gam[c] + bet[c];
    }
}

// ---------------------------------------------------------------------------
// Residual + LayerNorm:  h = LN(hin + tin) * g + b    (in-place safe on hin)
// ---------------------------------------------------------------------------
__global__ __launch_bounds__(256)
void add_ln_kernel(const float* __restrict__ hin, const float* __restrict__ tin,
                   const float* __restrict__ gam, const float* __restrict__ bet,
                   float* __restrict__ hout)
{
    int r = blockIdx.x;
    __shared__ float xs[HID];
    __shared__ float red[8];
    int t = threadIdx.x;

    float sum = 0.f;
#pragma unroll
    for (int i = 0; i < 3; i++) {
        int c = t + i*256;
        float x = hin[(size_t)r*HID + c] + tin[(size_t)r*HID + c];
        xs[c] = x; sum += x;
    }
#pragma unroll
    for (int o = 16; o > 0; o >>= 1) sum += __shfl_xor_sync(~0u, sum, o);
    if ((t & 31) == 0) red[t>>5] = sum;
    __syncthreads();
    float tot = 0.f;
#pragma unroll
    for (int i = 0; i < 8; i++) tot += red[i];
    float mean = tot * (1.f/HID);

    float vs = 0.f;
#pragma unroll
    for (int i = 0; i < 3; i++) {
        int c = t + i*256;
        float d = xs[c] - mean; vs += d*d;
    }
    __syncthreads();
#pragma unroll
    for (int o = 16; o > 0; o >>= 1) vs += __shfl_xor_sync(~0u, vs, o);
    if ((t & 31) == 0) red[t>>5] = vs;
    __syncthreads();
    float vtot = 0.f;
#pragma unroll
    for (int i = 0; i < 8; i++) vtot += red[i];
    float inv = rsqrtf(vtot * (1.f/HID) + 1e-12f);

#pragma unroll
    for (int i = 0; i < 3; i++) {
        int c = t + i*256;
        hout[(size_t)r*HID + c] = (xs[c] - mean) * inv * gam[c] + bet[c];
    }
}

// ---------------------------------------------------------------------------
// Tiled SGEMM:  C[M,N] = act(A[M,K] @ W[K,N] + bias[N])
// 64x64 C tile, TK=16, 256 threads, 4x4 per-thread microtile.
// grid = (N/64, M/64). act: 0 = none, 1 = exact GELU.
// ---------------------------------------------------------------------------
__device__ __forceinline__ float gelu_exact(float x)
{
    return 0.5f * x * (1.f + erff(x * 0.70710678118654752f));
}

__global__ __launch_bounds__(256)
void gemm_kernel(const float* __restrict__ A, const float* __restrict__ W,
                 const float* __restrict__ bias, float* __restrict__ C,
                 int K, int N, int act)
{
    __shared__ float As[16][68];   // [k][m], padded
    __shared__ float Bs[16][64];   // [k][n]
    int bn = blockIdx.x * 64;
    int bm = blockIdx.y * 64;
    int t  = threadIdx.x;
    int tx = t & 15, ty = t >> 4;

    float c[4][4];
#pragma unroll
    for (int i = 0; i < 4; i++)
#pragma unroll
        for (int j = 0; j < 4; j++) c[i][j] = 0.f;

    for (int k0 = 0; k0 < K; k0 += 16) {
        {   // A tile: 64 rows x 16 cols = 256 float4
            int r  = t >> 2;
            int c4 = (t & 3) << 2;
            float4 av = *(const float4*)&A[(size_t)(bm + r)*K + k0 + c4];
            As[c4+0][r] = av.x; As[c4+1][r] = av.y;
            As[c4+2][r] = av.z; As[c4+3][r] = av.w;
        }
        {   // B tile: 16 rows x 64 cols = 256 float4
            int r  = t >> 4;
            int c4 = (t & 15) << 2;
            *(float4*)&Bs[r][c4] = *(const float4*)&W[(size_t)(k0 + r)*N + bn + c4];
        }
        __syncthreads();
#pragma unroll
        for (int kk = 0; kk < 16; kk++) {
            float4 a4 = *(const float4*)&As[kk][ty*4];
            float4 b4 = *(const float4*)&Bs[kk][tx*4];
            float av[4] = {a4.x, a4.y, a4.z, a4.w};
            float bv[4] = {b4.x, b4.y, b4.z, b4.w};
#pragma unroll
            for (int i = 0; i < 4; i++)
#pragma unroll
                for (int j = 0; j < 4; j++) c[i][j] += av[i]*bv[j];
        }
        __syncthreads();
    }

#pragma unroll
    for (int i = 0; i < 4; i++) {
        int row = bm + ty*4 + i;
#pragma unroll
        for (int j = 0; j < 4; j++) {
            int col = bn + tx*4 + j;
            float vv = c[i][j] + bias[col];
            if (act == 1) vv = gelu_exact(vv);
            C[(size_t)row*N + col] = vv;
        }
    }
}

// ---------------------------------------------------------------------------
// Sliding-window attention. One block handles 16 queries of one (b, head).
// Keys needed: [q0-128, q0+160) -> 9 tiles of 32. Band |i-j| <= 128,
// 0 <= j < S, and key_mask[j] != 0. Probabilities for invalid keys are 0.
// grid = (S/16, NH, BB), 256 threads.
// ---------------------------------------------------------------------------
__global__ __launch_bounds__(256)
void attn_kernel(const float* __restrict__ qg, const float* __restrict__ kg,
                 const float* __restrict__ vg, const int* __restrict__ km,
                 float* __restrict__ ag)
{
    int qt   = blockIdx.x;
    int head = blockIdx.y;
    int b    = blockIdx.z;
    int q0   = qt * 16;
    int kbase = q0 - AW;

    __shared__ float sQ[16][64];
    __shared__ float sK[32][65];
    __shared__ float sS[16][288];

    int t = threadIdx.x;

    // Load Q tile, scaled by 1/sqrt(64)
    {
        int row = t >> 4, c4 = (t & 15) << 2;
        const float4 qv = *(const float4*)&qg[((size_t)(b*SS + q0 + row))*HID + head*HD + c4];
        sQ[row][c4+0] = qv.x * 0.125f; sQ[row][c4+1] = qv.y * 0.125f;
        sQ[row][c4+2] = qv.z * 0.125f; sQ[row][c4+3] = qv.w * 0.125f;
    }

    // ---- pass 1: scores ----
    int kq    = t & 31;   // key within tile
    int qrow0 = t >> 5;   // 0..7, handles qrow0 and qrow0+8
    for (int kt = 0; kt < 9; kt++) {
        __syncthreads();
        for (int li = t; li < 512; li += 256) {
            int row = li >> 4, c4 = (li & 15) << 2;
            int jg = kbase + kt*32 + row;
            float4 kv = make_float4(0.f, 0.f, 0.f, 0.f);
            if (jg >= 0 && jg < SS)
                kv = *(const float4*)&kg[((size_t)(b*SS + jg))*HID + head*HD + c4];
            sK[row][c4+0] = kv.x; sK[row][c4+1] = kv.y;
            sK[row][c4+2] = kv.z; sK[row][c4+3] = kv.w;
        }
        __syncthreads();
        float acc0 = 0.f, acc1 = 0.f;
#pragma unroll
        for (int d = 0; d < 64; d++) {
            float kk = sK[kq][d];
            acc0 += sQ[qrow0    ][d] * kk;
            acc1 += sQ[qrow0 + 8][d] * kk;
        }
        sS[qrow0    ][kt*32 + kq] = acc0;
        sS[qrow0 + 8][kt*32 + kq] = acc1;
    }
    __syncthreads();

    // ---- pass 2: masked softmax, one warp per 2 rows ----
    {
        int lane = t & 31, w = t >> 5;
#pragma unroll
        for (int rr = 0; rr < 2; rr++) {
            int qr = w*2 + rr;
            int qi = q0 + qr;
            float mx = -1e30f;
            for (int j = lane; j < 288; j += 32) {
                int jg = kbase + j;
                bool ok = (jg >= 0) && (jg < SS) && (jg >= qi - AW) && (jg <= qi + AW)
                          && (km[b*SS + jg] != 0);
                float sc = ok ? sS[qr][j] : -1e30f;
                sS[qr][j] = sc;
                mx = fmaxf(mx, sc);
            }
#pragma unroll
            for (int o = 16; o > 0; o >>= 1) mx = fmaxf(mx, __shfl_xor_sync(~0u, mx, o));
            float sum = 0.f;
            for (int j = lane; j < 288; j += 32) {
                float p = expf(sS[qr][j] - mx);   // exact 0 for masked (-1e30)
                sS[qr][j] = p; sum += p;
            }
#pragma unroll
            for (int o = 16; o > 0; o >>= 1) sum += __shfl_xor_sync(~0u, sum, o);
            float inv = 1.f / sum;
            for (int j = lane; j < 288; j += 32) sS[qr][j] *= inv;
        }
    }

    // ---- pass 3: out = P @ V ----
    int d  = t & 63;
    int qb = t >> 6;      // 0..3; rows qb, qb+4, qb+8, qb+12
    float acc[4] = {0.f, 0.f, 0.f, 0.f};
    for (int kt = 0; kt < 9; kt++) {
        __syncthreads();
        for (int li = t; li < 512; li += 256) {
            int row = li >> 4, c4 = (li & 15) << 2;
            int jg = kbase + kt*32 + row;
            float4 vv = make_float4(0.f, 0.f, 0.f, 0.f);
            if (jg >= 0 && jg < SS)
                vv = *(const float4*)&vg[((size_t)(b*SS + jg))*HID + head*HD + c4];
            sK[row][c4+0] = vv.x; sK[row][c4+1] = vv.y;
            sK[row][c4+2] = vv.z; sK[row][c4+3] = vv.w;
        }
        __syncthreads();
#pragma unroll
        for (int qq = 0; qq < 4; qq++) {
            int qr = qb + qq*4;
            const float* ps = &sS[qr][kt*32];
            float a0 = 0.f;
#pragma unroll
            for (int j = 0; j < 32; j++) a0 += ps[j] * sK[j][d];
            acc[qq] += a0;
        }
    }
#pragma unroll
    for (int qq = 0; qq < 4; qq++) {
        int qi = q0 + qb + qq*4;
        ag[((size_t)(b*SS + qi))*HID + head*HD + d] = acc[qq];
    }
}

// ---------------------------------------------------------------------------
// Final head: out[r] = sigmoid(h[r] . Wp + bp)
// ---------------------------------------------------------------------------
__global__ __launch_bounds__(256)
void final_kernel(const float* __restrict__ h, const float* __restrict__ Wp,
                  const float* __restrict__ bp, float* __restrict__ out)
{
    int r = blockIdx.x;
    __shared__ float red[8];
    int t = threadIdx.x;
    float sum = 0.f;
#pragma unroll
    for (int i = 0; i < 3; i++) {
        int c = t + i*256;
        sum += h[(size_t)r*HID + c] * Wp[c];
    }
#pragma unroll
    for (int o = 16; o > 0; o >>= 1) sum += __shfl_xor_sync(~0u, sum, o);
    if ((t & 31) == 0) red[t>>5] = sum;
    __syncthreads();
    if (t == 0) {
        float tot = 0.f;
#pragma unroll
        for (int i = 0; i < 8; i++) tot += red[i];
        tot += bp[0];
        out[r] = 1.f / (1.f + expf(-tot));
    }
}

// ---------------------------------------------------------------------------
// Host launcher
// ---------------------------------------------------------------------------
extern "C" void kernel_launch(void* const* d_in, const int* in_sizes, int n_in,
                              void* d_out, int out_size)
{
    (void)in_sizes; (void)n_in;
    const float* emb   = (const float*)d_in[0];
    const int*   amask = (const int*)  d_in[1];
    const float* pos   = (const float*)d_in[2];
    const float* tok   = (const float*)d_in[3];
    const float* eg    = (const float*)d_in[4];
    const float* eb    = (const float*)d_in[5];
    const float* Wq    = (const float*)d_in[6];
    const float* bq    = (const float*)d_in[7];
    const float* Wk    = (const float*)d_in[8];
    const float* bk    = (const float*)d_in[9];
    const float* Wv    = (const float*)d_in[10];
    const float* bv    = (const float*)d_in[11];
    const float* Wo    = (const float*)d_in[12];
    const float* bo    = (const float*)d_in[13];
    const float* ln1g  = (const float*)d_in[14];
    const float* ln1b  = (const float*)d_in[15];
    const float* Wi    = (const float*)d_in[16];
    const float* bi    = (const float*)d_in[17];
    const float* Wf    = (const float*)d_in[18];
    const float* bf    = (const float*)d_in[19];
    const float* ln2g  = (const float*)d_in[20];
    const float* ln2b  = (const float*)d_in[21];
    const float* Wp    = (const float*)d_in[22];
    const float* bp    = (const float*)d_in[23];

    float* scratch = nullptr;
    cudaGetSymbolAddress((void**)&scratch, g_scratch);
    float* h   = scratch;
    float* q   = scratch + 1*(size_t)ACT;
    float* k   = scratch + 2*(size_t)ACT;
    float* v   = scratch + 3*(size_t)ACT;
    float* a   = scratch + 4*(size_t)ACT;
    float* ffn = scratch + 5*(size_t)ACT;   // ROWS*4*HID

    embed_ln_kernel<<<ROWS, 256>>>(emb, pos, tok, eg, eb, h);

    dim3 g768(HID/64, ROWS/64);       // (12, 128)
    dim3 g3072(4*HID/64, ROWS/64);    // (48, 128)
    dim3 gattn(SS/16, NH, BB);

    for (int l = 0; l < NL; l++) {
        const size_t wofs  = (size_t)l * HID * HID;
        const size_t bofs  = (size_t)l * HID;
        const size_t wiofs = (size_t)l * HID * 4*HID;
        const size_t biofs = (size_t)l * 4*HID;

        gemm_kernel<<<g768, 256>>>(h, Wq + wofs, bq + bofs, q, HID, HID, 0);
        gemm_kernel<<<g768, 256>>>(h, Wk + wofs, bk + bofs, k, HID, HID, 0);
        gemm_kernel<<<g768, 256>>>(h, Wv + wofs, bv + bofs, v, HID, HID, 0);

        attn_kernel<<<gattn, 256>>>(q, k, v, amask, a);

        gemm_kernel<<<g768, 256>>>(a, Wo + wofs, bo + bofs, ffn, HID, HID, 0);
        add_ln_kernel<<<ROWS, 256>>>(h, ffn, ln1g + bofs, ln1b + bofs, h);

        gemm_kernel<<<g3072, 256>>>(h, Wi + wiofs, bi + biofs, ffn, HID, 4*HID, 1);
        gemm_kernel<<<g768, 256>>>(ffn, Wf + (size_t)l*4*HID*HID, bf + bofs, q, 4*HID, HID, 0);
        add_ln_kernel<<<ROWS, 256>>>(h, q, ln2g + bofs, ln2b + bofs, h);
    }

    final_kernel<<<ROWS, 256>>>(h, Wp, bp, (float*)d_out);
    (void)out_size;
}

// round 3
// speedup vs baseline: 2.3172x; 2.3172x over previous
#include <cuda_runtime.h>
#include <cuda_bf16.h>
#include <math.h>
#include <stdint.h>

// Problem constants
#define BB   2
#define SS   4096
#define HID  768
#define NL   4
#define NH   12
#define HD   64
#define AW   128
#define ROWS (BB*SS)      // 8192

// ---------------------------------------------------------------------------
// Scratch
// ---------------------------------------------------------------------------
#define ACT (ROWS*HID)                       // 6291456
#define WT_SM (NL*HID*HID)
#define WT_LG (NL*HID*4*HID)
__device__ float g_scratch[9*(size_t)ACT + 4*(size_t)WT_SM + 2*(size_t)WT_LG];

// ---------------------------------------------------------------------------
// helpers
// ---------------------------------------------------------------------------
__device__ __forceinline__ uint32_t smem_u32(const void* p){
    uint32_t a;
    asm("{ .reg .u64 t; cvta.to.shared.u64 t, %1; cvt.u32.u64 %0, t; }" : "=r"(a) : "l"(p));
    return a;
}
#define CP_ASYNC16(dst,src) asm volatile("cp.async.cg.shared.global [%0], [%1], 16;" :: "r"(dst), "l"(src))
#define CP_COMMIT() asm volatile("cp.async.commit_group;" ::: "memory")

__device__ __forceinline__ uint32_t f2tf(float x){
    uint32_t r; asm("cvt.rna.tf32.f32 %0, %1;" : "=r"(r) : "f"(x)); return r;
}
__device__ __forceinline__ void mma_tf32(float* d, const uint32_t* a, const uint32_t* b){
    asm volatile("mma.sync.aligned.m16n8k8.row.col.f32.tf32.tf32.f32 "
        "{%0,%1,%2,%3}, {%4,%5,%6,%7}, {%8,%9}, {%0,%1,%2,%3};"
        : "+f"(d[0]),"+f"(d[1]),"+f"(d[2]),"+f"(d[3])
        : "r"(a[0]),"r"(a[1]),"r"(a[2]),"r"(a[3]), "r"(b[0]),"r"(b[1]));
}
__device__ __forceinline__ float gelu_exact(float x){
    return 0.5f * x * (1.f + erff(x * 0.70710678118654752f));
}

// ---------------------------------------------------------------------------
// tf32 mma.sync GEMM: C[M,N] = act(A[M,K] @ BT[N,K]^T + bias[N])
// 128x128x16 tiles, 8 warps (2x4), warp tile 64x32 of m16n8k8.
// SMEM per stage: A[128][20], B[128][20] floats (stride-20 = conflict-free
// for the m16n8k8 fragment pattern). 3-stage cp.async pipeline.
// ---------------------------------------------------------------------------
#define GBM 128
#define GBN 128
#define GBK 16
#define NSTG 3
#define LDAB 20                               // padded row stride (floats)
#define STG  (2*GBM*LDAB*4)                   // 20480 bytes per stage
#define GEMM_SMEM (NSTG*STG)                  // 61440

__device__ __forceinline__ void load_chunk(const float* __restrict__ A, const float* __restrict__ BT,
                                           int K, int bm, int bn, int c, uint32_t stage)
{
    int t = threadIdx.x;
    const float* asrc = A  + (size_t)bm*K + (size_t)c*GBK;
    const float* bsrc = BT + (size_t)bn*K + (size_t)c*GBK;
#pragma unroll
    for (int i = 0; i < 2; i++){
        int idx = i*256 + t;                 // 0..511
        int row = idx >> 2, seg = idx & 3;
        CP_ASYNC16(stage + row*(LDAB*4) + seg*16, asrc + (size_t)row*K + seg*4);
    }
#pragma unroll
    for (int i = 0; i < 2; i++){
        int idx = i*256 + t;
        int row = idx >> 2, seg = idx & 3;
        CP_ASYNC16(stage + GBM*LDAB*4 + row*(LDAB*4) + seg*16, bsrc + (size_t)row*K + seg*4);
    }
    CP_COMMIT();
}

__global__ __launch_bounds__(256, 2)
void gemm_tc(const float* __restrict__ A, const float* __restrict__ BT,
             const float* __restrict__ bias, float* __restrict__ C,
             int K, int N, int act)
{
    extern __shared__ char smem[];
    uint32_t sb = smem_u32(smem);
    int t = threadIdx.x;
    int wid = t >> 5, lane = t & 31;
    int grp = lane >> 2, q4 = lane & 3;
    int mw = (wid & 1) * 64, nw = (wid >> 1) * 32;
    int bm = blockIdx.y * GBM, bn = blockIdx.x * GBN;

    float acc[4][4][4];
#pragma unroll
    for (int mi = 0; mi < 4; mi++)
#pragma unroll
        for (int ni = 0; ni < 4; ni++)
#pragma unroll
            for (int r = 0; r < 4; r++) acc[mi][ni][r] = 0.f;

    const int NC = K / GBK;

    load_chunk(A, BT, K, bm, bn, 0, sb);
    load_chunk(A, BT, K, bm, bn, 1, sb + STG);

    for (int c = 0; c < NC; c++){
        int slot = c % NSTG;
        if (c + 1 < NC) { asm volatile("cp.async.wait_group 1;" ::: "memory"); }
        else            { asm volatile("cp.async.wait_group 0;" ::: "memory"); }
        __syncthreads();
        if (c + 2 < NC)
            load_chunk(A, BT, K, bm, bn, c + 2, sb + ((c+2)%NSTG)*STG);

        const float* As = (const float*)(smem + slot*STG);
        const float* Bs = As + GBM*LDAB;
#pragma unroll
        for (int ks = 0; ks < 2; ks++){
            int k0 = ks*8;
            uint32_t af[4][4], bf[4][2];
#pragma unroll
            for (int mi = 0; mi < 4; mi++){
                int base = (mw + mi*16 + grp)*LDAB + k0 + q4;
                af[mi][0] = f2tf(As[base]);
                af[mi][1] = f2tf(As[base + 8*LDAB]);
                af[mi][2] = f2tf(As[base + 4]);
                af[mi][3] = f2tf(As[base + 8*LDAB + 4]);
            }
#pragma unroll
            for (int ni = 0; ni < 4; ni++){
                int base = (nw + ni*8 + grp)*LDAB + k0 + q4;
                bf[ni][0] = f2tf(Bs[base]);
                bf[ni][1] = f2tf(Bs[base + 4]);
            }
#pragma unroll
            for (int mi = 0; mi < 4; mi++)
#pragma unroll
                for (int ni = 0; ni < 4; ni++)
                    mma_tf32(acc[mi][ni], af[mi], bf[ni]);
        }
    }

    // epilogue: bias (+gelu), direct register stores
#pragma unroll
    for (int mi = 0; mi < 4; mi++){
        int r0 = bm + mw + mi*16 + grp;
#pragma unroll
        for (int ni = 0; ni < 4; ni++){
            int col = bn + nw + ni*8 + 2*q4;
            float bx = bias[col], by = bias[col+1];
            float2 v0, v1;
            v0.x = acc[mi][ni][0] + bx;  v0.y = acc[mi][ni][1] + by;
            v1.x = acc[mi][ni][2] + bx;  v1.y = acc[mi][ni][3] + by;
            if (act == 1){
                v0.x = gelu_exact(v0.x); v0.y = gelu_exact(v0.y);
                v1.x = gelu_exact(v1.x); v1.y = gelu_exact(v1.y);
            }
            *(float2*)&C[(size_t)r0*N + col]       = v0;
            *(float2*)&C[(size_t)(r0+8)*N + col]   = v1;
        }
    }
}

// ---------------------------------------------------------------------------
// Weight transpose: in [R,C] -> out [C,R], blockIdx.z = layer
// ---------------------------------------------------------------------------
__global__ __launch_bounds__(256)
void transpose_k(const float* __restrict__ in, float* __restrict__ out, int R, int C)
{
    __shared__ float tile[32][33];
    const float* src = in  + (size_t)blockIdx.z * R * C;
    float*       dst = out + (size_t)blockIdx.z * R * C;
    int r0 = blockIdx.y*32, c0 = blockIdx.x*32;
    int tx = threadIdx.x & 31, ty = threadIdx.x >> 5;
#pragma unroll
    for (int i = 0; i < 4; i++)
        tile[ty + i*8][tx] = src[(size_t)(r0 + ty + i*8)*C + c0 + tx];
    __syncthreads();
#pragma unroll
    for (int i = 0; i < 4; i++)
        dst[(size_t)(c0 + ty + i*8)*R + r0 + tx] = tile[tx][ty + i*8];
}

// ---------------------------------------------------------------------------
// Embedding + LayerNorm
// ---------------------------------------------------------------------------
__global__ __launch_bounds__(256)
void embed_ln_kernel(const float* __restrict__ emb, const float* __restrict__ pos,
                     const float* __restrict__ tok, const float* __restrict__ gam,
                     const float* __restrict__ bet, float* __restrict__ h)
{
    int r = blockIdx.x;
    int s = r & (SS-1);
    __shared__ float xs[HID];
    __shared__ float red[8];
    int t = threadIdx.x;

    float sum = 0.f;
#pragma unroll
    for (int i = 0; i < 3; i++) {
        int c = t + i*256;
        float x = emb[(size_t)r*HID + c] + pos[(size_t)(s+1)*HID + c] + tok[c];
        xs[c] = x; sum += x;
    }
#pragma unroll
    for (int o = 16; o > 0; o >>= 1) sum += __shfl_xor_sync(~0u, sum, o);
    if ((t & 31) == 0) red[t>>5] = sum;
    __syncthreads();
    float tot = 0.f;
#pragma unroll
    for (int i = 0; i < 8; i++) tot += red[i];
    float mean = tot * (1.f/HID);

    float vs = 0.f;
#pragma unroll
    for (int i = 0; i < 3; i++) {
        int c = t + i*256;
        float d = xs[c] - mean; vs += d*d;
    }
    __syncthreads();
#pragma unroll
    for (int o = 16; o > 0; o >>= 1) vs += __shfl_xor_sync(~0u, vs, o);
    if ((t & 31) == 0) red[t>>5] = vs;
    __syncthreads();
    float vtot = 0.f;
#pragma unroll
    for (int i = 0; i < 8; i++) vtot += red[i];
    float inv = rsqrtf(vtot * (1.f/HID) + 1e-12f);

#pragma unroll
    for (int i = 0; i < 3; i++) {
        int c = t + i*256;
        h[(size_t)r*HID + c] = (xs[c] - mean) * inv * gam[c] + bet[c];
    }
}

// ---------------------------------------------------------------------------
// Residual + LayerNorm
// ---------------------------------------------------------------------------
__global__ __launch_bounds__(256)
void add_ln_kernel(const float* __restrict__ hin, const float* __restrict__ tin,
                   const float* __restrict__ gam, const float* __restrict__ bet,
                   float* __restrict__ hout)
{
    int r = blockIdx.x;
    __shared__ float xs[HID];
    __shared__ float red[8];
    int t = threadIdx.x;

    float sum = 0.f;
#pragma unroll
    for (int i = 0; i < 3; i++) {
        int c = t + i*256;
        float x = hin[(size_t)r*HID + c] + tin[(size_t)r*HID + c];
        xs[c] = x; sum += x;
    }
#pragma unroll
    for (int o = 16; o > 0; o >>= 1) sum += __shfl_xor_sync(~0u, sum, o);
    if ((t & 31) == 0) red[t>>5] = sum;
    __syncthreads();
    float tot = 0.f;
#pragma unroll
    for (int i = 0; i < 8; i++) tot += red[i];
    float mean = tot * (1.f/HID);

    float vs = 0.f;
#pragma unroll
    for (int i = 0; i < 3; i++) {
        int c = t + i*256;
        float d = xs[c] - mean; vs += d*d;
    }
    __syncthreads();
#pragma unroll
    for (int o = 16; o > 0; o >>= 1) vs += __shfl_xor_sync(~0u, vs, o);
    if ((t & 31) == 0) red[t>>5] = vs;
    __syncthreads();
    float vtot = 0.f;
#pragma unroll
    for (int i = 0; i < 8; i++) vtot += red[i];
    float inv = rsqrtf(vtot * (1.f/HID) + 1e-12f);

#pragma unroll
    for (int i = 0; i < 3; i++) {
        int c = t + i*256;
        hout[(size_t)r*HID + c] = (xs[c] - mean) * inv * gam[c] + bet[c];
    }
}

// ---------------------------------------------------------------------------
// Sliding-window attention (fp32)
// ---------------------------------------------------------------------------
__global__ __launch_bounds__(256)
void attn_kernel(const float* __restrict__ qg, const float* __restrict__ kg,
                 const float* __restrict__ vg, const int* __restrict__ km,
                 float* __restrict__ ag)
{
    int qt   = blockIdx.x;
    int head = blockIdx.y;
    int b    = blockIdx.z;
    int q0   = qt * 16;
    int kbase = q0 - AW;

    __shared__ float sQ[16][64];
    __shared__ float sK[32][65];
    __shared__ float sS[16][288];

    int t = threadIdx.x;

    {
        int row = t >> 4, c4 = (t & 15) << 2;
        const float4 qv = *(const float4*)&qg[((size_t)(b*SS + q0 + row))*HID + head*HD + c4];
        sQ[row][c4+0] = qv.x * 0.125f; sQ[row][c4+1] = qv.y * 0.125f;
        sQ[row][c4+2] = qv.z * 0.125f; sQ[row][c4+3] = qv.w * 0.125f;
    }

    int kq    = t & 31;
    int qrow0 = t >> 5;
    for (int kt = 0; kt < 9; kt++) {
        __syncthreads();
        for (int li = t; li < 512; li += 256) {
            int row = li >> 4, c4 = (li & 15) << 2;
            int jg = kbase + kt*32 + row;
            float4 kv = make_float4(0.f, 0.f, 0.f, 0.f);
            if (jg >= 0 && jg < SS)
                kv = *(const float4*)&kg[((size_t)(b*SS + jg))*HID + head*HD + c4];
            sK[row][c4+0] = kv.x; sK[row][c4+1] = kv.y;
            sK[row][c4+2] = kv.z; sK[row][c4+3] = kv.w;
        }
        __syncthreads();
        float acc0 = 0.f, acc1 = 0.f;
#pragma unroll
        for (int d = 0; d < 64; d++) {
            float kk = sK[kq][d];
            acc0 += sQ[qrow0    ][d] * kk;
            acc1 += sQ[qrow0 + 8][d] * kk;
        }
        sS[qrow0    ][kt*32 + kq] = acc0;
        sS[qrow0 + 8][kt*32 + kq] = acc1;
    }
    __syncthreads();

    {
        int lane = t & 31, w = t >> 5;
#pragma unroll
        for (int rr = 0; rr < 2; rr++) {
            int qr = w*2 + rr;
            int qi = q0 + qr;
            float mx = -1e30f;
            for (int j = lane; j < 288; j += 32) {
                int jg = kbase + j;
                bool ok = (jg >= 0) && (jg < SS) && (jg >= qi - AW) && (jg <= qi + AW)
                          && (km[b*SS + jg] != 0);
                float sc = ok ? sS[qr][j] : -1e30f;
                sS[qr][j] = sc;
                mx = fmaxf(mx, sc);
            }
#pragma unroll
            for (int o = 16; o > 0; o >>= 1) mx = fmaxf(mx, __shfl_xor_sync(~0u, mx, o));
            float sum = 0.f;
            for (int j = lane; j < 288; j += 32) {
                float p = expf(sS[qr][j] - mx);
                sS[qr][j] = p; sum += p;
            }
#pragma unroll
            for (int o = 16; o > 0; o >>= 1) sum += __shfl_xor_sync(~0u, sum, o);
            float inv = 1.f / sum;
            for (int j = lane; j < 288; j += 32) sS[qr][j] *= inv;
        }
    }

    int d  = t & 63;
    int qb = t >> 6;
    float acc[4] = {0.f, 0.f, 0.f, 0.f};
    for (int kt = 0; kt < 9; kt++) {
        __syncthreads();
        for (int li = t; li < 512; li += 256) {
            int row = li >> 4, c4 = (li & 15) << 2;
            int jg = kbase + kt*32 + row;
            float4 vv = make_float4(0.f, 0.f, 0.f, 0.f);
            if (jg >= 0 && jg < SS)
                vv = *(const float4*)&vg[((size_t)(b*SS + jg))*HID + head*HD + c4];
            sK[row][c4+0] = vv.x; sK[row][c4+1] = vv.y;
            sK[row][c4+2] = vv.z; sK[row][c4+3] = vv.w;
        }
        __syncthreads();
#pragma unroll
        for (int qq = 0; qq < 4; qq++) {
            int qr = qb + qq*4;
            const float* ps = &sS[qr][kt*32];
            float a0 = 0.f;
#pragma unroll
            for (int j = 0; j < 32; j++) a0 += ps[j] * sK[j][d];
            acc[qq] += a0;
        }
    }
#pragma unroll
    for (int qq = 0; qq < 4; qq++) {
        int qi = q0 + qb + qq*4;
        ag[((size_t)(b*SS + qi))*HID + head*HD + d] = acc[qq];
    }
}

// ---------------------------------------------------------------------------
// Final head
// ---------------------------------------------------------------------------
__global__ __launch_bounds__(256)
void final_kernel(const float* __restrict__ h, const float* __restrict__ Wp,
                  const float* __restrict__ bp, float* __restrict__ out)
{
    int r = blockIdx.x;
    __shared__ float red[8];
    int t = threadIdx.x;
    float sum = 0.f;
#pragma unroll
    for (int i = 0; i < 3; i++) {
        int c = t + i*256;
        sum += h[(size_t)r*HID + c] * Wp[c];
    }
#pragma unroll
    for (int o = 16; o > 0; o >>= 1) sum += __shfl_xor_sync(~0u, sum, o);
    if ((t & 31) == 0) red[t>>5] = sum;
    __syncthreads();
    if (t == 0) {
        float tot = 0.f;
#pragma unroll
        for (int i = 0; i < 8; i++) tot += red[i];
        tot += bp[0];
        out[r] = 1.f / (1.f + expf(-tot));
    }
}

// ---------------------------------------------------------------------------
// Host launcher
// ---------------------------------------------------------------------------
extern "C" void kernel_launch(void* const* d_in, const int* in_sizes, int n_in,
                              void* d_out, int out_size)
{
    (void)in_sizes; (void)n_in;
    const float* emb   = (const float*)d_in[0];
    const int*   amask = (const int*)  d_in[1];
    const float* pos   = (const float*)d_in[2];
    const float* tok   = (const float*)d_in[3];
    const float* eg    = (const float*)d_in[4];
    const float* eb    = (const float*)d_in[5];
    const float* Wq    = (const float*)d_in[6];
    const float* bq    = (const float*)d_in[7];
    const float* Wk    = (const float*)d_in[8];
    const float* bk    = (const float*)d_in[9];
    const float* Wv    = (const float*)d_in[10];
    const float* bv    = (const float*)d_in[11];
    const float* Wo    = (const float*)d_in[12];
    const float* bo    = (const float*)d_in[13];
    const float* ln1g  = (const float*)d_in[14];
    const float* ln1b  = (const float*)d_in[15];
    const float* Wi    = (const float*)d_in[16];
    const float* bi    = (const float*)d_in[17];
    const float* Wf    = (const float*)d_in[18];
    const float* bf    = (const float*)d_in[19];
    const float* ln2g  = (const float*)d_in[20];
    const float* ln2b  = (const float*)d_in[21];
    const float* Wp    = (const float*)d_in[22];
    const float* bp    = (const float*)d_in[23];

    float* scratch = nullptr;
    cudaGetSymbolAddress((void**)&scratch, g_scratch);
    float* h   = scratch;
    float* q   = scratch + 1*(size_t)ACT;
    float* k   = scratch + 2*(size_t)ACT;
    float* v   = scratch + 3*(size_t)ACT;
    float* a   = scratch + 4*(size_t)ACT;
    float* ffn = scratch + 5*(size_t)ACT;
    float* WqT = scratch + 9*(size_t)ACT;
    float* WkT = WqT + (size_t)WT_SM;
    float* WvT = WkT + (size_t)WT_SM;
    float* WoT = WvT + (size_t)WT_SM;
    float* WiT = WoT + (size_t)WT_SM;
    float* WfT = WiT + (size_t)WT_LG;

    cudaFuncSetAttribute(gemm_tc, cudaFuncAttributeMaxDynamicSharedMemorySize, GEMM_SMEM);

    transpose_k<<<dim3(HID/32, HID/32, NL), 256>>>(Wq, WqT, HID, HID);
    transpose_k<<<dim3(HID/32, HID/32, NL), 256>>>(Wk, WkT, HID, HID);
    transpose_k<<<dim3(HID/32, HID/32, NL), 256>>>(Wv, WvT, HID, HID);
    transpose_k<<<dim3(HID/32, HID/32, NL), 256>>>(Wo, WoT, HID, HID);
    transpose_k<<<dim3(4*HID/32, HID/32, NL), 256>>>(Wi, WiT, HID, 4*HID);
    transpose_k<<<dim3(HID/32, 4*HID/32, NL), 256>>>(Wf, WfT, 4*HID, HID);

    embed_ln_kernel<<<ROWS, 256>>>(emb, pos, tok, eg, eb, h);

    dim3 g768(HID/GBN, ROWS/GBM);      // (6, 64)
    dim3 g3072(4*HID/GBN, ROWS/GBM);   // (24, 64)
    dim3 gattn(SS/16, NH, BB);

    for (int l = 0; l < NL; l++) {
        const size_t wofs  = (size_t)l * HID * HID;
        const size_t bofs  = (size_t)l * HID;
        const size_t wlofs = (size_t)l * HID * 4*HID;
        const size_t blofs = (size_t)l * 4*HID;

        gemm_tc<<<g768, 256, GEMM_SMEM>>>(h, WqT + wofs, bq + bofs, q, HID, HID, 0);
        gemm_tc<<<g768, 256, GEMM_SMEM>>>(h, WkT + wofs, bk + bofs, k, HID, HID, 0);
        gemm_tc<<<g768, 256, GEMM_SMEM>>>(h, WvT + wofs, bv + bofs, v, HID, HID, 0);

        attn_kernel<<<gattn, 256>>>(q, k, v, amask, a);

        gemm_tc<<<g768, 256, GEMM_SMEM>>>(a, WoT + wofs, bo + bofs, ffn, HID, HID, 0);
        add_ln_kernel<<<ROWS, 256>>>(h, ffn, ln1g + bofs, ln1b + bofs, h);

        gemm_tc<<<g3072, 256, GEMM_SMEM>>>(h, WiT + wlofs, bi + blofs, ffn, HID, 4*HID, 1);
        gemm_tc<<<g768, 256, GEMM_SMEM>>>(ffn, WfT + wlofs, bf + bofs, q, 4*HID, HID, 0);
        add_ln_kernel<<<ROWS, 256>>>(h, q, ln2g + bofs, ln2b + bofs, h);
    }

    final_kernel<<<ROWS, 256>>>(h, Wp, bp, (float*)d_out);
    (void)out_size;
}

// round 4
// speedup vs baseline: 2.5737x; 1.1107x over previous
#include <cuda_runtime.h>
#include <cuda_bf16.h>
#include <math.h>
#include <stdint.h>

// Problem constants
#define BB   2
#define SS   4096
#define HID  768
#define NL   4
#define NH   12
#define HD   64
#define AW   128
#define ROWS (BB*SS)      // 8192

// ---------------------------------------------------------------------------
// Scratch
// ---------------------------------------------------------------------------
#define ACT (ROWS*HID)                       // 6291456
#define WT_SM (NL*HID*HID)                   // 2359296
#define WT_LG (NL*HID*4*HID)                 // 9437184
// h(1) qkv(3) a(1) ffn(4) = 9*ACT ; WqkvT = 3*WT_SM ; WoT = WT_SM ; WiT+WfT = 2*WT_LG ; bqkv
__device__ float g_scratch[9*(size_t)ACT + 4*(size_t)WT_SM + 2*(size_t)WT_LG + NL*3*HID];

// ---------------------------------------------------------------------------
// helpers
// ---------------------------------------------------------------------------
__device__ __forceinline__ uint32_t smem_u32(const void* p){
    uint32_t a;
    asm("{ .reg .u64 t; cvta.to.shared.u64 t, %1; cvt.u32.u64 %0, t; }" : "=r"(a) : "l"(p));
    return a;
}
#define CP_ASYNC16(dst,src) asm volatile("cp.async.cg.shared.global [%0], [%1], 16;" :: "r"(dst), "l"(src))
#define CP_COMMIT() asm volatile("cp.async.commit_group;" ::: "memory")

__device__ __forceinline__ void mma_tf32(float* d, const uint32_t* a, const uint32_t* b){
    asm volatile("mma.sync.aligned.m16n8k8.row.col.f32.tf32.tf32.f32 "
        "{%0,%1,%2,%3}, {%4,%5,%6,%7}, {%8,%9}, {%0,%1,%2,%3};"
        : "+f"(d[0]),"+f"(d[1]),"+f"(d[2]),"+f"(d[3])
        : "r"(a[0]),"r"(a[1]),"r"(a[2]),"r"(a[3]), "r"(b[0]),"r"(b[1]));
}
__device__ __forceinline__ float gelu_exact(float x){
    return 0.5f * x * (1.f + erff(x * 0.70710678118654752f));
}

// ---------------------------------------------------------------------------
// tf32 mma.sync GEMM: C[M,N] = act(A[M,K] @ BT[N,K]^T + bias[N])
// 128x128x16 tiles, 8 warps (2x4), warp tile 64x32 of m16n8k8.
// Raw fp32 bits fed to tf32 MMA (HW truncation; no cvt).
// ---------------------------------------------------------------------------
#define GBM 128
#define GBN 128
#define GBK 16
#define NSTG 3
#define LDAB 20
#define STG  (2*GBM*LDAB*4)                   // 20480
#define GEMM_SMEM (NSTG*STG)                  // 61440

__device__ __forceinline__ void load_chunk(const float* __restrict__ A, const float* __restrict__ BT,
                                           int K, int bm, int bn, int c, uint32_t stage)
{
    int t = threadIdx.x;
    const float* asrc = A  + (size_t)bm*K + (size_t)c*GBK;
    const float* bsrc = BT + (size_t)bn*K + (size_t)c*GBK;
#pragma unroll
    for (int i = 0; i < 2; i++){
        int idx = i*256 + t;
        int row = idx >> 2, seg = idx & 3;
        CP_ASYNC16(stage + row*(LDAB*4) + seg*16, asrc + (size_t)row*K + seg*4);
    }
#pragma unroll
    for (int i = 0; i < 2; i++){
        int idx = i*256 + t;
        int row = idx >> 2, seg = idx & 3;
        CP_ASYNC16(stage + GBM*LDAB*4 + row*(LDAB*4) + seg*16, bsrc + (size_t)row*K + seg*4);
    }
    CP_COMMIT();
}

__global__ __launch_bounds__(256, 2)
void gemm_tc(const float* __restrict__ A, const float* __restrict__ BT,
             const float* __restrict__ bias, float* __restrict__ C,
             int K, int N, int act)
{
    extern __shared__ char smem[];
    uint32_t sb = smem_u32(smem);
    int t = threadIdx.x;
    int wid = t >> 5, lane = t & 31;
    int grp = lane >> 2, q4 = lane & 3;
    int mw = (wid & 1) * 64, nw = (wid >> 1) * 32;
    int bm = blockIdx.y * GBM, bn = blockIdx.x * GBN;

    float acc[4][4][4];
#pragma unroll
    for (int mi = 0; mi < 4; mi++)
#pragma unroll
        for (int ni = 0; ni < 4; ni++)
#pragma unroll
            for (int r = 0; r < 4; r++) acc[mi][ni][r] = 0.f;

    const int NC = K / GBK;

    load_chunk(A, BT, K, bm, bn, 0, sb);
    load_chunk(A, BT, K, bm, bn, 1, sb + STG);

    for (int c = 0; c < NC; c++){
        int slot = c % NSTG;
        if (c + 1 < NC) { asm volatile("cp.async.wait_group 1;" ::: "memory"); }
        else            { asm volatile("cp.async.wait_group 0;" ::: "memory"); }
        __syncthreads();
        if (c + 2 < NC)
            load_chunk(A, BT, K, bm, bn, c + 2, sb + ((c+2)%NSTG)*STG);

        const float* As = (const float*)(smem + slot*STG);
        const float* Bs = As + GBM*LDAB;
#pragma unroll
        for (int ks = 0; ks < 2; ks++){
            int k0 = ks*8;
            uint32_t af[4][4], bf[4][2];
#pragma unroll
            for (int mi = 0; mi < 4; mi++){
                int base = (mw + mi*16 + grp)*LDAB + k0 + q4;
                af[mi][0] = __float_as_uint(As[base]);
                af[mi][1] = __float_as_uint(As[base + 8*LDAB]);
                af[mi][2] = __float_as_uint(As[base + 4]);
                af[mi][3] = __float_as_uint(As[base + 8*LDAB + 4]);
            }
#pragma unroll
            for (int ni = 0; ni < 4; ni++){
                int base = (nw + ni*8 + grp)*LDAB + k0 + q4;
                bf[ni][0] = __float_as_uint(Bs[base]);
                bf[ni][1] = __float_as_uint(Bs[base + 4]);
            }
#pragma unroll
            for (int mi = 0; mi < 4; mi++)
#pragma unroll
                for (int ni = 0; ni < 4; ni++)
                    mma_tf32(acc[mi][ni], af[mi], bf[ni]);
        }
    }

#pragma unroll
    for (int mi = 0; mi < 4; mi++){
        int r0 = bm + mw + mi*16 + grp;
#pragma unroll
        for (int ni = 0; ni < 4; ni++){
            int col = bn + nw + ni*8 + 2*q4;
            float bx = bias[col], by = bias[col+1];
            float2 v0, v1;
            v0.x = acc[mi][ni][0] + bx;  v0.y = acc[mi][ni][1] + by;
            v1.x = acc[mi][ni][2] + bx;  v1.y = acc[mi][ni][3] + by;
            if (act == 1){
                v0.x = gelu_exact(v0.x); v0.y = gelu_exact(v0.y);
                v1.x = gelu_exact(v1.x); v1.y = gelu_exact(v1.y);
            }
            *(float2*)&C[(size_t)r0*N + col]     = v0;
            *(float2*)&C[(size_t)(r0+8)*N + col] = v1;
        }
    }
}

// ---------------------------------------------------------------------------
// Weight transpose: in [R,C] (+z*R*C) -> out [C,R] (+z*outStride)
// ---------------------------------------------------------------------------
__global__ __launch_bounds__(256)
void transpose_k(const float* __restrict__ in, float* __restrict__ out,
                 int R, int C, size_t outStride)
{
    __shared__ float tile[32][33];
    const float* src = in  + (size_t)blockIdx.z * R * C;
    float*       dst = out + (size_t)blockIdx.z * outStride;
    int r0 = blockIdx.y*32, c0 = blockIdx.x*32;
    int tx = threadIdx.x & 31, ty = threadIdx.x >> 5;
#pragma unroll
    for (int i = 0; i < 4; i++)
        tile[ty + i*8][tx] = src[(size_t)(r0 + ty + i*8)*C + c0 + tx];
    __syncthreads();
#pragma unroll
    for (int i = 0; i < 4; i++)
        dst[(size_t)(c0 + ty + i*8)*R + r0 + tx] = tile[tx][ty + i*8];
}

__global__ __launch_bounds__(256)
void pack_qkv_bias(const float* __restrict__ bq, const float* __restrict__ bk,
                   const float* __restrict__ bv, float* __restrict__ o)
{
    int l = blockIdx.x, t = threadIdx.x;
    for (int i = t; i < HID; i += 256){
        o[l*3*HID + i]         = bq[l*HID + i];
        o[l*3*HID + HID + i]   = bk[l*HID + i];
        o[l*3*HID + 2*HID + i] = bv[l*HID + i];
    }
}

// ---------------------------------------------------------------------------
// Embedding + LayerNorm
// ---------------------------------------------------------------------------
__global__ __launch_bounds__(256)
void embed_ln_kernel(const float* __restrict__ emb, const float* __restrict__ pos,
                     const float* __restrict__ tok, const float* __restrict__ gam,
                     const float* __restrict__ bet, float* __restrict__ h)
{
    int r = blockIdx.x;
    int s = r & (SS-1);
    __shared__ float xs[HID];
    __shared__ float red[8];
    int t = threadIdx.x;

    float sum = 0.f;
#pragma unroll
    for (int i = 0; i < 3; i++) {
        int c = t + i*256;
        float x = emb[(size_t)r*HID + c] + pos[(size_t)(s+1)*HID + c] + tok[c];
        xs[c] = x; sum += x;
    }
#pragma unroll
    for (int o = 16; o > 0; o >>= 1) sum += __shfl_xor_sync(~0u, sum, o);
    if ((t & 31) == 0) red[t>>5] = sum;
    __syncthreads();
    float tot = 0.f;
#pragma unroll
    for (int i = 0; i < 8; i++) tot += red[i];
    float mean = tot * (1.f/HID);

    float vs = 0.f;
#pragma unroll
    for (int i = 0; i < 3; i++) {
        int c = t + i*256;
        float d = xs[c] - mean; vs += d*d;
    }
    __syncthreads();
#pragma unroll
    for (int o = 16; o > 0; o >>= 1) vs += __shfl_xor_sync(~0u, vs, o);
    if ((t & 31) == 0) red[t>>5] = vs;
    __syncthreads();
    float vtot = 0.f;
#pragma unroll
    for (int i = 0; i < 8; i++) vtot += red[i];
    float inv = rsqrtf(vtot * (1.f/HID) + 1e-12f);

#pragma unroll
    for (int i = 0; i < 3; i++) {
        int c = t + i*256;
        h[(size_t)r*HID + c] = (xs[c] - mean) * inv * gam[c] + bet[c];
    }
}

// ---------------------------------------------------------------------------
// Residual + LayerNorm
// ---------------------------------------------------------------------------
__global__ __launch_bounds__(256)
void add_ln_kernel(const float* __restrict__ hin, const float* __restrict__ tin,
                   const float* __restrict__ gam, const float* __restrict__ bet,
                   float* __restrict__ hout)
{
    int r = blockIdx.x;
    __shared__ float xs[HID];
    __shared__ float red[8];
    int t = threadIdx.x;

    float sum = 0.f;
#pragma unroll
    for (int i = 0; i < 3; i++) {
        int c = t + i*256;
        float x = hin[(size_t)r*HID + c] + tin[(size_t)r*HID + c];
        xs[c] = x; sum += x;
    }
#pragma unroll
    for (int o = 16; o > 0; o >>= 1) sum += __shfl_xor_sync(~0u, sum, o);
    if ((t & 31) == 0) red[t>>5] = sum;
    __syncthreads();
    float tot = 0.f;
#pragma unroll
    for (int i = 0; i < 8; i++) tot += red[i];
    float mean = tot * (1.f/HID);

    float vs = 0.f;
#pragma unroll
    for (int i = 0; i < 3; i++) {
        int c = t + i*256;
        float d = xs[c] - mean; vs += d*d;
    }
    __syncthreads();
#pragma unroll
    for (int o = 16; o > 0; o >>= 1) vs += __shfl_xor_sync(~0u, vs, o);
    if ((t & 31) == 0) red[t>>5] = vs;
    __syncthreads();
    float vtot = 0.f;
#pragma unroll
    for (int i = 0; i < 8; i++) vtot += red[i];
    float inv = rsqrtf(vtot * (1.f/HID) + 1e-12f);

#pragma unroll
    for (int i = 0; i < 3; i++) {
        int c = t + i*256;
        hout[(size_t)r*HID + c] = (xs[c] - mean) * inv * gam[c] + bet[c];
    }
}

// ---------------------------------------------------------------------------
// Sliding-window attention, 32-query tiles, reads packed qkv [ROWS, 2304].
// Keys [q0-128, q0+192) -> 10 tiles of 32. grid = (S/32, NH, BB), 256 thr.
// Dynamic smem: sQ[32][64], sK[32][68], sS[32][320] = 57856 bytes.
// ---------------------------------------------------------------------------
#define QT 32
#define NKT 10
#define ATT_SMEM ((QT*64 + 32*68 + QT*320)*4)

__global__ __launch_bounds__(256)
void attn_kernel(const float* __restrict__ qkv, const int* __restrict__ km,
                 float* __restrict__ ag)
{
    int qt   = blockIdx.x;
    int head = blockIdx.y;
    int b    = blockIdx.z;
    int q0   = qt * QT;
    int kbase = q0 - AW;

    extern __shared__ float sm[];
    float (*sQ)[64]  = (float(*)[64]) sm;
    float (*sK)[68]  = (float(*)[68]) (sm + QT*64);
    float (*sS)[320] = (float(*)[320])(sm + QT*64 + 32*68);

    int t = threadIdx.x;
    const size_t rstr = 3*HID;   // 2304

    // load Q (32 x 64), scaled
    for (int li = t; li < QT*16; li += 256){
        int row = li >> 4, c4 = (li & 15) << 2;
        const float4 qv = *(const float4*)&qkv[((size_t)(b*SS + q0 + row))*rstr + head*HD + c4];
        sQ[row][c4+0] = qv.x * 0.125f; sQ[row][c4+1] = qv.y * 0.125f;
        sQ[row][c4+2] = qv.z * 0.125f; sQ[row][c4+3] = qv.w * 0.125f;
    }

    // ---- pass 1: scores ----
    int kq    = t & 31;
    int qrow0 = t >> 5;   // rows qrow0, +8, +16, +24
    for (int kt = 0; kt < NKT; kt++){
        __syncthreads();
        for (int li = t; li < 512; li += 256){
            int row = li >> 4, c4 = (li & 15) << 2;
            int jg = kbase + kt*32 + row;
            float4 kv = make_float4(0.f,0.f,0.f,0.f);
            if (jg >= 0 && jg < SS)
                kv = *(const float4*)&qkv[((size_t)(b*SS + jg))*rstr + HID + head*HD + c4];
            sK[row][c4+0] = kv.x; sK[row][c4+1] = kv.y;
            sK[row][c4+2] = kv.z; sK[row][c4+3] = kv.w;
        }
        __syncthreads();
        float a0=0.f, a1=0.f, a2=0.f, a3=0.f;
#pragma unroll
        for (int d4 = 0; d4 < 16; d4++){
            float4 kk = *(const float4*)&sK[kq][d4*4];
            float4 qa = *(const float4*)&sQ[qrow0   ][d4*4];
            float4 qb = *(const float4*)&sQ[qrow0+ 8][d4*4];
            float4 qc = *(const float4*)&sQ[qrow0+16][d4*4];
            float4 qd = *(const float4*)&sQ[qrow0+24][d4*4];
            a0 += qa.x*kk.x + qa.y*kk.y + qa.z*kk.z + qa.w*kk.w;
            a1 += qb.x*kk.x + qb.y*kk.y + qb.z*kk.z + qb.w*kk.w;
            a2 += qc.x*kk.x + qc.y*kk.y + qc.z*kk.z + qc.w*kk.w;
            a3 += qd.x*kk.x + qd.y*kk.y + qd.z*kk.z + qd.w*kk.w;
        }
        sS[qrow0   ][kt*32 + kq] = a0;
        sS[qrow0+ 8][kt*32 + kq] = a1;
        sS[qrow0+16][kt*32 + kq] = a2;
        sS[qrow0+24][kt*32 + kq] = a3;
    }
    __syncthreads();

    // ---- pass 2: masked softmax, warp w handles rows w*4..w*4+3 ----
    {
        int lane = t & 31, w = t >> 5;
#pragma unroll
        for (int rr = 0; rr < 4; rr++){
            int qr = w*4 + rr;
            int qi = q0 + qr;
            float mx = -1e30f;
            for (int j = lane; j < 320; j += 32){
                int jg = kbase + j;
                bool ok = (jg >= 0) && (jg < SS) && (jg >= qi - AW) && (jg <= qi + AW)
                          && (km[b*SS + jg] != 0);
                float sc = ok ? sS[qr][j] : -1e30f;
                sS[qr][j] = sc;
                mx = fmaxf(mx, sc);
            }
#pragma unroll
            for (int o = 16; o > 0; o >>= 1) mx = fmaxf(mx, __shfl_xor_sync(~0u, mx, o));
            float sum = 0.f;
            for (int j = lane; j < 320; j += 32){
                float p = expf(sS[qr][j] - mx);
                sS[qr][j] = p; sum += p;
            }
#pragma unroll
            for (int o = 16; o > 0; o >>= 1) sum += __shfl_xor_sync(~0u, sum, o);
            float inv = 1.f / sum;
            for (int j = lane; j < 320; j += 32) sS[qr][j] *= inv;
        }
    }

    // ---- pass 3: out = P @ V ----
    int d  = t & 63;
    int qb4 = t >> 6;   // queries qb4 + 4*qq
    float acc[8];
#pragma unroll
    for (int i = 0; i < 8; i++) acc[i] = 0.f;
    for (int kt = 0; kt < NKT; kt++){
        __syncthreads();
        for (int li = t; li < 512; li += 256){
            int row = li >> 4, c4 = (li & 15) << 2;
            int jg = kbase + kt*32 + row;
            float4 vv = make_float4(0.f,0.f,0.f,0.f);
            if (jg >= 0 && jg < SS)
                vv = *(const float4*)&qkv[((size_t)(b*SS + jg))*rstr + 2*HID + head*HD + c4];
            sK[row][c4+0] = vv.x; sK[row][c4+1] = vv.y;
            sK[row][c4+2] = vv.z; sK[row][c4+3] = vv.w;
        }
        __syncthreads();
#pragma unroll
        for (int qq = 0; qq < 8; qq++){
            int qr = qb4 + qq*4;
            const float* ps = &sS[qr][kt*32];
            float s = 0.f;
#pragma unroll
            for (int j = 0; j < 32; j++) s += ps[j] * sK[j][d];
            acc[qq] += s;
        }
    }
#pragma unroll
    for (int qq = 0; qq < 8; qq++){
        int qi = q0 + qb4 + qq*4;
        ag[((size_t)(b*SS + qi))*HID + head*HD + d] = acc[qq];
    }
}

// ---------------------------------------------------------------------------
// Final head
// ---------------------------------------------------------------------------
__global__ __launch_bounds__(256)
void final_kernel(const float* __restrict__ h, const float* __restrict__ Wp,
                  const float* __restrict__ bp, float* __restrict__ out)
{
    int r = blockIdx.x;
    __shared__ float red[8];
    int t = threadIdx.x;
    float sum = 0.f;
#pragma unroll
    for (int i = 0; i < 3; i++) {
        int c = t + i*256;
        sum += h[(size_t)r*HID + c] * Wp[c];
    }
#pragma unroll
    for (int o = 16; o > 0; o >>= 1) sum += __shfl_xor_sync(~0u, sum, o);
    if ((t & 31) == 0) red[t>>5] = sum;
    __syncthreads();
    if (t == 0) {
        float tot = 0.f;
#pragma unroll
        for (int i = 0; i < 8; i++) tot += red[i];
        tot += bp[0];
        out[r] = 1.f / (1.f + expf(-tot));
    }
}

// ---------------------------------------------------------------------------
// Host launcher
// ---------------------------------------------------------------------------
extern "C" void kernel_launch(void* const* d_in, const int* in_sizes, int n_in,
                              void* d_out, int out_size)
{
    (void)in_sizes; (void)n_in;
    const float* emb   = (const float*)d_in[0];
    const int*   amask = (const int*)  d_in[1];
    const float* pos   = (const float*)d_in[2];
    const float* tok   = (const float*)d_in[3];
    const float* eg    = (const float*)d_in[4];
    const float* eb    = (const float*)d_in[5];
    const float* Wq    = (const float*)d_in[6];
    const float* bq    = (const float*)d_in[7];
    const float* Wk    = (const float*)d_in[8];
    const float* bk    = (const float*)d_in[9];
    const float* Wv    = (const float*)d_in[10];
    const float* bv    = (const float*)d_in[11];
    const float* Wo    = (const float*)d_in[12];
    const float* bo    = (const float*)d_in[13];
    const float* ln1g  = (const float*)d_in[14];
    const float* ln1b  = (const float*)d_in[15];
    const float* Wi    = (const float*)d_in[16];
    const float* bi    = (const float*)d_in[17];
    const float* Wf    = (const float*)d_in[18];
    const float* bf    = (const float*)d_in[19];
    const float* ln2g  = (const float*)d_in[20];
    const float* ln2b  = (const float*)d_in[21];
    const float* Wp    = (const float*)d_in[22];
    const float* bp    = (const float*)d_in[23];

    float* scratch = nullptr;
    cudaGetSymbolAddress((void**)&scratch, g_scratch);
    float* h     = scratch;
    float* qkv   = scratch + 1*(size_t)ACT;     // [ROWS, 2304]
    float* a     = scratch + 4*(size_t)ACT;
    float* ffn   = scratch + 5*(size_t)ACT;     // 4*ACT
    float* tmp   = qkv;                          // reuse qkv after attention
    float* WqkvT = scratch + 9*(size_t)ACT;     // [NL][2304,768]
    float* WoT   = WqkvT + 3*(size_t)WT_SM;
    float* WiT   = WoT   + (size_t)WT_SM;
    float* WfT   = WiT   + (size_t)WT_LG;
    float* bqkv  = WfT   + (size_t)WT_LG;       // [NL][2304]

    cudaFuncSetAttribute(gemm_tc, cudaFuncAttributeMaxDynamicSharedMemorySize, GEMM_SMEM);
    cudaFuncSetAttribute(attn_kernel, cudaFuncAttributeMaxDynamicSharedMemorySize, ATT_SMEM);

    const size_t LSTR = (size_t)3*HID*HID;      // per-layer stride of WqkvT

    transpose_k<<<dim3(HID/32, HID/32, NL), 256>>>(Wq, WqkvT,               HID, HID, LSTR);
    transpose_k<<<dim3(HID/32, HID/32, NL), 256>>>(Wk, WqkvT + (size_t)HID*HID,   HID, HID, LSTR);
    transpose_k<<<dim3(HID/32, HID/32, NL), 256>>>(Wv, WqkvT + (size_t)2*HID*HID, HID, HID, LSTR);
    transpose_k<<<dim3(HID/32, HID/32, NL), 256>>>(Wo, WoT, HID, HID, (size_t)HID*HID);
    transpose_k<<<dim3(4*HID/32, HID/32, NL), 256>>>(Wi, WiT, HID, 4*HID, (size_t)4*HID*HID);
    transpose_k<<<dim3(HID/32, 4*HID/32, NL), 256>>>(Wf, WfT, 4*HID, HID, (size_t)4*HID*HID);
    pack_qkv_bias<<<NL, 256>>>(bq, bk, bv, bqkv);

    embed_ln_kernel<<<ROWS, 256>>>(emb, pos, tok, eg, eb, h);

    dim3 gqkv(3*HID/GBN, ROWS/GBM);    // (18, 64)
    dim3 g768(HID/GBN, ROWS/GBM);      // (6, 64)
    dim3 g3072(4*HID/GBN, ROWS/GBM);   // (24, 64)
    dim3 gattn(SS/QT, NH, BB);         // (128, 12, 2)

    for (int l = 0; l < NL; l++) {
        const size_t wofs  = (size_t)l * HID * HID;
        const size_t bofs  = (size_t)l * HID;
        const size_t wlofs = (size_t)l * HID * 4*HID;
        const size_t blofs = (size_t)l * 4*HID;

        gemm_tc<<<gqkv, 256, GEMM_SMEM>>>(h, WqkvT + l*LSTR, bqkv + l*3*HID, qkv, HID, 3*HID, 0);

        attn_kernel<<<gattn, 256, ATT_SMEM>>>(qkv, amask, a);

        gemm_tc<<<g768, 256, GEMM_SMEM>>>(a, WoT + wofs, bo + bofs, tmp, HID, HID, 0);
        add_ln_kernel<<<ROWS, 256>>>(h, tmp, ln1g + bofs, ln1b + bofs, h);

        gemm_tc<<<g3072, 256, GEMM_SMEM>>>(h, WiT + wlofs, bi + blofs, ffn, HID, 4*HID, 1);
        gemm_tc<<<g768, 256, GEMM_SMEM>>>(ffn, WfT + wlofs, bf + bofs, tmp, 4*HID, HID, 0);
        add_ln_kernel<<<ROWS, 256>>>(h, tmp, ln2g + bofs, ln2b + bofs, h);
    }

    final_kernel<<<ROWS, 256>>>(h, Wp, bp, (float*)d_out);
    (void)out_size;
}

// round 5
// speedup vs baseline: 2.7269x; 1.0595x over previous
#include <cuda_runtime.h>
#include <cuda_bf16.h>
#include <math.h>
#include <stdint.h>

// Problem constants
#define BB   2
#define SS   4096
#define HID  768
#define NL   4
#define NH   12
#define HD   64
#define AW   128
#define ROWS (BB*SS)      // 8192

// ---------------------------------------------------------------------------
// Scratch
// ---------------------------------------------------------------------------
#define ACT (ROWS*HID)                       // 6291456
#define WT_SM (NL*HID*HID)
#define WT_LG (NL*HID*4*HID)
__device__ float g_scratch[9*(size_t)ACT + 4*(size_t)WT_SM + 2*(size_t)WT_LG + NL*3*HID];

// ---------------------------------------------------------------------------
// helpers
// ---------------------------------------------------------------------------
__device__ __forceinline__ uint32_t smem_u32(const void* p){
    uint32_t a;
    asm("{ .reg .u64 t; cvta.to.shared.u64 t, %1; cvt.u32.u64 %0, t; }" : "=r"(a) : "l"(p));
    return a;
}
#define CP_ASYNC16(dst,src) asm volatile("cp.async.cg.shared.global [%0], [%1], 16;" :: "r"(dst), "l"(src))
#define CP_COMMIT() asm volatile("cp.async.commit_group;" ::: "memory")

__device__ __forceinline__ void mma_tf32(float* d, const uint32_t* a, const uint32_t* b){
    asm volatile("mma.sync.aligned.m16n8k8.row.col.f32.tf32.tf32.f32 "
        "{%0,%1,%2,%3}, {%4,%5,%6,%7}, {%8,%9}, {%0,%1,%2,%3};"
        : "+f"(d[0]),"+f"(d[1]),"+f"(d[2]),"+f"(d[3])
        : "r"(a[0]),"r"(a[1]),"r"(a[2]),"r"(a[3]), "r"(b[0]),"r"(b[1]));
}
__device__ __forceinline__ float gelu_exact(float x){
    return 0.5f * x * (1.f + erff(x * 0.70710678118654752f));
}
__device__ __forceinline__ float wred_sum(float v){
#pragma unroll
    for (int o = 16; o > 0; o >>= 1) v += __shfl_xor_sync(~0u, v, o);
    return v;
}

// ---------------------------------------------------------------------------
// tf32 mma.sync GEMM: C[M,N] = act(A[M,K] @ BT[N,K]^T + bias[N])
// 128x128x16 block tile, 128 threads = 4 warps (2x2), warp tile 64x64.
// 3-stage cp.async pipeline, 2 CTAs/SM.
// ---------------------------------------------------------------------------
#define GBM 128
#define GBN 128
#define GBK 16
#define NSTG 3
#define LDAB 20
#define STG  (2*GBM*LDAB*4)                   // 20480
#define GEMM_SMEM (NSTG*STG)                  // 61440

__device__ __forceinline__ void load_chunk(const float* __restrict__ A, const float* __restrict__ BT,
                                           int K, int bm, int bn, int c, uint32_t stage)
{
    int t = threadIdx.x;
    const float* asrc = A  + (size_t)bm*K + (size_t)c*GBK;
    const float* bsrc = BT + (size_t)bn*K + (size_t)c*GBK;
#pragma unroll
    for (int i = 0; i < 4; i++){
        int idx = i*128 + t;                 // 0..511
        int row = idx >> 2, seg = idx & 3;
        CP_ASYNC16(stage + row*(LDAB*4) + seg*16, asrc + (size_t)row*K + seg*4);
    }
#pragma unroll
    for (int i = 0; i < 4; i++){
        int idx = i*128 + t;
        int row = idx >> 2, seg = idx & 3;
        CP_ASYNC16(stage + GBM*LDAB*4 + row*(LDAB*4) + seg*16, bsrc + (size_t)row*K + seg*4);
    }
    CP_COMMIT();
}

__global__ __launch_bounds__(128, 2)
void gemm_tc(const float* __restrict__ A, const float* __restrict__ BT,
             const float* __restrict__ bias, float* __restrict__ C,
             int K, int N, int act)
{
    extern __shared__ char smem[];
    uint32_t sb = smem_u32(smem);
    int t = threadIdx.x;
    int wid = t >> 5, lane = t & 31;
    int grp = lane >> 2, q4 = lane & 3;
    int mw = (wid & 1) * 64, nw = (wid >> 1) * 64;
    int bm = blockIdx.y * GBM, bn = blockIdx.x * GBN;

    float acc[4][8][4];
#pragma unroll
    for (int mi = 0; mi < 4; mi++)
#pragma unroll
        for (int ni = 0; ni < 8; ni++)
#pragma unroll
            for (int r = 0; r < 4; r++) acc[mi][ni][r] = 0.f;

    const int NC = K / GBK;

    load_chunk(A, BT, K, bm, bn, 0, sb);
    load_chunk(A, BT, K, bm, bn, 1, sb + STG);

    for (int c = 0; c < NC; c++){
        int slot = c % NSTG;
        if (c + 1 < NC) { asm volatile("cp.async.wait_group 1;" ::: "memory"); }
        else            { asm volatile("cp.async.wait_group 0;" ::: "memory"); }
        __syncthreads();
        if (c + 2 < NC)
            load_chunk(A, BT, K, bm, bn, c + 2, sb + ((c+2)%NSTG)*STG);

        const float* As = (const float*)(smem + slot*STG);
        const float* Bs = As + GBM*LDAB;
#pragma unroll
        for (int ks = 0; ks < 2; ks++){
            int k0 = ks*8;
            uint32_t af[4][4], bf[8][2];
#pragma unroll
            for (int mi = 0; mi < 4; mi++){
                int base = (mw + mi*16 + grp)*LDAB + k0 + q4;
                af[mi][0] = __float_as_uint(As[base]);
                af[mi][1] = __float_as_uint(As[base + 8*LDAB]);
                af[mi][2] = __float_as_uint(As[base + 4]);
                af[mi][3] = __float_as_uint(As[base + 8*LDAB + 4]);
            }
#pragma unroll
            for (int ni = 0; ni < 8; ni++){
                int base = (nw + ni*8 + grp)*LDAB + k0 + q4;
                bf[ni][0] = __float_as_uint(Bs[base]);
                bf[ni][1] = __float_as_uint(Bs[base + 4]);
            }
#pragma unroll
            for (int mi = 0; mi < 4; mi++)
#pragma unroll
                for (int ni = 0; ni < 8; ni++)
                    mma_tf32(acc[mi][ni], af[mi], bf[ni]);
        }
    }

#pragma unroll
    for (int mi = 0; mi < 4; mi++){
        int r0 = bm + mw + mi*16 + grp;
#pragma unroll
        for (int ni = 0; ni < 8; ni++){
            int col = bn + nw + ni*8 + 2*q4;
            float bx = bias[col], by = bias[col+1];
            float2 v0, v1;
            v0.x = acc[mi][ni][0] + bx;  v0.y = acc[mi][ni][1] + by;
            v1.x = acc[mi][ni][2] + bx;  v1.y = acc[mi][ni][3] + by;
            if (act == 1){
                v0.x = gelu_exact(v0.x); v0.y = gelu_exact(v0.y);
                v1.x = gelu_exact(v1.x); v1.y = gelu_exact(v1.y);
            }
            *(float2*)&C[(size_t)r0*N + col]     = v0;
            *(float2*)&C[(size_t)(r0+8)*N + col] = v1;
        }
    }
}

// ---------------------------------------------------------------------------
// Weight transpose + bias pack
// ---------------------------------------------------------------------------
__global__ __launch_bounds__(256)
void transpose_k(const float* __restrict__ in, float* __restrict__ out,
                 int R, int C, size_t outStride)
{
    __shared__ float tile[32][33];
    const float* src = in  + (size_t)blockIdx.z * R * C;
    float*       dst = out + (size_t)blockIdx.z * outStride;
    int r0 = blockIdx.y*32, c0 = blockIdx.x*32;
    int tx = threadIdx.x & 31, ty = threadIdx.x >> 5;
#pragma unroll
    for (int i = 0; i < 4; i++)
        tile[ty + i*8][tx] = src[(size_t)(r0 + ty + i*8)*C + c0 + tx];
    __syncthreads();
#pragma unroll
    for (int i = 0; i < 4; i++)
        dst[(size_t)(c0 + ty + i*8)*R + r0 + tx] = tile[tx][ty + i*8];
}

__global__ __launch_bounds__(256)
void pack_qkv_bias(const float* __restrict__ bq, const float* __restrict__ bk,
                   const float* __restrict__ bv, float* __restrict__ o)
{
    int l = blockIdx.x, t = threadIdx.x;
    for (int i = t; i < HID; i += 256){
        o[l*3*HID + i]         = bq[l*HID + i];
        o[l*3*HID + HID + i]   = bk[l*HID + i];
        o[l*3*HID + 2*HID + i] = bv[l*HID + i];
    }
}

// ---------------------------------------------------------------------------
// Warp-per-row LayerNorm kernels (8 rows / block of 256 threads)
// ---------------------------------------------------------------------------
__global__ __launch_bounds__(256)
void embed_ln_kernel(const float* __restrict__ emb, const float* __restrict__ pos,
                     const float* __restrict__ tok, const float* __restrict__ gam,
                     const float* __restrict__ bet, float* __restrict__ h)
{
    int w = threadIdx.x >> 5, lane = threadIdx.x & 31;
    int r = blockIdx.x*8 + w;
    int s = r & (SS-1);
    const float* er = emb + (size_t)r*HID;
    const float* pr = pos + (size_t)(s+1)*HID;

    float x[24];
    float sum = 0.f;
#pragma unroll
    for (int i = 0; i < 6; i++){
        int c = i*128 + lane*4;
        float4 e = *(const float4*)&er[c];
        float4 p = *(const float4*)&pr[c];
        float4 tk = *(const float4*)&tok[c];
        x[i*4+0] = e.x + p.x + tk.x;
        x[i*4+1] = e.y + p.y + tk.y;
        x[i*4+2] = e.z + p.z + tk.z;
        x[i*4+3] = e.w + p.w + tk.w;
        sum += x[i*4+0] + x[i*4+1] + x[i*4+2] + x[i*4+3];
    }
    float mean = wred_sum(sum) * (1.f/HID);
    float vs = 0.f;
#pragma unroll
    for (int i = 0; i < 24; i++){ float d = x[i] - mean; vs += d*d; }
    float inv = rsqrtf(wred_sum(vs) * (1.f/HID) + 1e-12f);

    float* hr = h + (size_t)r*HID;
#pragma unroll
    for (int i = 0; i < 6; i++){
        int c = i*128 + lane*4;
        float4 g = *(const float4*)&gam[c];
        float4 b = *(const float4*)&bet[c];
        float4 o;
        o.x = (x[i*4+0] - mean)*inv*g.x + b.x;
        o.y = (x[i*4+1] - mean)*inv*g.y + b.y;
        o.z = (x[i*4+2] - mean)*inv*g.z + b.z;
        o.w = (x[i*4+3] - mean)*inv*g.w + b.w;
        *(float4*)&hr[c] = o;
    }
}

__global__ __launch_bounds__(256)
void add_ln_kernel(const float* __restrict__ hin, const float* __restrict__ tin,
                   const float* __restrict__ gam, const float* __restrict__ bet,
                   float* __restrict__ hout)
{
    int w = threadIdx.x >> 5, lane = threadIdx.x & 31;
    int r = blockIdx.x*8 + w;
    const float* ar = hin + (size_t)r*HID;
    const float* br = tin + (size_t)r*HID;

    float x[24];
    float sum = 0.f;
#pragma unroll
    for (int i = 0; i < 6; i++){
        int c = i*128 + lane*4;
        float4 a = *(const float4*)&ar[c];
        float4 b = *(const float4*)&br[c];
        x[i*4+0] = a.x + b.x; x[i*4+1] = a.y + b.y;
        x[i*4+2] = a.z + b.z; x[i*4+3] = a.w + b.w;
        sum += x[i*4+0] + x[i*4+1] + x[i*4+2] + x[i*4+3];
    }
    float mean = wred_sum(sum) * (1.f/HID);
    float vs = 0.f;
#pragma unroll
    for (int i = 0; i < 24; i++){ float d = x[i] - mean; vs += d*d; }
    float inv = rsqrtf(wred_sum(vs) * (1.f/HID) + 1e-12f);

    float* hr = hout + (size_t)r*HID;
#pragma unroll
    for (int i = 0; i < 6; i++){
        int c = i*128 + lane*4;
        float4 g = *(const float4*)&gam[c];
        float4 b = *(const float4*)&bet[c];
        float4 o;
        o.x = (x[i*4+0] - mean)*inv*g.x + b.x;
        o.y = (x[i*4+1] - mean)*inv*g.y + b.y;
        o.z = (x[i*4+2] - mean)*inv*g.z + b.z;
        o.w = (x[i*4+3] - mean)*inv*g.w + b.w;
        *(float4*)&hr[c] = o;
    }
}

__global__ __launch_bounds__(256)
void final_kernel(const float* __restrict__ h, const float* __restrict__ Wp,
                  const float* __restrict__ bp, float* __restrict__ out)
{
    int w = threadIdx.x >> 5, lane = threadIdx.x & 31;
    int r = blockIdx.x*8 + w;
    const float* hr = h + (size_t)r*HID;
    float sum = 0.f;
#pragma unroll
    for (int i = 0; i < 6; i++){
        int c = i*128 + lane*4;
        float4 a = *(const float4*)&hr[c];
        float4 b = *(const float4*)&Wp[c];
        sum += a.x*b.x + a.y*b.y + a.z*b.z + a.w*b.w;
    }
    sum = wred_sum(sum);
    if (lane == 0) out[r] = 1.f / (1.f + expf(-(sum + bp[0])));
}

// ---------------------------------------------------------------------------
// Sliding-window attention, 32-query tiles, reads packed qkv [ROWS, 2304].
// ---------------------------------------------------------------------------
#define QT 32
#define NKT 10
#define ATT_SMEM ((QT*64 + 32*68 + QT*320)*4)

__global__ __launch_bounds__(256)
void attn_kernel(const float* __restrict__ qkv, const int* __restrict__ km,
                 float* __restrict__ ag)
{
    int qt   = blockIdx.x;
    int head = blockIdx.y;
    int b    = blockIdx.z;
    int q0   = qt * QT;
    int kbase = q0 - AW;

    extern __shared__ float sm[];
    float (*sQ)[64]  = (float(*)[64]) sm;
    float (*sK)[68]  = (float(*)[68]) (sm + QT*64);
    float (*sS)[320] = (float(*)[320])(sm + QT*64 + 32*68);

    int t = threadIdx.x;
    const size_t rstr = 3*HID;

    for (int li = t; li < QT*16; li += 256){
        int row = li >> 4, c4 = (li & 15) << 2;
        const float4 qv = *(const float4*)&qkv[((size_t)(b*SS + q0 + row))*rstr + head*HD + c4];
        sQ[row][c4+0] = qv.x * 0.125f; sQ[row][c4+1] = qv.y * 0.125f;
        sQ[row][c4+2] = qv.z * 0.125f; sQ[row][c4+3] = qv.w * 0.125f;
    }

    int kq    = t & 31;
    int qrow0 = t >> 5;
    for (int kt = 0; kt < NKT; kt++){
        __syncthreads();
        for (int li = t; li < 512; li += 256){
            int row = li >> 4, c4 = (li & 15) << 2;
            int jg = kbase + kt*32 + row;
            float4 kv = make_float4(0.f,0.f,0.f,0.f);
            if (jg >= 0 && jg < SS)
                kv = *(const float4*)&qkv[((size_t)(b*SS + jg))*rstr + HID + head*HD + c4];
            sK[row][c4+0] = kv.x; sK[row][c4+1] = kv.y;
            sK[row][c4+2] = kv.z; sK[row][c4+3] = kv.w;
        }
        __syncthreads();
        float a0=0.f, a1=0.f, a2=0.f, a3=0.f;
#pragma unroll
        for (int d4 = 0; d4 < 16; d4++){
            float4 kk = *(const float4*)&sK[kq][d4*4];
            float4 qa = *(const float4*)&sQ[qrow0   ][d4*4];
            float4 qb = *(const float4*)&sQ[qrow0+ 8][d4*4];
            float4 qc = *(const float4*)&sQ[qrow0+16][d4*4];
            float4 qd = *(const float4*)&sQ[qrow0+24][d4*4];
            a0 += qa.x*kk.x + qa.y*kk.y + qa.z*kk.z + qa.w*kk.w;
            a1 += qb.x*kk.x + qb.y*kk.y + qb.z*kk.z + qb.w*kk.w;
            a2 += qc.x*kk.x + qc.y*kk.y + qc.z*kk.z + qc.w*kk.w;
            a3 += qd.x*kk.x + qd.y*kk.y + qd.z*kk.z + qd.w*kk.w;
        }
        sS[qrow0   ][kt*32 + kq] = a0;
        sS[qrow0+ 8][kt*32 + kq] = a1;
        sS[qrow0+16][kt*32 + kq] = a2;
        sS[qrow0+24][kt*32 + kq] = a3;
    }
    __syncthreads();

    {
        int lane = t & 31, w = t >> 5;
#pragma unroll
        for (int rr = 0; rr < 4; rr++){
            int qr = w*4 + rr;
            int qi = q0 + qr;
            float mx = -1e30f;
            for (int j = lane; j < 320; j += 32){
                int jg = kbase + j;
                bool ok = (jg >= 0) && (jg < SS) && (jg >= qi - AW) && (jg <= qi + AW)
                          && (km[b*SS + jg] != 0);
                float sc = ok ? sS[qr][j] : -1e30f;
                sS[qr][j] = sc;
                mx = fmaxf(mx, sc);
            }
#pragma unroll
            for (int o = 16; o > 0; o >>= 1) mx = fmaxf(mx, __shfl_xor_sync(~0u, mx, o));
            float sum = 0.f;
            for (int j = lane; j < 320; j += 32){
                float p = expf(sS[qr][j] - mx);
                sS[qr][j] = p; sum += p;
            }
#pragma unroll
            for (int o = 16; o > 0; o >>= 1) sum += __shfl_xor_sync(~0u, sum, o);
            float inv = 1.f / sum;
            for (int j = lane; j < 320; j += 32) sS[qr][j] *= inv;
        }
    }

    int d  = t & 63;
    int qb4 = t >> 6;
    float acc[8];
#pragma unroll
    for (int i = 0; i < 8; i++) acc[i] = 0.f;
    for (int kt = 0; kt < NKT; kt++){
        __syncthreads();
        for (int li = t; li < 512; li += 256){
            int row = li >> 4, c4 = (li & 15) << 2;
            int jg = kbase + kt*32 + row;
            float4 vv = make_float4(0.f,0.f,0.f,0.f);
            if (jg >= 0 && jg < SS)
                vv = *(const float4*)&qkv[((size_t)(b*SS + jg))*rstr + 2*HID + head*HD + c4];
            sK[row][c4+0] = vv.x; sK[row][c4+1] = vv.y;
            sK[row][c4+2] = vv.z; sK[row][c4+3] = vv.w;
        }
        __syncthreads();
#pragma unroll
        for (int qq = 0; qq < 8; qq++){
            int qr = qb4 + qq*4;
            const float* ps = &sS[qr][kt*32];
            float s = 0.f;
#pragma unroll
            for (int j = 0; j < 32; j++) s += ps[j] * sK[j][d];
            acc[qq] += s;
        }
    }
#pragma unroll
    for (int qq = 0; qq < 8; qq++){
        int qi = q0 + qb4 + qq*4;
        ag[((size_t)(b*SS + qi))*HID + head*HD + d] = acc[qq];
    }
}

// ---------------------------------------------------------------------------
// Host launcher
// ---------------------------------------------------------------------------
extern "C" void kernel_launch(void* const* d_in, const int* in_sizes, int n_in,
                              void* d_out, int out_size)
{
    (void)in_sizes; (void)n_in;
    const float* emb   = (const float*)d_in[0];
    const int*   amask = (const int*)  d_in[1];
    const float* pos   = (const float*)d_in[2];
    const float* tok   = (const float*)d_in[3];
    const float* eg    = (const float*)d_in[4];
    const float* eb    = (const float*)d_in[5];
    const float* Wq    = (const float*)d_in[6];
    const float* bq    = (const float*)d_in[7];
    const float* Wk    = (const float*)d_in[8];
    const float* bk    = (const float*)d_in[9];
    const float* Wv    = (const float*)d_in[10];
    const float* bv    = (const float*)d_in[11];
    const float* Wo    = (const float*)d_in[12];
    const float* bo    = (const float*)d_in[13];
    const float* ln1g  = (const float*)d_in[14];
    const float* ln1b  = (const float*)d_in[15];
    const float* Wi    = (const float*)d_in[16];
    const float* bi    = (const float*)d_in[17];
    const float* Wf    = (const float*)d_in[18];
    const float* bf    = (const float*)d_in[19];
    const float* ln2g  = (const float*)d_in[20];
    const float* ln2b  = (const float*)d_in[21];
    const float* Wp    = (const float*)d_in[22];
    const float* bp    = (const float*)d_in[23];

    float* scratch = nullptr;
    cudaGetSymbolAddress((void**)&scratch, g_scratch);
    float* h     = scratch;
    float* qkv   = scratch + 1*(size_t)ACT;
    float* a     = scratch + 4*(size_t)ACT;
    float* ffn   = scratch + 5*(size_t)ACT;
    float* tmp   = qkv;
    float* WqkvT = scratch + 9*(size_t)ACT;
    float* WoT   = WqkvT + 3*(size_t)WT_SM;
    float* WiT   = WoT   + (size_t)WT_SM;
    float* WfT   = WiT   + (size_t)WT_LG;
    float* bqkv  = WfT   + (size_t)WT_LG;

    cudaFuncSetAttribute(gemm_tc, cudaFuncAttributeMaxDynamicSharedMemorySize, GEMM_SMEM);
    cudaFuncSetAttribute(attn_kernel, cudaFuncAttributeMaxDynamicSharedMemorySize, ATT_SMEM);

    const size_t LSTR = (size_t)3*HID*HID;

    transpose_k<<<dim3(HID/32, HID/32, NL), 256>>>(Wq, WqkvT,                     HID, HID, LSTR);
    transpose_k<<<dim3(HID/32, HID/32, NL), 256>>>(Wk, WqkvT + (size_t)HID*HID,   HID, HID, LSTR);
    transpose_k<<<dim3(HID/32, HID/32, NL), 256>>>(Wv, WqkvT + (size_t)2*HID*HID, HID, HID, LSTR);
    transpose_k<<<dim3(HID/32, HID/32, NL), 256>>>(Wo, WoT, HID, HID, (size_t)HID*HID);
    transpose_k<<<dim3(4*HID/32, HID/32, NL), 256>>>(Wi, WiT, HID, 4*HID, (size_t)4*HID*HID);
    transpose_k<<<dim3(HID/32, 4*HID/32, NL), 256>>>(Wf, WfT, 4*HID, HID, (size_t)4*HID*HID);
    pack_qkv_bias<<<NL, 256>>>(bq, bk, bv, bqkv);

    embed_ln_kernel<<<ROWS/8, 256>>>(emb, pos, tok, eg, eb, h);

    dim3 gqkv(3*HID/GBN, ROWS/GBM);
    dim3 g768(HID/GBN, ROWS/GBM);
    dim3 g3072(4*HID/GBN, ROWS/GBM);
    dim3 gattn(SS/QT, NH, BB);

    for (int l = 0; l < NL; l++) {
        const size_t wofs  = (size_t)l * HID * HID;
        const size_t bofs  = (size_t)l * HID;
        const size_t wlofs = (size_t)l * HID * 4*HID;
        const size_t blofs = (size_t)l * 4*HID;

        gemm_tc<<<gqkv, 128, GEMM_SMEM>>>(h, WqkvT + l*LSTR, bqkv + l*3*HID, qkv, HID, 3*HID, 0);

        attn_kernel<<<gattn, 256, ATT_SMEM>>>(qkv, amask, a);

        gemm_tc<<<g768, 128, GEMM_SMEM>>>(a, WoT + wofs, bo + bofs, tmp, HID, HID, 0);
        add_ln_kernel<<<ROWS/8, 256>>>(h, tmp, ln1g + bofs, ln1b + bofs, h);

        gemm_tc<<<g3072, 128, GEMM_SMEM>>>(h, WiT + wlofs, bi + blofs, ffn, HID, 4*HID, 1);
        gemm_tc<<<g768, 128, GEMM_SMEM>>>(ffn, WfT + wlofs, bf + bofs, tmp, 4*HID, HID, 0);
        add_ln_kernel<<<ROWS/8, 256>>>(h, tmp, ln2g + bofs, ln2b + bofs, h);
    }

    final_kernel<<<ROWS/8, 256>>>(h, Wp, bp, (float*)d_out);
    (void)out_size;
}

// round 6
// speedup vs baseline: 3.0545x; 1.1202x over previous
#include <cuda_runtime.h>
#include <cuda_bf16.h>
#include <math.h>
#include <stdint.h>

// Problem constants
#define BB   2
#define SS   4096
#define HID  768
#define NL   4
#define NH   12
#define HD   64
#define AW   128
#define ROWS (BB*SS)      // 8192

// ---------------------------------------------------------------------------
// Scratch
// ---------------------------------------------------------------------------
#define ACT (ROWS*HID)
#define WT_SM (NL*HID*HID)
#define WT_LG (NL*HID*4*HID)
__device__ float g_scratch[9*(size_t)ACT + 4*(size_t)WT_SM + 2*(size_t)WT_LG + NL*3*HID];

// ---------------------------------------------------------------------------
// helpers
// ---------------------------------------------------------------------------
__device__ __forceinline__ uint32_t smem_u32(const void* p){
    uint32_t a;
    asm("{ .reg .u64 t; cvta.to.shared.u64 t, %1; cvt.u32.u64 %0, t; }" : "=r"(a) : "l"(p));
    return a;
}
#define CP_ASYNC16(dst,src)      asm volatile("cp.async.cg.shared.global [%0], [%1], 16;" :: "r"(dst), "l"(src))
#define CP_ASYNC16Z(dst,src,nb)  asm volatile("cp.async.cg.shared.global [%0], [%1], 16, %2;" :: "r"(dst), "l"(src), "r"(nb))
#define CP_COMMIT() asm volatile("cp.async.commit_group;" ::: "memory")

__device__ __forceinline__ void mma_tf32(float* d, const uint32_t* a, const uint32_t* b){
    asm volatile("mma.sync.aligned.m16n8k8.row.col.f32.tf32.tf32.f32 "
        "{%0,%1,%2,%3}, {%4,%5,%6,%7}, {%8,%9}, {%0,%1,%2,%3};"
        : "+f"(d[0]),"+f"(d[1]),"+f"(d[2]),"+f"(d[3])
        : "r"(a[0]),"r"(a[1]),"r"(a[2]),"r"(a[3]), "r"(b[0]),"r"(b[1]));
}
__device__ __forceinline__ float gelu_exact(float x){
    return 0.5f * x * (1.f + erff(x * 0.70710678118654752f));
}
__device__ __forceinline__ float wred_sum(float v){
#pragma unroll
    for (int o = 16; o > 0; o >>= 1) v += __shfl_xor_sync(~0u, v, o);
    return v;
}

// ---------------------------------------------------------------------------
// tf32 mma.sync GEMM (unchanged from R5)
// ---------------------------------------------------------------------------
#define GBM 128
#define GBN 128
#define GBK 16
#define NSTG 3
#define LDAB 20
#define STG  (2*GBM*LDAB*4)
#define GEMM_SMEM (NSTG*STG)

__device__ __forceinline__ void load_chunk(const float* __restrict__ A, const float* __restrict__ BT,
                                           int K, int bm, int bn, int c, uint32_t stage)
{
    int t = threadIdx.x;
    const float* asrc = A  + (size_t)bm*K + (size_t)c*GBK;
    const float* bsrc = BT + (size_t)bn*K + (size_t)c*GBK;
#pragma unroll
    for (int i = 0; i < 4; i++){
        int idx = i*128 + t;
        int row = idx >> 2, seg = idx & 3;
        CP_ASYNC16(stage + row*(LDAB*4) + seg*16, asrc + (size_t)row*K + seg*4);
    }
#pragma unroll
    for (int i = 0; i < 4; i++){
        int idx = i*128 + t;
        int row = idx >> 2, seg = idx & 3;
        CP_ASYNC16(stage + GBM*LDAB*4 + row*(LDAB*4) + seg*16, bsrc + (size_t)row*K + seg*4);
    }
    CP_COMMIT();
}

__global__ __launch_bounds__(128, 2)
void gemm_tc(const float* __restrict__ A, const float* __restrict__ BT,
             const float* __restrict__ bias, float* __restrict__ C,
             int K, int N, int act)
{
    extern __shared__ char smem[];
    uint32_t sb = smem_u32(smem);
    int t = threadIdx.x;
    int wid = t >> 5, lane = t & 31;
    int grp = lane >> 2, q4 = lane & 3;
    int mw = (wid & 1) * 64, nw = (wid >> 1) * 64;
    int bm = blockIdx.y * GBM, bn = blockIdx.x * GBN;

    float acc[4][8][4];
#pragma unroll
    for (int mi = 0; mi < 4; mi++)
#pragma unroll
        for (int ni = 0; ni < 8; ni++)
#pragma unroll
            for (int r = 0; r < 4; r++) acc[mi][ni][r] = 0.f;

    const int NC = K / GBK;

    load_chunk(A, BT, K, bm, bn, 0, sb);
    load_chunk(A, BT, K, bm, bn, 1, sb + STG);

    for (int c = 0; c < NC; c++){
        int slot = c % NSTG;
        if (c + 1 < NC) { asm volatile("cp.async.wait_group 1;" ::: "memory"); }
        else            { asm volatile("cp.async.wait_group 0;" ::: "memory"); }
        __syncthreads();
        if (c + 2 < NC)
            load_chunk(A, BT, K, bm, bn, c + 2, sb + ((c+2)%NSTG)*STG);

        const float* As = (const float*)(smem + slot*STG);
        const float* Bs = As + GBM*LDAB;
#pragma unroll
        for (int ks = 0; ks < 2; ks++){
            int k0 = ks*8;
            uint32_t af[4][4], bf[8][2];
#pragma unroll
            for (int mi = 0; mi < 4; mi++){
                int base = (mw + mi*16 + grp)*LDAB + k0 + q4;
                af[mi][0] = __float_as_uint(As[base]);
                af[mi][1] = __float_as_uint(As[base + 8*LDAB]);
                af[mi][2] = __float_as_uint(As[base + 4]);
                af[mi][3] = __float_as_uint(As[base + 8*LDAB + 4]);
            }
#pragma unroll
            for (int ni = 0; ni < 8; ni++){
                int base = (nw + ni*8 + grp)*LDAB + k0 + q4;
                bf[ni][0] = __float_as_uint(Bs[base]);
                bf[ni][1] = __float_as_uint(Bs[base + 4]);
            }
#pragma unroll
            for (int mi = 0; mi < 4; mi++)
#pragma unroll
                for (int ni = 0; ni < 8; ni++)
                    mma_tf32(acc[mi][ni], af[mi], bf[ni]);
        }
    }

#pragma unroll
    for (int mi = 0; mi < 4; mi++){
        int r0 = bm + mw + mi*16 + grp;
#pragma unroll
        for (int ni = 0; ni < 8; ni++){
            int col = bn + nw + ni*8 + 2*q4;
            float bx = bias[col], by = bias[col+1];
            float2 v0, v1;
            v0.x = acc[mi][ni][0] + bx;  v0.y = acc[mi][ni][1] + by;
            v1.x = acc[mi][ni][2] + bx;  v1.y = acc[mi][ni][3] + by;
            if (act == 1){
                v0.x = gelu_exact(v0.x); v0.y = gelu_exact(v0.y);
                v1.x = gelu_exact(v1.x); v1.y = gelu_exact(v1.y);
            }
            *(float2*)&C[(size_t)r0*N + col]     = v0;
            *(float2*)&C[(size_t)(r0+8)*N + col] = v1;
        }
    }
}

// ---------------------------------------------------------------------------
// Weight transpose + bias pack
// ---------------------------------------------------------------------------
__global__ __launch_bounds__(256)
void transpose_k(const float* __restrict__ in, float* __restrict__ out,
                 int R, int C, size_t outStride)
{
    __shared__ float tile[32][33];
    const float* src = in  + (size_t)blockIdx.z * R * C;
    float*       dst = out + (size_t)blockIdx.z * outStride;
    int r0 = blockIdx.y*32, c0 = blockIdx.x*32;
    int tx = threadIdx.x & 31, ty = threadIdx.x >> 5;
#pragma unroll
    for (int i = 0; i < 4; i++)
        tile[ty + i*8][tx] = src[(size_t)(r0 + ty + i*8)*C + c0 + tx];
    __syncthreads();
#pragma unroll
    for (int i = 0; i < 4; i++)
        dst[(size_t)(c0 + ty + i*8)*R + r0 + tx] = tile[tx][ty + i*8];
}

__global__ __launch_bounds__(256)
void pack_qkv_bias(const float* __restrict__ bq, const float* __restrict__ bk,
                   const float* __restrict__ bv, float* __restrict__ o)
{
    int l = blockIdx.x, t = threadIdx.x;
    for (int i = t; i < HID; i += 256){
        o[l*3*HID + i]         = bq[l*HID + i];
        o[l*3*HID + HID + i]   = bk[l*HID + i];
        o[l*3*HID + 2*HID + i] = bv[l*HID + i];
    }
}

// ---------------------------------------------------------------------------
// Warp-per-row LayerNorm kernels
// ---------------------------------------------------------------------------
__global__ __launch_bounds__(256)
void embed_ln_kernel(const float* __restrict__ emb, const float* __restrict__ pos,
                     const float* __restrict__ tok, const float* __restrict__ gam,
                     const float* __restrict__ bet, float* __restrict__ h)
{
    int w = threadIdx.x >> 5, lane = threadIdx.x & 31;
    int r = blockIdx.x*8 + w;
    int s = r & (SS-1);
    const float* er = emb + (size_t)r*HID;
    const float* pr = pos + (size_t)(s+1)*HID;

    float x[24];
    float sum = 0.f;
#pragma unroll
    for (int i = 0; i < 6; i++){
        int c = i*128 + lane*4;
        float4 e = *(const float4*)&er[c];
        float4 p = *(const float4*)&pr[c];
        float4 tk = *(const float4*)&tok[c];
        x[i*4+0] = e.x + p.x + tk.x;
        x[i*4+1] = e.y + p.y + tk.y;
        x[i*4+2] = e.z + p.z + tk.z;
        x[i*4+3] = e.w + p.w + tk.w;
        sum += x[i*4+0] + x[i*4+1] + x[i*4+2] + x[i*4+3];
    }
    float mean = wred_sum(sum) * (1.f/HID);
    float vs = 0.f;
#pragma unroll
    for (int i = 0; i < 24; i++){ float d = x[i] - mean; vs += d*d; }
    float inv = rsqrtf(wred_sum(vs) * (1.f/HID) + 1e-12f);

    float* hr = h + (size_t)r*HID;
#pragma unroll
    for (int i = 0; i < 6; i++){
        int c = i*128 + lane*4;
        float4 g = *(const float4*)&gam[c];
        float4 b = *(const float4*)&bet[c];
        float4 o;
        o.x = (x[i*4+0] - mean)*inv*g.x + b.x;
        o.y = (x[i*4+1] - mean)*inv*g.y + b.y;
        o.z = (x[i*4+2] - mean)*inv*g.z + b.z;
        o.w = (x[i*4+3] - mean)*inv*g.w + b.w;
        *(float4*)&hr[c] = o;
    }
}

__global__ __launch_bounds__(256)
void add_ln_kernel(const float* __restrict__ hin, const float* __restrict__ tin,
                   const float* __restrict__ gam, const float* __restrict__ bet,
                   float* __restrict__ hout)
{
    int w = threadIdx.x >> 5, lane = threadIdx.x & 31;
    int r = blockIdx.x*8 + w;
    const float* ar = hin + (size_t)r*HID;
    const float* br = tin + (size_t)r*HID;

    float x[24];
    float sum = 0.f;
#pragma unroll
    for (int i = 0; i < 6; i++){
        int c = i*128 + lane*4;
        float4 a = *(const float4*)&ar[c];
        float4 b = *(const float4*)&br[c];
        x[i*4+0] = a.x + b.x; x[i*4+1] = a.y + b.y;
        x[i*4+2] = a.z + b.z; x[i*4+3] = a.w + b.w;
        sum += x[i*4+0] + x[i*4+1] + x[i*4+2] + x[i*4+3];
    }
    float mean = wred_sum(sum) * (1.f/HID);
    float vs = 0.f;
#pragma unroll
    for (int i = 0; i < 24; i++){ float d = x[i] - mean; vs += d*d; }
    float inv = rsqrtf(wred_sum(vs) * (1.f/HID) + 1e-12f);

    float* hr = hout + (size_t)r*HID;
#pragma unroll
    for (int i = 0; i < 6; i++){
        int c = i*128 + lane*4;
        float4 g = *(const float4*)&gam[c];
        float4 b = *(const float4*)&bet[c];
        float4 o;
        o.x = (x[i*4+0] - mean)*inv*g.x + b.x;
        o.y = (x[i*4+1] - mean)*inv*g.y + b.y;
        o.z = (x[i*4+2] - mean)*inv*g.z + b.z;
        o.w = (x[i*4+3] - mean)*inv*g.w + b.w;
        *(float4*)&hr[c] = o;
    }
}

__global__ __launch_bounds__(256)
void final_kernel(const float* __restrict__ h, const float* __restrict__ Wp,
                  const float* __restrict__ bp, float* __restrict__ out)
{
    int w = threadIdx.x >> 5, lane = threadIdx.x & 31;
    int r = blockIdx.x*8 + w;
    const float* hr = h + (size_t)r*HID;
    float sum = 0.f;
#pragma unroll
    for (int i = 0; i < 6; i++){
        int c = i*128 + lane*4;
        float4 a = *(const float4*)&hr[c];
        float4 b = *(const float4*)&Wp[c];
        sum += a.x*b.x + a.y*b.y + a.z*b.z + a.w*b.w;
    }
    sum = wred_sum(sum);
    if (lane == 0) out[r] = 1.f / (1.f + expf(-(sum + bp[0])));
}

// ---------------------------------------------------------------------------
// Tensor-core sliding-window attention.
// One block per (b, head, 32-query tile). 256 threads = 8 warps.
// Whole 320-key window in SMEM. QK^T and P@V via m16n8k8 tf32 MMA.
// SMEM (floats): sQ[32][72], sKV[320][72], sS[32][328]  -> 143360 bytes.
// ---------------------------------------------------------------------------
#define QT   32
#define KW   320            // window keys
#define KVS  72             // K/V smem row stride
#define SSTR 328            // scores row stride
#define SQ_OFF  0
#define SKV_OFF (QT*KVS)                 // 2304
#define SS_OFF  (SKV_OFF + KW*KVS)       // 25344
#define ATT_SMEM ((SS_OFF + QT*SSTR)*4)  // 143360

__global__ __launch_bounds__(256)
void attn_kernel(const float* __restrict__ qkv, const int* __restrict__ km,
                 float* __restrict__ ag)
{
    int qt   = blockIdx.x;
    int head = blockIdx.y;
    int b    = blockIdx.z;
    int q0   = qt * QT;
    int kbase = q0 - AW;

    extern __shared__ float sm[];
    float* sQ  = sm + SQ_OFF;
    float* sKV = sm + SKV_OFF;
    float* sS  = sm + SS_OFF;
    uint32_t skv_b = smem_u32(sKV);

    int t = threadIdx.x;
    int wid = t >> 5, lane = t & 31;
    int grp = lane >> 2, q4 = lane & 3;
    const size_t rstr = 3*HID;
    const float* base_b = qkv + (size_t)b*SS*rstr;

    // ---- load Q (scaled) ----
    for (int li = t; li < QT*16; li += 256){
        int row = li >> 4, c4 = (li & 15) << 2;
        const float4 qv = *(const float4*)&base_b[(size_t)(q0 + row)*rstr + head*HD + c4];
        float* d = &sQ[row*KVS + c4];
        d[0] = qv.x * 0.125f; d[1] = qv.y * 0.125f;
        d[2] = qv.z * 0.125f; d[3] = qv.w * 0.125f;
    }

    // ---- load K window via cp.async (zero-fill outside [0,S)) ----
    {
        const float* ksrc = base_b + HID + head*HD;
#pragma unroll
        for (int i = 0; i < 20; i++){
            int idx = i*256 + t;              // 0..5119
            int row = idx >> 4, seg = idx & 15;
            int jg = kbase + row;
            uint32_t nb = (jg >= 0 && jg < SS) ? 16u : 0u;
            int jc = jg < 0 ? 0 : (jg >= SS ? SS-1 : jg);
            CP_ASYNC16Z(skv_b + (row*KVS + seg*4)*4, ksrc + (size_t)jc*rstr + seg*4, nb);
        }
        CP_COMMIT();
    }
    asm volatile("cp.async.wait_group 0;" ::: "memory");
    __syncthreads();

    // ---- QK^T: warp w handles keys [w*40, w*40+40) ----
    {
        float acc[2][5][4];
#pragma unroll
        for (int mi = 0; mi < 2; mi++)
#pragma unroll
            for (int nt = 0; nt < 5; nt++)
#pragma unroll
                for (int r = 0; r < 4; r++) acc[mi][nt][r] = 0.f;

#pragma unroll
        for (int ks = 0; ks < 8; ks++){
            int k0 = ks*8;
            uint32_t af[2][4];
#pragma unroll
            for (int mi = 0; mi < 2; mi++){
                int rbase = (mi*16 + grp)*KVS + k0 + q4;
                af[mi][0] = __float_as_uint(sQ[rbase]);
                af[mi][1] = __float_as_uint(sQ[rbase + 8*KVS]);
                af[mi][2] = __float_as_uint(sQ[rbase + 4]);
                af[mi][3] = __float_as_uint(sQ[rbase + 8*KVS + 4]);
            }
#pragma unroll
            for (int nt = 0; nt < 5; nt++){
                int n0 = wid*40 + nt*8;
                uint32_t bf[2];
                int bbase = (n0 + grp)*KVS + k0 + q4;
                bf[0] = __float_as_uint(sKV[bbase]);
                bf[1] = __float_as_uint(sKV[bbase + 4]);
                mma_tf32(acc[0][nt], af[0], bf);
                mma_tf32(acc[1][nt], af[1], bf);
            }
        }
        // store scores
#pragma unroll
        for (int mi = 0; mi < 2; mi++){
            int r0 = mi*16 + grp;
#pragma unroll
            for (int nt = 0; nt < 5; nt++){
                int col = wid*40 + nt*8 + 2*q4;
                *(float2*)&sS[r0*SSTR + col]     = make_float2(acc[mi][nt][0], acc[mi][nt][1]);
                *(float2*)&sS[(r0+8)*SSTR + col] = make_float2(acc[mi][nt][2], acc[mi][nt][3]);
            }
        }
    }
    __syncthreads();

    // ---- kick off V load (overlaps softmax) ----
    {
        const float* vsrc = base_b + 2*HID + head*HD;
#pragma unroll
        for (int i = 0; i < 20; i++){
            int idx = i*256 + t;
            int row = idx >> 4, seg = idx & 15;
            int jg = kbase + row;
            uint32_t nb = (jg >= 0 && jg < SS) ? 16u : 0u;
            int jc = jg < 0 ? 0 : (jg >= SS ? SS-1 : jg);
            CP_ASYNC16Z(skv_b + (row*KVS + seg*4)*4, vsrc + (size_t)jc*rstr + seg*4, nb);
        }
        CP_COMMIT();
    }

    // ---- masked softmax: warp w rows w*4..w*4+3 ----
    {
#pragma unroll
        for (int rr = 0; rr < 4; rr++){
            int qr = wid*4 + rr;
            int qi = q0 + qr;
            float mx = -1e30f;
            for (int j = lane; j < KW; j += 32){
                int jg = kbase + j;
                bool ok = (jg >= 0) && (jg < SS) && (jg >= qi - AW) && (jg <= qi + AW)
                          && (km[b*SS + jg] != 0);
                float sc = ok ? sS[qr*SSTR + j] : -1e30f;
                sS[qr*SSTR + j] = sc;
                mx = fmaxf(mx, sc);
            }
#pragma unroll
            for (int o = 16; o > 0; o >>= 1) mx = fmaxf(mx, __shfl_xor_sync(~0u, mx, o));
            float sum = 0.f;
            for (int j = lane; j < KW; j += 32){
                float p = __expf(sS[qr*SSTR + j] - mx);
                sS[qr*SSTR + j] = p; sum += p;
            }
#pragma unroll
            for (int o = 16; o > 0; o >>= 1) sum += __shfl_xor_sync(~0u, sum, o);
            float inv = 1.f / sum;
            for (int j = lane; j < KW; j += 32) sS[qr*SSTR + j] *= inv;
        }
    }
    asm volatile("cp.async.wait_group 0;" ::: "memory");
    __syncthreads();

    // ---- P @ V: warp w handles dims [w*8, w*8+8) ----
    {
        int n0 = wid*8;
        float acc[2][4];
#pragma unroll
        for (int mi = 0; mi < 2; mi++)
#pragma unroll
            for (int r = 0; r < 4; r++) acc[mi][r] = 0.f;

#pragma unroll 4
        for (int ks = 0; ks < 40; ks++){
            int k0 = ks*8;
            uint32_t af[2][4], bf[2];
#pragma unroll
            for (int mi = 0; mi < 2; mi++){
                int rbase = (mi*16 + grp)*SSTR + k0 + q4;
                af[mi][0] = __float_as_uint(sS[rbase]);
                af[mi][1] = __float_as_uint(sS[rbase + 8*SSTR]);
                af[mi][2] = __float_as_uint(sS[rbase + 4]);
                af[mi][3] = __float_as_uint(sS[rbase + 8*SSTR + 4]);
            }
            int bbase = (k0 + q4)*KVS + n0 + grp;
            bf[0] = __float_as_uint(sKV[bbase]);
            bf[1] = __float_as_uint(sKV[bbase + 4*KVS]);
            mma_tf32(acc[0], af[0], bf);
            mma_tf32(acc[1], af[1], bf);
        }
        // write out
#pragma unroll
        for (int mi = 0; mi < 2; mi++){
            int r0 = q0 + mi*16 + grp;
            int col = head*HD + n0 + 2*q4;
            *(float2*)&ag[((size_t)(b*SS + r0))*HID + col]     = make_float2(acc[mi][0], acc[mi][1]);
            *(float2*)&ag[((size_t)(b*SS + r0 + 8))*HID + col] = make_float2(acc[mi][2], acc[mi][3]);
        }
    }
}

// ---------------------------------------------------------------------------
// Host launcher
// ---------------------------------------------------------------------------
extern "C" void kernel_launch(void* const* d_in, const int* in_sizes, int n_in,
                              void* d_out, int out_size)
{
    (void)in_sizes; (void)n_in;
    const float* emb   = (const float*)d_in[0];
    const int*   amask = (const int*)  d_in[1];
    const float* pos   = (const float*)d_in[2];
    const float* tok   = (const float*)d_in[3];
    const float* eg    = (const float*)d_in[4];
    const float* eb    = (const float*)d_in[5];
    const float* Wq    = (const float*)d_in[6];
    const float* bq    = (const float*)d_in[7];
    const float* Wk    = (const float*)d_in[8];
    const float* bk    = (const float*)d_in[9];
    const float* Wv    = (const float*)d_in[10];
    const float* bv    = (const float*)d_in[11];
    const float* Wo    = (const float*)d_in[12];
    const float* bo    = (const float*)d_in[13];
    const float* ln1g  = (const float*)d_in[14];
    const float* ln1b  = (const float*)d_in[15];
    const float* Wi    = (const float*)d_in[16];
    const float* bi    = (const float*)d_in[17];
    const float* Wf    = (const float*)d_in[18];
    const float* bf    = (const float*)d_in[19];
    const float* ln2g  = (const float*)d_in[20];
    const float* ln2b  = (const float*)d_in[21];
    const float* Wp    = (const float*)d_in[22];
    const float* bp    = (const float*)d_in[23];

    float* scratch = nullptr;
    cudaGetSymbolAddress((void**)&scratch, g_scratch);
    float* h     = scratch;
    float* qkv   = scratch + 1*(size_t)ACT;
    float* a     = scratch + 4*(size_t)ACT;
    float* ffn   = scratch + 5*(size_t)ACT;
    float* tmp   = qkv;
    float* WqkvT = scratch + 9*(size_t)ACT;
    float* WoT   = WqkvT + 3*(size_t)WT_SM;
    float* WiT   = WoT   + (size_t)WT_SM;
    float* WfT   = WiT   + (size_t)WT_LG;
    float* bqkv  = WfT   + (size_t)WT_LG;

    cudaFuncSetAttribute(gemm_tc, cudaFuncAttributeMaxDynamicSharedMemorySize, GEMM_SMEM);
    cudaFuncSetAttribute(attn_kernel, cudaFuncAttributeMaxDynamicSharedMemorySize, ATT_SMEM);

    const size_t LSTR = (size_t)3*HID*HID;

    transpose_k<<<dim3(HID/32, HID/32, NL), 256>>>(Wq, WqkvT,                     HID, HID, LSTR);
    transpose_k<<<dim3(HID/32, HID/32, NL), 256>>>(Wk, WqkvT + (size_t)HID*HID,   HID, HID, LSTR);
    transpose_k<<<dim3(HID/32, HID/32, NL), 256>>>(Wv, WqkvT + (size_t)2*HID*HID, HID, HID, LSTR);
    transpose_k<<<dim3(HID/32, HID/32, NL), 256>>>(Wo, WoT, HID, HID, (size_t)HID*HID);
    transpose_k<<<dim3(4*HID/32, HID/32, NL), 256>>>(Wi, WiT, HID, 4*HID, (size_t)4*HID*HID);
    transpose_k<<<dim3(HID/32, 4*HID/32, NL), 256>>>(Wf, WfT, 4*HID, HID, (size_t)4*HID*HID);
    pack_qkv_bias<<<NL, 256>>>(bq, bk, bv, bqkv);

    embed_ln_kernel<<<ROWS/8, 256>>>(emb, pos, tok, eg, eb, h);

    dim3 gqkv(3*HID/GBN, ROWS/GBM);
    dim3 g768(HID/GBN, ROWS/GBM);
    dim3 g3072(4*HID/GBN, ROWS/GBM);
    dim3 gattn(SS/QT, NH, BB);

    for (int l = 0; l < NL; l++) {
        const size_t wofs  = (size_t)l * HID * HID;
        const size_t bofs  = (size_t)l * HID;
        const size_t wlofs = (size_t)l * HID * 4*HID;
        const size_t blofs = (size_t)l * 4*HID;

        gemm_tc<<<gqkv, 128, GEMM_SMEM>>>(h, WqkvT + l*LSTR, bqkv + l*3*HID, qkv, HID, 3*HID, 0);

        attn_kernel<<<gattn, 256, ATT_SMEM>>>(qkv, amask, a);

        gemm_tc<<<g768, 128, GEMM_SMEM>>>(a, WoT + wofs, bo + bofs, tmp, HID, HID, 0);
        add_ln_kernel<<<ROWS/8, 256>>>(h, tmp, ln1g + bofs, ln1b + bofs, h);

        gemm_tc<<<g3072, 128, GEMM_SMEM>>>(h, WiT + wlofs, bi + blofs, ffn, HID, 4*HID, 1);
        gemm_tc<<<g768, 128, GEMM_SMEM>>>(ffn, WfT + wlofs, bf + bofs, tmp, 4*HID, HID, 0);
        add_ln_kernel<<<ROWS/8, 256>>>(h, tmp, ln2g + bofs, ln2b + bofs, h);
    }

    final_kernel<<<ROWS/8, 256>>>(h, Wp, bp, (float*)d_out);
    (void)out_size;
}

// round 7
// speedup vs baseline: 4.6533x; 1.5234x over previous
#include <cuda_runtime.h>
#include <cuda_fp16.h>
#include <math.h>
#include <stdint.h>

// Problem constants
#define BB   2
#define SS   4096
#define HID  768
#define NL   4
#define NH   12
#define HD   64
#define AW   128
#define ROWS (BB*SS)      // 8192

// ---------------------------------------------------------------------------
// Scratch (floats; halves are carved out via casts)
// ---------------------------------------------------------------------------
#define ACT (ROWS*HID)
#define WT_SM (NL*HID*HID)
#define WT_LG (NL*HID*4*HID)
__device__ float g_scratch[9*(size_t)ACT + 4*(size_t)WT_SM + 2*(size_t)WT_LG + NL*3*HID];

// ---------------------------------------------------------------------------
// helpers
// ---------------------------------------------------------------------------
__device__ __forceinline__ uint32_t smem_u32(const void* p){
    uint32_t a;
    asm("{ .reg .u64 t; cvta.to.shared.u64 t, %1; cvt.u32.u64 %0, t; }" : "=r"(a) : "l"(p));
    return a;
}
#define CP_ASYNC16(dst,src)      asm volatile("cp.async.cg.shared.global [%0], [%1], 16;" :: "r"(dst), "l"(src))
#define CP_ASYNC16Z(dst,src,nb)  asm volatile("cp.async.cg.shared.global [%0], [%1], 16, %2;" :: "r"(dst), "l"(src), "r"(nb))
#define CP_COMMIT() asm volatile("cp.async.commit_group;" ::: "memory")

__device__ __forceinline__ void mma_tf32(float* d, const uint32_t* a, const uint32_t* b){
    asm volatile("mma.sync.aligned.m16n8k8.row.col.f32.tf32.tf32.f32 "
        "{%0,%1,%2,%3}, {%4,%5,%6,%7}, {%8,%9}, {%0,%1,%2,%3};"
        : "+f"(d[0]),"+f"(d[1]),"+f"(d[2]),"+f"(d[3])
        : "r"(a[0]),"r"(a[1]),"r"(a[2]),"r"(a[3]), "r"(b[0]),"r"(b[1]));
}
__device__ __forceinline__ void mma_f16(float* d, const uint32_t* a, const uint32_t* b){
    asm volatile("mma.sync.aligned.m16n8k16.row.col.f32.f16.f16.f32 "
        "{%0,%1,%2,%3}, {%4,%5,%6,%7}, {%8,%9}, {%0,%1,%2,%3};"
        : "+f"(d[0]),"+f"(d[1]),"+f"(d[2]),"+f"(d[3])
        : "r"(a[0]),"r"(a[1]),"r"(a[2]),"r"(a[3]), "r"(b[0]),"r"(b[1]));
}
__device__ __forceinline__ float gelu_exact(float x){
    return 0.5f * x * (1.f + erff(x * 0.70710678118654752f));
}
__device__ __forceinline__ float wred_sum(float v){
#pragma unroll
    for (int o = 16; o > 0; o >>= 1) v += __shfl_xor_sync(~0u, v, o);
    return v;
}

// ---------------------------------------------------------------------------
// fp16 mma.sync GEMM: C[M,N] = act(A[M,K] @ BT[N,K]^T + bias[N])
// A, BT fp16; C fp32 or fp16 (mode bit1), gelu (mode bit0).
// 128x128 block, 128 thr = 4 warps (2x2), warp tile 64x64 of m16n8k16.
// K chunks of 32 halves; smem rows = 20 uint32 (80B) stride (conflict-free).
// ---------------------------------------------------------------------------
#define GBM 128
#define GBN 128
#define GBK 32
#define NSTG 3
#define LDAB 20                      // uint32 per smem row
#define STG  (2*GBM*LDAB*4)          // 20480 bytes
#define GEMM_SMEM (NSTG*STG)         // 61440

__device__ __forceinline__ void load_chunk16(const __half* __restrict__ A, const __half* __restrict__ BT,
                                             int K, int bm, int bn, int c, uint32_t stage)
{
    int t = threadIdx.x;
    const __half* asrc = A  + (size_t)bm*K + (size_t)c*GBK;
    const __half* bsrc = BT + (size_t)bn*K + (size_t)c*GBK;
#pragma unroll
    for (int i = 0; i < 4; i++){
        int idx = i*128 + t;
        int row = idx >> 2, seg = idx & 3;
        CP_ASYNC16(stage + row*80 + seg*16, asrc + (size_t)row*K + seg*8);
    }
#pragma unroll
    for (int i = 0; i < 4; i++){
        int idx = i*128 + t;
        int row = idx >> 2, seg = idx & 3;
        CP_ASYNC16(stage + GBM*80 + row*80 + seg*16, bsrc + (size_t)row*K + seg*8);
    }
    CP_COMMIT();
}

__global__ __launch_bounds__(128, 2)
void gemm_tc(const __half* __restrict__ A, const __half* __restrict__ BT,
             const float* __restrict__ bias, void* __restrict__ Cv,
             int K, int N, int mode)
{
    extern __shared__ char smem[];
    int t = threadIdx.x;
    int wid = t >> 5, lane = t & 31;
    int grp = lane >> 2, q4 = lane & 3;
    int mw = (wid & 1) * 64, nw = (wid >> 1) * 64;
    int bm = blockIdx.y * GBM, bn = blockIdx.x * GBN;

    float acc[4][8][4];
#pragma unroll
    for (int mi = 0; mi < 4; mi++)
#pragma unroll
        for (int ni = 0; ni < 8; ni++)
#pragma unroll
            for (int r = 0; r < 4; r++) acc[mi][ni][r] = 0.f;

    uint32_t sb = smem_u32(smem);
    const int NC = K / GBK;

    load_chunk16(A, BT, K, bm, bn, 0, sb);
    load_chunk16(A, BT, K, bm, bn, 1, sb + STG);

    for (int c = 0; c < NC; c++){
        int slot = c % NSTG;
        if (c + 1 < NC) { asm volatile("cp.async.wait_group 1;" ::: "memory"); }
        else            { asm volatile("cp.async.wait_group 0;" ::: "memory"); }
        __syncthreads();
        if (c + 2 < NC)
            load_chunk16(A, BT, K, bm, bn, c + 2, sb + ((c+2)%NSTG)*STG);

        const uint32_t* As = (const uint32_t*)(smem + slot*STG);
        const uint32_t* Bs = As + GBM*LDAB;
#pragma unroll
        for (int ks = 0; ks < 2; ks++){
            int k0 = ks*8;      // uint32 offset (16 halves)
            uint32_t af[4][4], bf[8][2];
#pragma unroll
            for (int mi = 0; mi < 4; mi++){
                int base = (mw + mi*16 + grp)*LDAB + k0 + q4;
                af[mi][0] = As[base];
                af[mi][1] = As[base + 8*LDAB];
                af[mi][2] = As[base + 4];
                af[mi][3] = As[base + 8*LDAB + 4];
            }
#pragma unroll
            for (int ni = 0; ni < 8; ni++){
                int base = (nw + ni*8 + grp)*LDAB + k0 + q4;
                bf[ni][0] = Bs[base];
                bf[ni][1] = Bs[base + 4];
            }
#pragma unroll
            for (int mi = 0; mi < 4; mi++)
#pragma unroll
                for (int ni = 0; ni < 8; ni++)
                    mma_f16(acc[mi][ni], af[mi], bf[ni]);
        }
    }

    float* Cf = (float*)Cv;
    __half* Ch = (__half*)Cv;
#pragma unroll
    for (int mi = 0; mi < 4; mi++){
        int r0 = bm + mw + mi*16 + grp;
#pragma unroll
        for (int ni = 0; ni < 8; ni++){
            int col = bn + nw + ni*8 + 2*q4;
            float bx = bias[col], by = bias[col+1];
            float a0 = acc[mi][ni][0] + bx, a1 = acc[mi][ni][1] + by;
            float a2 = acc[mi][ni][2] + bx, a3 = acc[mi][ni][3] + by;
            if (mode & 1){
                a0 = gelu_exact(a0); a1 = gelu_exact(a1);
                a2 = gelu_exact(a2); a3 = gelu_exact(a3);
            }
            if (mode & 2){
                *(__half2*)&Ch[(size_t)r0*N + col]     = __floats2half2_rn(a0, a1);
                *(__half2*)&Ch[(size_t)(r0+8)*N + col] = __floats2half2_rn(a2, a3);
            } else {
                *(float2*)&Cf[(size_t)r0*N + col]     = make_float2(a0, a1);
                *(float2*)&Cf[(size_t)(r0+8)*N + col] = make_float2(a2, a3);
            }
        }
    }
}

// ---------------------------------------------------------------------------
// Weight transpose to fp16: in fp32 [R,C] (+z*R*C) -> out fp16 [C,R] (+z*outStride)
// ---------------------------------------------------------------------------
__global__ __launch_bounds__(256)
void transpose_h(const float* __restrict__ in, __half* __restrict__ out,
                 int R, int C, size_t outStride)
{
    __shared__ float tile[32][33];
    const float* src = in  + (size_t)blockIdx.z * R * C;
    __half*      dst = out + (size_t)blockIdx.z * outStride;
    int r0 = blockIdx.y*32, c0 = blockIdx.x*32;
    int tx = threadIdx.x & 31, ty = threadIdx.x >> 5;
#pragma unroll
    for (int i = 0; i < 4; i++)
        tile[ty + i*8][tx] = src[(size_t)(r0 + ty + i*8)*C + c0 + tx];
    __syncthreads();
#pragma unroll
    for (int i = 0; i < 4; i++)
        dst[(size_t)(c0 + ty + i*8)*R + r0 + tx] = __float2half(tile[tx][ty + i*8]);
}

__global__ __launch_bounds__(256)
void pack_qkv_bias(const float* __restrict__ bq, const float* __restrict__ bk,
                   const float* __restrict__ bv, float* __restrict__ o)
{
    int l = blockIdx.x, t = threadIdx.x;
    for (int i = t; i < HID; i += 256){
        o[l*3*HID + i]         = bq[l*HID + i];
        o[l*3*HID + HID + i]   = bk[l*HID + i];
        o[l*3*HID + 2*HID + i] = bv[l*HID + i];
    }
}

// ---------------------------------------------------------------------------
// Warp-per-row LayerNorm kernels; emit fp32 + fp16 shadow
// ---------------------------------------------------------------------------
__global__ __launch_bounds__(256)
void embed_ln_kernel(const float* __restrict__ emb, const float* __restrict__ pos,
                     const float* __restrict__ tok, const float* __restrict__ gam,
                     const float* __restrict__ bet, float* __restrict__ h,
                     __half* __restrict__ h16)
{
    int w = threadIdx.x >> 5, lane = threadIdx.x & 31;
    int r = blockIdx.x*8 + w;
    int s = r & (SS-1);
    const float* er = emb + (size_t)r*HID;
    const float* pr = pos + (size_t)(s+1)*HID;

    float x[24];
    float sum = 0.f;
#pragma unroll
    for (int i = 0; i < 6; i++){
        int c = i*128 + lane*4;
        float4 e = *(const float4*)&er[c];
        float4 p = *(const float4*)&pr[c];
        float4 tk = *(const float4*)&tok[c];
        x[i*4+0] = e.x + p.x + tk.x;
        x[i*4+1] = e.y + p.y + tk.y;
        x[i*4+2] = e.z + p.z + tk.z;
        x[i*4+3] = e.w + p.w + tk.w;
        sum += x[i*4+0] + x[i*4+1] + x[i*4+2] + x[i*4+3];
    }
    float mean = wred_sum(sum) * (1.f/HID);
    float vs = 0.f;
#pragma unroll
    for (int i = 0; i < 24; i++){ float d = x[i] - mean; vs += d*d; }
    float inv = rsqrtf(wred_sum(vs) * (1.f/HID) + 1e-12f);

    float* hr = h + (size_t)r*HID;
    __half* h16r = h16 + (size_t)r*HID;
#pragma unroll
    for (int i = 0; i < 6; i++){
        int c = i*128 + lane*4;
        float4 g = *(const float4*)&gam[c];
        float4 b = *(const float4*)&bet[c];
        float4 o;
        o.x = (x[i*4+0] - mean)*inv*g.x + b.x;
        o.y = (x[i*4+1] - mean)*inv*g.y + b.y;
        o.z = (x[i*4+2] - mean)*inv*g.z + b.z;
        o.w = (x[i*4+3] - mean)*inv*g.w + b.w;
        *(float4*)&hr[c] = o;
        *(__half2*)&h16r[c]   = __floats2half2_rn(o.x, o.y);
        *(__half2*)&h16r[c+2] = __floats2half2_rn(o.z, o.w);
    }
}

__global__ __launch_bounds__(256)
void add_ln_kernel(const float* __restrict__ hin, const float* __restrict__ tin,
                   const float* __restrict__ gam, const float* __restrict__ bet,
                   float* __restrict__ hout, __half* __restrict__ h16)
{
    int w = threadIdx.x >> 5, lane = threadIdx.x & 31;
    int r = blockIdx.x*8 + w;
    const float* ar = hin + (size_t)r*HID;
    const float* br = tin + (size_t)r*HID;

    float x[24];
    float sum = 0.f;
#pragma unroll
    for (int i = 0; i < 6; i++){
        int c = i*128 + lane*4;
        float4 a = *(const float4*)&ar[c];
        float4 b = *(const float4*)&br[c];
        x[i*4+0] = a.x + b.x; x[i*4+1] = a.y + b.y;
        x[i*4+2] = a.z + b.z; x[i*4+3] = a.w + b.w;
        sum += x[i*4+0] + x[i*4+1] + x[i*4+2] + x[i*4+3];
    }
    float mean = wred_sum(sum) * (1.f/HID);
    float vs = 0.f;
#pragma unroll
    for (int i = 0; i < 24; i++){ float d = x[i] - mean; vs += d*d; }
    float inv = rsqrtf(wred_sum(vs) * (1.f/HID) + 1e-12f);

    float* hr = hout + (size_t)r*HID;
    __half* h16r = h16 + (size_t)r*HID;
#pragma unroll
    for (int i = 0; i < 6; i++){
        int c = i*128 + lane*4;
        float4 g = *(const float4*)&gam[c];
        float4 b = *(const float4*)&bet[c];
        float4 o;
        o.x = (x[i*4+0] - mean)*inv*g.x + b.x;
        o.y = (x[i*4+1] - mean)*inv*g.y + b.y;
        o.z = (x[i*4+2] - mean)*inv*g.z + b.z;
        o.w = (x[i*4+3] - mean)*inv*g.w + b.w;
        *(float4*)&hr[c] = o;
        *(__half2*)&h16r[c]   = __floats2half2_rn(o.x, o.y);
        *(__half2*)&h16r[c+2] = __floats2half2_rn(o.z, o.w);
    }
}

__global__ __launch_bounds__(256)
void final_kernel(const float* __restrict__ h, const float* __restrict__ Wp,
                  const float* __restrict__ bp, float* __restrict__ out)
{
    int w = threadIdx.x >> 5, lane = threadIdx.x & 31;
    int r = blockIdx.x*8 + w;
    const float* hr = h + (size_t)r*HID;
    float sum = 0.f;
#pragma unroll
    for (int i = 0; i < 6; i++){
        int c = i*128 + lane*4;
        float4 a = *(const float4*)&hr[c];
        float4 b = *(const float4*)&Wp[c];
        sum += a.x*b.x + a.y*b.y + a.z*b.z + a.w*b.w;
    }
    sum = wred_sum(sum);
    if (lane == 0) out[r] = 1.f / (1.f + expf(-(sum + bp[0])));
}

// ---------------------------------------------------------------------------
// Tensor-core sliding-window attention (tf32 on fp32 qkv), fp16 output.
// ---------------------------------------------------------------------------
#define QT   32
#define KW   320
#define KVS  72
#define SSTR 328
#define SQ_OFF  0
#define SKV_OFF (QT*KVS)
#define SS_OFF  (SKV_OFF + KW*KVS)
#define ATT_SMEM ((SS_OFF + QT*SSTR)*4)

__global__ __launch_bounds__(256)
void attn_kernel(const float* __restrict__ qkv, const int* __restrict__ km,
                 __half* __restrict__ ag16)
{
    int qt   = blockIdx.x;
    int head = blockIdx.y;
    int b    = blockIdx.z;
    int q0   = qt * QT;
    int kbase = q0 - AW;

    extern __shared__ float sm[];
    float* sQ  = sm + SQ_OFF;
    float* sKV = sm + SKV_OFF;
    float* sS  = sm + SS_OFF;
    uint32_t skv_b = smem_u32(sKV);

    int t = threadIdx.x;
    int wid = t >> 5, lane = t & 31;
    int grp = lane >> 2, q4 = lane & 3;
    const size_t rstr = 3*HID;
    const float* base_b = qkv + (size_t)b*SS*rstr;

    for (int li = t; li < QT*16; li += 256){
        int row = li >> 4, c4 = (li & 15) << 2;
        const float4 qv = *(const float4*)&base_b[(size_t)(q0 + row)*rstr + head*HD + c4];
        float* d = &sQ[row*KVS + c4];
        d[0] = qv.x * 0.125f; d[1] = qv.y * 0.125f;
        d[2] = qv.z * 0.125f; d[3] = qv.w * 0.125f;
    }

    {
        const float* ksrc = base_b + HID + head*HD;
#pragma unroll
        for (int i = 0; i < 20; i++){
            int idx = i*256 + t;
            int row = idx >> 4, seg = idx & 15;
            int jg = kbase + row;
            uint32_t nb = (jg >= 0 && jg < SS) ? 16u : 0u;
            int jc = jg < 0 ? 0 : (jg >= SS ? SS-1 : jg);
            CP_ASYNC16Z(skv_b + (row*KVS + seg*4)*4, ksrc + (size_t)jc*rstr + seg*4, nb);
        }
        CP_COMMIT();
    }
    asm volatile("cp.async.wait_group 0;" ::: "memory");
    __syncthreads();

    {
        float acc[2][5][4];
#pragma unroll
        for (int mi = 0; mi < 2; mi++)
#pragma unroll
            for (int nt = 0; nt < 5; nt++)
#pragma unroll
                for (int r = 0; r < 4; r++) acc[mi][nt][r] = 0.f;

#pragma unroll
        for (int ks = 0; ks < 8; ks++){
            int k0 = ks*8;
            uint32_t af[2][4];
#pragma unroll
            for (int mi = 0; mi < 2; mi++){
                int rbase = (mi*16 + grp)*KVS + k0 + q4;
                af[mi][0] = __float_as_uint(sQ[rbase]);
                af[mi][1] = __float_as_uint(sQ[rbase + 8*KVS]);
                af[mi][2] = __float_as_uint(sQ[rbase + 4]);
                af[mi][3] = __float_as_uint(sQ[rbase + 8*KVS + 4]);
            }
#pragma unroll
            for (int nt = 0; nt < 5; nt++){
                int n0 = wid*40 + nt*8;
                uint32_t bf[2];
                int bbase = (n0 + grp)*KVS + k0 + q4;
                bf[0] = __float_as_uint(sKV[bbase]);
                bf[1] = __float_as_uint(sKV[bbase + 4]);
                mma_tf32(acc[0][nt], af[0], bf);
                mma_tf32(acc[1][nt], af[1], bf);
            }
        }
#pragma unroll
        for (int mi = 0; mi < 2; mi++){
            int r0 = mi*16 + grp;
#pragma unroll
            for (int nt = 0; nt < 5; nt++){
                int col = wid*40 + nt*8 + 2*q4;
                *(float2*)&sS[r0*SSTR + col]     = make_float2(acc[mi][nt][0], acc[mi][nt][1]);
                *(float2*)&sS[(r0+8)*SSTR + col] = make_float2(acc[mi][nt][2], acc[mi][nt][3]);
            }
        }
    }
    __syncthreads();

    {
        const float* vsrc = base_b + 2*HID + head*HD;
#pragma unroll
        for (int i = 0; i < 20; i++){
            int idx = i*256 + t;
            int row = idx >> 4, seg = idx & 15;
            int jg = kbase + row;
            uint32_t nb = (jg >= 0 && jg < SS) ? 16u : 0u;
            int jc = jg < 0 ? 0 : (jg >= SS ? SS-1 : jg);
            CP_ASYNC16Z(skv_b + (row*KVS + seg*4)*4, vsrc + (size_t)jc*rstr + seg*4, nb);
        }
        CP_COMMIT();
    }

    {
#pragma unroll
        for (int rr = 0; rr < 4; rr++){
            int qr = wid*4 + rr;
            int qi = q0 + qr;
            float mx = -1e30f;
            for (int j = lane; j < KW; j += 32){
                int jg = kbase + j;
                bool ok = (jg >= 0) && (jg < SS) && (jg >= qi - AW) && (jg <= qi + AW)
                          && (km[b*SS + jg] != 0);
                float sc = ok ? sS[qr*SSTR + j] : -1e30f;
                sS[qr*SSTR + j] = sc;
                mx = fmaxf(mx, sc);
            }
#pragma unroll
            for (int o = 16; o > 0; o >>= 1) mx = fmaxf(mx, __shfl_xor_sync(~0u, mx, o));
            float sum = 0.f;
            for (int j = lane; j < KW; j += 32){
                float p = __expf(sS[qr*SSTR + j] - mx);
                sS[qr*SSTR + j] = p; sum += p;
            }
#pragma unroll
            for (int o = 16; o > 0; o >>= 1) sum += __shfl_xor_sync(~0u, sum, o);
            float inv = 1.f / sum;
            for (int j = lane; j < KW; j += 32) sS[qr*SSTR + j] *= inv;
        }
    }
    asm volatile("cp.async.wait_group 0;" ::: "memory");
    __syncthreads();

    {
        int n0 = wid*8;
        float acc[2][4];
#pragma unroll
        for (int mi = 0; mi < 2; mi++)
#pragma unroll
            for (int r = 0; r < 4; r++) acc[mi][r] = 0.f;

#pragma unroll 4
        for (int ks = 0; ks < 40; ks++){
            int k0 = ks*8;
            uint32_t af[2][4], bf[2];
#pragma unroll
            for (int mi = 0; mi < 2; mi++){
                int rbase = (mi*16 + grp)*SSTR + k0 + q4;
                af[mi][0] = __float_as_uint(sS[rbase]);
                af[mi][1] = __float_as_uint(sS[rbase + 8*SSTR]);
                af[mi][2] = __float_as_uint(sS[rbase + 4]);
                af[mi][3] = __float_as_uint(sS[rbase + 8*SSTR + 4]);
            }
            int bbase = (k0 + q4)*KVS + n0 + grp;
            bf[0] = __float_as_uint(sKV[bbase]);
            bf[1] = __float_as_uint(sKV[bbase + 4*KVS]);
            mma_tf32(acc[0], af[0], bf);
            mma_tf32(acc[1], af[1], bf);
        }
#pragma unroll
        for (int mi = 0; mi < 2; mi++){
            int r0 = q0 + mi*16 + grp;
            int col = head*HD + n0 + 2*q4;
            *(__half2*)&ag16[((size_t)(b*SS + r0))*HID + col]     = __floats2half2_rn(acc[mi][0], acc[mi][1]);
            *(__half2*)&ag16[((size_t)(b*SS + r0 + 8))*HID + col] = __floats2half2_rn(acc[mi][2], acc[mi][3]);
        }
    }
}

// ---------------------------------------------------------------------------
// Host launcher
// ---------------------------------------------------------------------------
extern "C" void kernel_launch(void* const* d_in, const int* in_sizes, int n_in,
                              void* d_out, int out_size)
{
    (void)in_sizes; (void)n_in;
    const float* emb   = (const float*)d_in[0];
    const int*   amask = (const int*)  d_in[1];
    const float* pos   = (const float*)d_in[2];
    const float* tok   = (const float*)d_in[3];
    const float* eg    = (const float*)d_in[4];
    const float* eb    = (const float*)d_in[5];
    const float* Wq    = (const float*)d_in[6];
    const float* bq    = (const float*)d_in[7];
    const float* Wk    = (const float*)d_in[8];
    const float* bk    = (const float*)d_in[9];
    const float* Wv    = (const float*)d_in[10];
    const float* bv    = (const float*)d_in[11];
    const float* Wo    = (const float*)d_in[12];
    const float* bo    = (const float*)d_in[13];
    const float* ln1g  = (const float*)d_in[14];
    const float* ln1b  = (const float*)d_in[15];
    const float* Wi    = (const float*)d_in[16];
    const float* bi    = (const float*)d_in[17];
    const float* Wf    = (const float*)d_in[18];
    const float* bf    = (const float*)d_in[19];
    const float* ln2g  = (const float*)d_in[20];
    const float* ln2b  = (const float*)d_in[21];
    const float* Wp    = (const float*)d_in[22];
    const float* bp    = (const float*)d_in[23];

    float* scratch = nullptr;
    cudaGetSymbolAddress((void**)&scratch, g_scratch);
    float*  h     = scratch;                                  // ACT
    float*  qkv   = scratch + 1*(size_t)ACT;                  // 3*ACT
    float*  tmp   = qkv;                                      // reuse after attention
    __half* h16   = (__half*)(scratch + 4*(size_t)ACT);       // ACT halves
    __half* a16   = (__half*)(scratch + 4*(size_t)ACT + ACT/2);
    __half* ffn16 = (__half*)(scratch + 5*(size_t)ACT);       // 4*ACT halves = 2*ACT floats
    __half* WqkvT = (__half*)(scratch + 7*(size_t)ACT);       // NL*3*HID*HID halves
    __half* WoT   = WqkvT + 3*(size_t)WT_SM;
    __half* WiT   = WoT   + (size_t)WT_SM;
    __half* WfT   = WiT   + (size_t)WT_LG;
    float*  bqkv  = (float*)(WfT + (size_t)WT_LG);
    // align bqkv up to 4 bytes (it already is: even number of halves before it)

    cudaFuncSetAttribute(gemm_tc, cudaFuncAttributeMaxDynamicSharedMemorySize, GEMM_SMEM);
    cudaFuncSetAttribute(attn_kernel, cudaFuncAttributeMaxDynamicSharedMemorySize, ATT_SMEM);

    const size_t LSTR = (size_t)3*HID*HID;

    transpose_h<<<dim3(HID/32, HID/32, NL), 256>>>(Wq, WqkvT,                     HID, HID, LSTR);
    transpose_h<<<dim3(HID/32, HID/32, NL), 256>>>(Wk, WqkvT + (size_t)HID*HID,   HID, HID, LSTR);
    transpose_h<<<dim3(HID/32, HID/32, NL), 256>>>(Wv, WqkvT + (size_t)2*HID*HID, HID, HID, LSTR);
    transpose_h<<<dim3(HID/32, HID/32, NL), 256>>>(Wo, WoT, HID, HID, (size_t)HID*HID);
    transpose_h<<<dim3(4*HID/32, HID/32, NL), 256>>>(Wi, WiT, HID, 4*HID, (size_t)4*HID*HID);
    transpose_h<<<dim3(HID/32, 4*HID/32, NL), 256>>>(Wf, WfT, 4*HID, HID, (size_t)4*HID*HID);
    pack_qkv_bias<<<NL, 256>>>(bq, bk, bv, bqkv);

    embed_ln_kernel<<<ROWS/8, 256>>>(emb, pos, tok, eg, eb, h, h16);

    dim3 gqkv(3*HID/GBN, ROWS/GBM);
    dim3 g768(HID/GBN, ROWS/GBM);
    dim3 g3072(4*HID/GBN, ROWS/GBM);
    dim3 gattn(SS/QT, NH, BB);

    for (int l = 0; l < NL; l++) {
        const size_t wofs  = (size_t)l * HID * HID;
        const size_t bofs  = (size_t)l * HID;
        const size_t wlofs = (size_t)l * HID * 4*HID;
        const size_t blofs = (size_t)l * 4*HID;

        gemm_tc<<<gqkv, 128, GEMM_SMEM>>>(h16, WqkvT + l*LSTR, bqkv + l*3*HID, qkv, HID, 3*HID, 0);

        attn_kernel<<<gattn, 256, ATT_SMEM>>>(qkv, amask, a16);

        gemm_tc<<<g768, 128, GEMM_SMEM>>>(a16, WoT + wofs, bo + bofs, tmp, HID, HID, 0);
        add_ln_kernel<<<ROWS/8, 256>>>(h, tmp, ln1g + bofs, ln1b + bofs, h, h16);

        gemm_tc<<<g3072, 128, GEMM_SMEM>>>(h16, WiT + wlofs, bi + blofs, ffn16, HID, 4*HID, 3);
        gemm_tc<<<g768, 128, GEMM_SMEM>>>(ffn16, WfT + wlofs, bf + bofs, tmp, 4*HID, HID, 0);
        add_ln_kernel<<<ROWS/8, 256>>>(h, tmp, ln2g + bofs, ln2b + bofs, h, h16);
    }

    final_kernel<<<ROWS/8, 256>>>(h, Wp, bp, (float*)d_out);
    (void)out_size;
}

// round 8
// speedup vs baseline: 4.7876x; 1.0289x over previous
#include <cuda_runtime.h>
#include <cuda_fp16.h>
#include <math.h>
#include <stdint.h>

// Problem constants
#define BB   2
#define SS   4096
#define HID  768
#define NL   4
#define NH   12
#define HD   64
#define AW   128
#define ROWS (BB*SS)      // 8192

// ---------------------------------------------------------------------------
// Scratch
// ---------------------------------------------------------------------------
#define ACT (ROWS*HID)
#define WT_SM (NL*HID*HID)
#define WT_LG (NL*HID*4*HID)
__device__ float g_scratch[9*(size_t)ACT + 4*(size_t)WT_SM + 2*(size_t)WT_LG + NL*3*HID];

// ---------------------------------------------------------------------------
// helpers
// ---------------------------------------------------------------------------
__device__ __forceinline__ uint32_t smem_u32(const void* p){
    uint32_t a;
    asm("{ .reg .u64 t; cvta.to.shared.u64 t, %1; cvt.u32.u64 %0, t; }" : "=r"(a) : "l"(p));
    return a;
}
#define CP_ASYNC16(dst,src)      asm volatile("cp.async.cg.shared.global [%0], [%1], 16;" :: "r"(dst), "l"(src))
#define CP_ASYNC16Z(dst,src,nb)  asm volatile("cp.async.cg.shared.global [%0], [%1], 16, %2;" :: "r"(dst), "l"(src), "r"(nb))
#define CP_COMMIT() asm volatile("cp.async.commit_group;" ::: "memory")
#define LDSM4(r, a) \
    asm volatile("ldmatrix.sync.aligned.m8n8.x4.shared.b16 {%0,%1,%2,%3}, [%4];" \
        : "=r"((r)[0]),"=r"((r)[1]),"=r"((r)[2]),"=r"((r)[3]) : "r"(a))

__device__ __forceinline__ void mma_tf32(float* d, const uint32_t* a, const uint32_t* b){
    asm volatile("mma.sync.aligned.m16n8k8.row.col.f32.tf32.tf32.f32 "
        "{%0,%1,%2,%3}, {%4,%5,%6,%7}, {%8,%9}, {%0,%1,%2,%3};"
        : "+f"(d[0]),"+f"(d[1]),"+f"(d[2]),"+f"(d[3])
        : "r"(a[0]),"r"(a[1]),"r"(a[2]),"r"(a[3]), "r"(b[0]),"r"(b[1]));
}
__device__ __forceinline__ void mma_f16(float* d, const uint32_t* a, const uint32_t* b){
    asm volatile("mma.sync.aligned.m16n8k16.row.col.f32.f16.f16.f32 "
        "{%0,%1,%2,%3}, {%4,%5,%6,%7}, {%8,%9}, {%0,%1,%2,%3};"
        : "+f"(d[0]),"+f"(d[1]),"+f"(d[2]),"+f"(d[3])
        : "r"(a[0]),"r"(a[1]),"r"(a[2]),"r"(a[3]), "r"(b[0]),"r"(b[1]));
}
__device__ __forceinline__ float gelu_exact(float x){
    return 0.5f * x * (1.f + erff(x * 0.70710678118654752f));
}
__device__ __forceinline__ float wred_sum(float v){
#pragma unroll
    for (int o = 16; o > 0; o >>= 1) v += __shfl_xor_sync(~0u, v, o);
    return v;
}

// ---------------------------------------------------------------------------
// fp16 mma.sync GEMM with ldmatrix fragment loads.
// C[M,N] = act(A[M,K] @ BT[N,K]^T + bias[N]); A,BT fp16; smem row = 80 bytes.
// ---------------------------------------------------------------------------
#define GBM 128
#define GBN 128
#define GBK 32
#define NSTG 3
#define LDAB 20
#define STG  (2*GBM*LDAB*4)          // 20480
#define GEMM_SMEM (NSTG*STG)

__device__ __forceinline__ void load_chunk16(const __half* __restrict__ A, const __half* __restrict__ BT,
                                             int K, int bm, int bn, int c, uint32_t stage)
{
    int t = threadIdx.x;
    const __half* asrc = A  + (size_t)bm*K + (size_t)c*GBK;
    const __half* bsrc = BT + (size_t)bn*K + (size_t)c*GBK;
#pragma unroll
    for (int i = 0; i < 4; i++){
        int idx = i*128 + t;
        int row = idx >> 2, seg = idx & 3;
        CP_ASYNC16(stage + row*80 + seg*16, asrc + (size_t)row*K + seg*8);
    }
#pragma unroll
    for (int i = 0; i < 4; i++){
        int idx = i*128 + t;
        int row = idx >> 2, seg = idx & 3;
        CP_ASYNC16(stage + GBM*80 + row*80 + seg*16, bsrc + (size_t)row*K + seg*8);
    }
    CP_COMMIT();
}

__global__ __launch_bounds__(128, 2)
void gemm_tc(const __half* __restrict__ A, const __half* __restrict__ BT,
             const float* __restrict__ bias, void* __restrict__ Cv,
             int K, int N, int mode)
{
    extern __shared__ char smem[];
    int t = threadIdx.x;
    int wid = t >> 5, lane = t & 31;
    int grp = lane >> 2, q4 = lane & 3;
    int mw = (wid & 1) * 64, nw = (wid >> 1) * 64;
    int bm = blockIdx.y * GBM, bn = blockIdx.x * GBN;

    // ldmatrix per-lane offsets
    int lm = lane >> 3, lr = lane & 7;
    uint32_t aoff = (uint32_t)(((lm & 1)*8 + lr)*80 + (lm >> 1)*16);
    uint32_t boff = (uint32_t)(((lm >> 1)*8 + lr)*80 + (lm & 1)*16);

    float acc[4][8][4];
#pragma unroll
    for (int mi = 0; mi < 4; mi++)
#pragma unroll
        for (int ni = 0; ni < 8; ni++)
#pragma unroll
            for (int r = 0; r < 4; r++) acc[mi][ni][r] = 0.f;

    uint32_t sb = smem_u32(smem);
    const int NC = K / GBK;

    load_chunk16(A, BT, K, bm, bn, 0, sb);
    load_chunk16(A, BT, K, bm, bn, 1, sb + STG);

    for (int c = 0; c < NC; c++){
        int slot = c % NSTG;
        if (c + 1 < NC) { asm volatile("cp.async.wait_group 1;" ::: "memory"); }
        else            { asm volatile("cp.async.wait_group 0;" ::: "memory"); }
        __syncthreads();
        if (c + 2 < NC)
            load_chunk16(A, BT, K, bm, bn, c + 2, sb + ((c+2)%NSTG)*STG);

        uint32_t As_b = sb + slot*STG;
        uint32_t Bs_b = As_b + GBM*80;
#pragma unroll
        for (int ks = 0; ks < 2; ks++){
            uint32_t kb = ks*32;
            uint32_t af[4][4], bf[8][2];
#pragma unroll
            for (int mi = 0; mi < 4; mi++)
                LDSM4(af[mi], As_b + (mw + mi*16)*80 + aoff + kb);
#pragma unroll
            for (int p = 0; p < 4; p++){
                uint32_t r[4];
                LDSM4(r, Bs_b + (nw + p*16)*80 + boff + kb);
                bf[2*p][0] = r[0]; bf[2*p][1] = r[1];
                bf[2*p+1][0] = r[2]; bf[2*p+1][1] = r[3];
            }
#pragma unroll
            for (int mi = 0; mi < 4; mi++)
#pragma unroll
                for (int ni = 0; ni < 8; ni++)
                    mma_f16(acc[mi][ni], af[mi], bf[ni]);
        }
    }

    float* Cf = (float*)Cv;
    __half* Ch = (__half*)Cv;
#pragma unroll
    for (int mi = 0; mi < 4; mi++){
        int r0 = bm + mw + mi*16 + grp;
#pragma unroll
        for (int ni = 0; ni < 8; ni++){
            int col = bn + nw + ni*8 + 2*q4;
            float bx = bias[col], by = bias[col+1];
            float a0 = acc[mi][ni][0] + bx, a1 = acc[mi][ni][1] + by;
            float a2 = acc[mi][ni][2] + bx, a3 = acc[mi][ni][3] + by;
            if (mode & 1){
                a0 = gelu_exact(a0); a1 = gelu_exact(a1);
                a2 = gelu_exact(a2); a3 = gelu_exact(a3);
            }
            if (mode & 2){
                *(__half2*)&Ch[(size_t)r0*N + col]     = __floats2half2_rn(a0, a1);
                *(__half2*)&Ch[(size_t)(r0+8)*N + col] = __floats2half2_rn(a2, a3);
            } else {
                *(float2*)&Cf[(size_t)r0*N + col]     = make_float2(a0, a1);
                *(float2*)&Cf[(size_t)(r0+8)*N + col] = make_float2(a2, a3);
            }
        }
    }
}

// ---------------------------------------------------------------------------
// Weight transpose to fp16 + bias pack
// ---------------------------------------------------------------------------
__global__ __launch_bounds__(256)
void transpose_h(const float* __restrict__ in, __half* __restrict__ out,
                 int R, int C, size_t outStride)
{
    __shared__ float tile[32][33];
    const float* src = in  + (size_t)blockIdx.z * R * C;
    __half*      dst = out + (size_t)blockIdx.z * outStride;
    int r0 = blockIdx.y*32, c0 = blockIdx.x*32;
    int tx = threadIdx.x & 31, ty = threadIdx.x >> 5;
#pragma unroll
    for (int i = 0; i < 4; i++)
        tile[ty + i*8][tx] = src[(size_t)(r0 + ty + i*8)*C + c0 + tx];
    __syncthreads();
#pragma unroll
    for (int i = 0; i < 4; i++)
        dst[(size_t)(c0 + ty + i*8)*R + r0 + tx] = __float2half(tile[tx][ty + i*8]);
}

__global__ __launch_bounds__(256)
void pack_qkv_bias(const float* __restrict__ bq, const float* __restrict__ bk,
                   const float* __restrict__ bv, float* __restrict__ o)
{
    int l = blockIdx.x, t = threadIdx.x;
    for (int i = t; i < HID; i += 256){
        o[l*3*HID + i]         = bq[l*HID + i];
        o[l*3*HID + HID + i]   = bk[l*HID + i];
        o[l*3*HID + 2*HID + i] = bv[l*HID + i];
    }
}

// ---------------------------------------------------------------------------
// Warp-per-row LayerNorm kernels; emit fp32 + fp16 shadow
// ---------------------------------------------------------------------------
__global__ __launch_bounds__(256)
void embed_ln_kernel(const float* __restrict__ emb, const float* __restrict__ pos,
                     const float* __restrict__ tok, const float* __restrict__ gam,
                     const float* __restrict__ bet, float* __restrict__ h,
                     __half* __restrict__ h16)
{
    int w = threadIdx.x >> 5, lane = threadIdx.x & 31;
    int r = blockIdx.x*8 + w;
    int s = r & (SS-1);
    const float* er = emb + (size_t)r*HID;
    const float* pr = pos + (size_t)(s+1)*HID;

    float x[24];
    float sum = 0.f;
#pragma unroll
    for (int i = 0; i < 6; i++){
        int c = i*128 + lane*4;
        float4 e = *(const float4*)&er[c];
        float4 p = *(const float4*)&pr[c];
        float4 tk = *(const float4*)&tok[c];
        x[i*4+0] = e.x + p.x + tk.x;
        x[i*4+1] = e.y + p.y + tk.y;
        x[i*4+2] = e.z + p.z + tk.z;
        x[i*4+3] = e.w + p.w + tk.w;
        sum += x[i*4+0] + x[i*4+1] + x[i*4+2] + x[i*4+3];
    }
    float mean = wred_sum(sum) * (1.f/HID);
    float vs = 0.f;
#pragma unroll
    for (int i = 0; i < 24; i++){ float d = x[i] - mean; vs += d*d; }
    float inv = rsqrtf(wred_sum(vs) * (1.f/HID) + 1e-12f);

    float* hr = h + (size_t)r*HID;
    __half* h16r = h16 + (size_t)r*HID;
#pragma unroll
    for (int i = 0; i < 6; i++){
        int c = i*128 + lane*4;
        float4 g = *(const float4*)&gam[c];
        float4 b = *(const float4*)&bet[c];
        float4 o;
        o.x = (x[i*4+0] - mean)*inv*g.x + b.x;
        o.y = (x[i*4+1] - mean)*inv*g.y + b.y;
        o.z = (x[i*4+2] - mean)*inv*g.z + b.z;
        o.w = (x[i*4+3] - mean)*inv*g.w + b.w;
        *(float4*)&hr[c] = o;
        *(__half2*)&h16r[c]   = __floats2half2_rn(o.x, o.y);
        *(__half2*)&h16r[c+2] = __floats2half2_rn(o.z, o.w);
    }
}

__global__ __launch_bounds__(256)
void add_ln_kernel(const float* __restrict__ hin, const float* __restrict__ tin,
                   const float* __restrict__ gam, const float* __restrict__ bet,
                   float* __restrict__ hout, __half* __restrict__ h16)
{
    int w = threadIdx.x >> 5, lane = threadIdx.x & 31;
    int r = blockIdx.x*8 + w;
    const float* ar = hin + (size_t)r*HID;
    const float* br = tin + (size_t)r*HID;

    float x[24];
    float sum = 0.f;
#pragma unroll
    for (int i = 0; i < 6; i++){
        int c = i*128 + lane*4;
        float4 a = *(const float4*)&ar[c];
        float4 b = *(const float4*)&br[c];
        x[i*4+0] = a.x + b.x; x[i*4+1] = a.y + b.y;
        x[i*4+2] = a.z + b.z; x[i*4+3] = a.w + b.w;
        sum += x[i*4+0] + x[i*4+1] + x[i*4+2] + x[i*4+3];
    }
    float mean = wred_sum(sum) * (1.f/HID);
    float vs = 0.f;
#pragma unroll
    for (int i = 0; i < 24; i++){ float d = x[i] - mean; vs += d*d; }
    float inv = rsqrtf(wred_sum(vs) * (1.f/HID) + 1e-12f);

    float* hr = hout + (size_t)r*HID;
    __half* h16r = h16 + (size_t)r*HID;
#pragma unroll
    for (int i = 0; i < 6; i++){
        int c = i*128 + lane*4;
        float4 g = *(const float4*)&gam[c];
        float4 b = *(const float4*)&bet[c];
        float4 o;
        o.x = (x[i*4+0] - mean)*inv*g.x + b.x;
        o.y = (x[i*4+1] - mean)*inv*g.y + b.y;
        o.z = (x[i*4+2] - mean)*inv*g.z + b.z;
        o.w = (x[i*4+3] - mean)*inv*g.w + b.w;
        *(float4*)&hr[c] = o;
        *(__half2*)&h16r[c]   = __floats2half2_rn(o.x, o.y);
        *(__half2*)&h16r[c+2] = __floats2half2_rn(o.z, o.w);
    }
}

__global__ __launch_bounds__(256)
void final_kernel(const float* __restrict__ h, const float* __restrict__ Wp,
                  const float* __restrict__ bp, float* __restrict__ out)
{
    int w = threadIdx.x >> 5, lane = threadIdx.x & 31;
    int r = blockIdx.x*8 + w;
    const float* hr = h + (size_t)r*HID;
    float sum = 0.f;
#pragma unroll
    for (int i = 0; i < 6; i++){
        int c = i*128 + lane*4;
        float4 a = *(const float4*)&hr[c];
        float4 b = *(const float4*)&Wp[c];
        sum += a.x*b.x + a.y*b.y + a.z*b.z + a.w*b.w;
    }
    sum = wred_sum(sum);
    if (lane == 0) out[r] = 1.f / (1.f + expf(-(sum + bp[0])));
}

// ---------------------------------------------------------------------------
// Tensor-core sliding-window attention (tf32 on fp32 qkv), fp16 output.
// ---------------------------------------------------------------------------
#define QT   32
#define KW   320
#define KVS  72
#define SSTR 328
#define SQ_OFF  0
#define SKV_OFF (QT*KVS)
#define SS_OFF  (SKV_OFF + KW*KVS)
#define ATT_SMEM ((SS_OFF + QT*SSTR)*4)

__global__ __launch_bounds__(256)
void attn_kernel(const float* __restrict__ qkv, const int* __restrict__ km,
                 __half* __restrict__ ag16)
{
    int qt   = blockIdx.x;
    int head = blockIdx.y;
    int b    = blockIdx.z;
    int q0   = qt * QT;
    int kbase = q0 - AW;

    extern __shared__ float sm[];
    float* sQ  = sm + SQ_OFF;
    float* sKV = sm + SKV_OFF;
    float* sS  = sm + SS_OFF;
    uint32_t skv_b = smem_u32(sKV);

    int t = threadIdx.x;
    int wid = t >> 5, lane = t & 31;
    int grp = lane >> 2, q4 = lane & 3;
    const size_t rstr = 3*HID;
    const float* base_b = qkv + (size_t)b*SS*rstr;

    for (int li = t; li < QT*16; li += 256){
        int row = li >> 4, c4 = (li & 15) << 2;
        const float4 qv = *(const float4*)&base_b[(size_t)(q0 + row)*rstr + head*HD + c4];
        float* d = &sQ[row*KVS + c4];
        d[0] = qv.x * 0.125f; d[1] = qv.y * 0.125f;
        d[2] = qv.z * 0.125f; d[3] = qv.w * 0.125f;
    }

    {
        const float* ksrc = base_b + HID + head*HD;
#pragma unroll
        for (int i = 0; i < 20; i++){
            int idx = i*256 + t;
            int row = idx >> 4, seg = idx & 15;
            int jg = kbase + row;
            uint32_t nb = (jg >= 0 && jg < SS) ? 16u : 0u;
            int jc = jg < 0 ? 0 : (jg >= SS ? SS-1 : jg);
            CP_ASYNC16Z(skv_b + (row*KVS + seg*4)*4, ksrc + (size_t)jc*rstr + seg*4, nb);
        }
        CP_COMMIT();
    }
    asm volatile("cp.async.wait_group 0;" ::: "memory");
    __syncthreads();

    {
        float acc[2][5][4];
#pragma unroll
        for (int mi = 0; mi < 2; mi++)
#pragma unroll
            for (int nt = 0; nt < 5; nt++)
#pragma unroll
                for (int r = 0; r < 4; r++) acc[mi][nt][r] = 0.f;

#pragma unroll
        for (int ks = 0; ks < 8; ks++){
            int k0 = ks*8;
            uint32_t af[2][4];
#pragma unroll
            for (int mi = 0; mi < 2; mi++){
                int rbase = (mi*16 + grp)*KVS + k0 + q4;
                af[mi][0] = __float_as_uint(sQ[rbase]);
                af[mi][1] = __float_as_uint(sQ[rbase + 8*KVS]);
                af[mi][2] = __float_as_uint(sQ[rbase + 4]);
                af[mi][3] = __float_as_uint(sQ[rbase + 8*KVS + 4]);
            }
#pragma unroll
            for (int nt = 0; nt < 5; nt++){
                int n0 = wid*40 + nt*8;
                uint32_t bf[2];
                int bbase = (n0 + grp)*KVS + k0 + q4;
                bf[0] = __float_as_uint(sKV[bbase]);
                bf[1] = __float_as_uint(sKV[bbase + 4]);
                mma_tf32(acc[0][nt], af[0], bf);
                mma_tf32(acc[1][nt], af[1], bf);
            }
        }
#pragma unroll
        for (int mi = 0; mi < 2; mi++){
            int r0 = mi*16 + grp;
#pragma unroll
            for (int nt = 0; nt < 5; nt++){
                int col = wid*40 + nt*8 + 2*q4;
                *(float2*)&sS[r0*SSTR + col]     = make_float2(acc[mi][nt][0], acc[mi][nt][1]);
                *(float2*)&sS[(r0+8)*SSTR + col] = make_float2(acc[mi][nt][2], acc[mi][nt][3]);
            }
        }
    }
    __syncthreads();

    {
        const float* vsrc = base_b + 2*HID + head*HD;
#pragma unroll
        for (int i = 0; i < 20; i++){
            int idx = i*256 + t;
            int row = idx >> 4, seg = idx & 15;
            int jg = kbase + row;
            uint32_t nb = (jg >= 0 && jg < SS) ? 16u : 0u;
            int jc = jg < 0 ? 0 : (jg >= SS ? SS-1 : jg);
            CP_ASYNC16Z(skv_b + (row*KVS + seg*4)*4, vsrc + (size_t)jc*rstr + seg*4, nb);
        }
        CP_COMMIT();
    }

    {
#pragma unroll
        for (int rr = 0; rr < 4; rr++){
            int qr = wid*4 + rr;
            int qi = q0 + qr;
            float mx = -1e30f;
            for (int j = lane; j < KW; j += 32){
                int jg = kbase + j;
                bool ok = (jg >= 0) && (jg < SS) && (jg >= qi - AW) && (jg <= qi + AW)
                          && (km[b*SS + jg] != 0);
                float sc = ok ? sS[qr*SSTR + j] : -1e30f;
                sS[qr*SSTR + j] = sc;
                mx = fmaxf(mx, sc);
            }
#pragma unroll
            for (int o = 16; o > 0; o >>= 1) mx = fmaxf(mx, __shfl_xor_sync(~0u, mx, o));
            float sum = 0.f;
            for (int j = lane; j < KW; j += 32){
                float p = __expf(sS[qr*SSTR + j] - mx);
                sS[qr*SSTR + j] = p; sum += p;
            }
#pragma unroll
            for (int o = 16; o > 0; o >>= 1) sum += __shfl_xor_sync(~0u, sum, o);
            float inv = 1.f / sum;
            for (int j = lane; j < KW; j += 32) sS[qr*SSTR + j] *= inv;
        }
    }
    asm volatile("cp.async.wait_group 0;" ::: "memory");
    __syncthreads();

    {
        int n0 = wid*8;
        float acc[2][4];
#pragma unroll
        for (int mi = 0; mi < 2; mi++)
#pragma unroll
            for (int r = 0; r < 4; r++) acc[mi][r] = 0.f;

#pragma unroll 4
        for (int ks = 0; ks < 40; ks++){
            int k0 = ks*8;
            uint32_t af[2][4], bf[2];
#pragma unroll
            for (int mi = 0; mi < 2; mi++){
                int rbase = (mi*16 + grp)*SSTR + k0 + q4;
                af[mi][0] = __float_as_uint(sS[rbase]);
                af[mi][1] = __float_as_uint(sS[rbase + 8*SSTR]);
                af[mi][2] = __float_as_uint(sS[rbase + 4]);
                af[mi][3] = __float_as_uint(sS[rbase + 8*SSTR + 4]);
            }
            int bbase = (k0 + q4)*KVS + n0 + grp;
            bf[0] = __float_as_uint(sKV[bbase]);
            bf[1] = __float_as_uint(sKV[bbase + 4*KVS]);
            mma_tf32(acc[0], af[0], bf);
            mma_tf32(acc[1], af[1], bf);
        }
#pragma unroll
        for (int mi = 0; mi < 2; mi++){
            int r0 = q0 + mi*16 + grp;
            int col = head*HD + n0 + 2*q4;
            *(__half2*)&ag16[((size_t)(b*SS + r0))*HID + col]     = __floats2half2_rn(acc[mi][0], acc[mi][1]);
            *(__half2*)&ag16[((size_t)(b*SS + r0 + 8))*HID + col] = __floats2half2_rn(acc[mi][2], acc[mi][3]);
        }
    }
}

// ---------------------------------------------------------------------------
// Host launcher
// ---------------------------------------------------------------------------
extern "C" void kernel_launch(void* const* d_in, const int* in_sizes, int n_in,
                              void* d_out, int out_size)
{
    (void)in_sizes; (void)n_in;
    const float* emb   = (const float*)d_in[0];
    const int*   amask = (const int*)  d_in[1];
    const float* pos   = (const float*)d_in[2];
    const float* tok   = (const float*)d_in[3];
    const float* eg    = (const float*)d_in[4];
    const float* eb    = (const float*)d_in[5];
    const float* Wq    = (const float*)d_in[6];
    const float* bq    = (const float*)d_in[7];
    const float* Wk    = (const float*)d_in[8];
    const float* bk    = (const float*)d_in[9];
    const float* Wv    = (const float*)d_in[10];
    const float* bv    = (const float*)d_in[11];
    const float* Wo    = (const float*)d_in[12];
    const float* bo    = (const float*)d_in[13];
    const float* ln1g  = (const float*)d_in[14];
    const float* ln1b  = (const float*)d_in[15];
    const float* Wi    = (const float*)d_in[16];
    const float* bi    = (const float*)d_in[17];
    const float* Wf    = (const float*)d_in[18];
    const float* bf    = (const float*)d_in[19];
    const float* ln2g  = (const float*)d_in[20];
    const float* ln2b  = (const float*)d_in[21];
    const float* Wp    = (const float*)d_in[22];
    const float* bp    = (const float*)d_in[23];

    float* scratch = nullptr;
    cudaGetSymbolAddress((void**)&scratch, g_scratch);
    float*  h     = scratch;
    float*  qkv   = scratch + 1*(size_t)ACT;
    float*  tmp   = qkv;
    __half* h16   = (__half*)(scratch + 4*(size_t)ACT);
    __half* a16   = (__half*)(scratch + 4*(size_t)ACT + ACT/2);
    __half* ffn16 = (__half*)(scratch + 5*(size_t)ACT);
    __half* WqkvT = (__half*)(scratch + 7*(size_t)ACT);
    __half* WoT   = WqkvT + 3*(size_t)WT_SM;
    __half* WiT   = WoT   + (size_t)WT_SM;
    __half* WfT   = WiT   + (size_t)WT_LG;
    float*  bqkv  = (float*)(WfT + (size_t)WT_LG);

    cudaFuncSetAttribute(gemm_tc, cudaFuncAttributeMaxDynamicSharedMemorySize, GEMM_SMEM);
    cudaFuncSetAttribute(attn_kernel, cudaFuncAttributeMaxDynamicSharedMemorySize, ATT_SMEM);

    const size_t LSTR = (size_t)3*HID*HID;

    transpose_h<<<dim3(HID/32, HID/32, NL), 256>>>(Wq, WqkvT,                     HID, HID, LSTR);
    transpose_h<<<dim3(HID/32, HID/32, NL), 256>>>(Wk, WqkvT + (size_t)HID*HID,   HID, HID, LSTR);
    transpose_h<<<dim3(HID/32, HID/32, NL), 256>>>(Wv, WqkvT + (size_t)2*HID*HID, HID, HID, LSTR);
    transpose_h<<<dim3(HID/32, HID/32, NL), 256>>>(Wo, WoT, HID, HID, (size_t)HID*HID);
    transpose_h<<<dim3(4*HID/32, HID/32, NL), 256>>>(Wi, WiT, HID, 4*HID, (size_t)4*HID*HID);
    transpose_h<<<dim3(HID/32, 4*HID/32, NL), 256>>>(Wf, WfT, 4*HID, HID, (size_t)4*HID*HID);
    pack_qkv_bias<<<NL, 256>>>(bq, bk, bv, bqkv);

    embed_ln_kernel<<<ROWS/8, 256>>>(emb, pos, tok, eg, eb, h, h16);

    dim3 gqkv(3*HID/GBN, ROWS/GBM);
    dim3 g768(HID/GBN, ROWS/GBM);
    dim3 g3072(4*HID/GBN, ROWS/GBM);
    dim3 gattn(SS/QT, NH, BB);

    for (int l = 0; l < NL; l++) {
        const size_t wofs  = (size_t)l * HID * HID;
        const size_t bofs  = (size_t)l * HID;
        const size_t wlofs = (size_t)l * HID * 4*HID;
        const size_t blofs = (size_t)l * 4*HID;

        gemm_tc<<<gqkv, 128, GEMM_SMEM>>>(h16, WqkvT + l*LSTR, bqkv + l*3*HID, qkv, HID, 3*HID, 0);

        attn_kernel<<<gattn, 256, ATT_SMEM>>>(qkv, amask, a16);

        gemm_tc<<<g768, 128, GEMM_SMEM>>>(a16, WoT + wofs, bo + bofs, tmp, HID, HID, 0);
        add_ln_kernel<<<ROWS/8, 256>>>(h, tmp, ln1g + bofs, ln1b + bofs, h, h16);

        gemm_tc<<<g3072, 128, GEMM_SMEM>>>(h16, WiT + wlofs, bi + blofs, ffn16, HID, 4*HID, 3);
        gemm_tc<<<g768, 128, GEMM_SMEM>>>(ffn16, WfT + wlofs, bf + bofs, tmp, 4*HID, HID, 0);
        add_ln_kernel<<<ROWS/8, 256>>>(h, tmp, ln2g + bofs, ln2b + bofs, h, h16);
    }

    final_kernel<<<ROWS/8, 256>>>(h, Wp, bp, (float*)d_out);
    (void)out_size;
}

// round 9
// speedup vs baseline: 5.8812x; 1.2284x over previous
#include <cuda_runtime.h>
#include <cuda_fp16.h>
#include <math.h>
#include <stdint.h>

// Problem constants
#define BB   2
#define SS   4096
#define HID  768
#define NL   4
#define NH   12
#define HD   64
#define AW   128
#define ROWS (BB*SS)      // 8192

// ---------------------------------------------------------------------------
// Scratch
// ---------------------------------------------------------------------------
#define ACT (ROWS*HID)
#define WT_SM (NL*HID*HID)
#define WT_LG (NL*HID*4*HID)
__device__ float g_scratch[9*(size_t)ACT + 4*(size_t)WT_SM + 2*(size_t)WT_LG + NL*3*HID];

// ---------------------------------------------------------------------------
// helpers
// ---------------------------------------------------------------------------
__device__ __forceinline__ uint32_t smem_u32(const void* p){
    uint32_t a;
    asm("{ .reg .u64 t; cvta.to.shared.u64 t, %1; cvt.u32.u64 %0, t; }" : "=r"(a) : "l"(p));
    return a;
}
#define CP_ASYNC16(dst,src)      asm volatile("cp.async.cg.shared.global [%0], [%1], 16;" :: "r"(dst), "l"(src))
#define CP_ASYNC16Z(dst,src,nb)  asm volatile("cp.async.cg.shared.global [%0], [%1], 16, %2;" :: "r"(dst), "l"(src), "r"(nb))
#define CP_COMMIT() asm volatile("cp.async.commit_group;" ::: "memory")
#define LDSM4(r, a) \
    asm volatile("ldmatrix.sync.aligned.m8n8.x4.shared.b16 {%0,%1,%2,%3}, [%4];" \
        : "=r"((r)[0]),"=r"((r)[1]),"=r"((r)[2]),"=r"((r)[3]) : "r"(a))

__device__ __forceinline__ void mma_f16(float* d, const uint32_t* a, const uint32_t* b){
    asm volatile("mma.sync.aligned.m16n8k16.row.col.f32.f16.f16.f32 "
        "{%0,%1,%2,%3}, {%4,%5,%6,%7}, {%8,%9}, {%0,%1,%2,%3};"
        : "+f"(d[0]),"+f"(d[1]),"+f"(d[2]),"+f"(d[3])
        : "r"(a[0]),"r"(a[1]),"r"(a[2]),"r"(a[3]), "r"(b[0]),"r"(b[1]));
}
__device__ __forceinline__ float gelu_exact(float x){
    return 0.5f * x * (1.f + erff(x * 0.70710678118654752f));
}
__device__ __forceinline__ float wred_sum(float v){
#pragma unroll
    for (int o = 16; o > 0; o >>= 1) v += __shfl_xor_sync(~0u, v, o);
    return v;
}

// ---------------------------------------------------------------------------
// fp16 mma.sync GEMM with ldmatrix fragment loads (unchanged from R8).
// ---------------------------------------------------------------------------
#define GBM 128
#define GBN 128
#define GBK 32
#define NSTG 3
#define LDAB 20
#define STG  (2*GBM*LDAB*4)
#define GEMM_SMEM (NSTG*STG)

__device__ __forceinline__ void load_chunk16(const __half* __restrict__ A, const __half* __restrict__ BT,
                                             int K, int bm, int bn, int c, uint32_t stage)
{
    int t = threadIdx.x;
    const __half* asrc = A  + (size_t)bm*K + (size_t)c*GBK;
    const __half* bsrc = BT + (size_t)bn*K + (size_t)c*GBK;
#pragma unroll
    for (int i = 0; i < 4; i++){
        int idx = i*128 + t;
        int row = idx >> 2, seg = idx & 3;
        CP_ASYNC16(stage + row*80 + seg*16, asrc + (size_t)row*K + seg*8);
    }
#pragma unroll
    for (int i = 0; i < 4; i++){
        int idx = i*128 + t;
        int row = idx >> 2, seg = idx & 3;
        CP_ASYNC16(stage + GBM*80 + row*80 + seg*16, bsrc + (size_t)row*K + seg*8);
    }
    CP_COMMIT();
}

__global__ __launch_bounds__(128, 2)
void gemm_tc(const __half* __restrict__ A, const __half* __restrict__ BT,
             const float* __restrict__ bias, void* __restrict__ Cv,
             int K, int N, int mode)
{
    extern __shared__ char smem[];
    int t = threadIdx.x;
    int wid = t >> 5, lane = t & 31;
    int grp = lane >> 2, q4 = lane & 3;
    int mw = (wid & 1) * 64, nw = (wid >> 1) * 64;
    int bm = blockIdx.y * GBM, bn = blockIdx.x * GBN;

    int lm = lane >> 3, lr = lane & 7;
    uint32_t aoff = (uint32_t)(((lm & 1)*8 + lr)*80 + (lm >> 1)*16);
    uint32_t boff = (uint32_t)(((lm >> 1)*8 + lr)*80 + (lm & 1)*16);

    float acc[4][8][4];
#pragma unroll
    for (int mi = 0; mi < 4; mi++)
#pragma unroll
        for (int ni = 0; ni < 8; ni++)
#pragma unroll
            for (int r = 0; r < 4; r++) acc[mi][ni][r] = 0.f;

    uint32_t sb = smem_u32(smem);
    const int NC = K / GBK;

    load_chunk16(A, BT, K, bm, bn, 0, sb);
    load_chunk16(A, BT, K, bm, bn, 1, sb + STG);

    for (int c = 0; c < NC; c++){
        int slot = c % NSTG;
        if (c + 1 < NC) { asm volatile("cp.async.wait_group 1;" ::: "memory"); }
        else            { asm volatile("cp.async.wait_group 0;" ::: "memory"); }
        __syncthreads();
        if (c + 2 < NC)
            load_chunk16(A, BT, K, bm, bn, c + 2, sb + ((c+2)%NSTG)*STG);

        uint32_t As_b = sb + slot*STG;
        uint32_t Bs_b = As_b + GBM*80;
#pragma unroll
        for (int ks = 0; ks < 2; ks++){
            uint32_t kb = ks*32;
            uint32_t af[4][4], bf[8][2];
#pragma unroll
            for (int mi = 0; mi < 4; mi++)
                LDSM4(af[mi], As_b + (mw + mi*16)*80 + aoff + kb);
#pragma unroll
            for (int p = 0; p < 4; p++){
                uint32_t r[4];
                LDSM4(r, Bs_b + (nw + p*16)*80 + boff + kb);
                bf[2*p][0] = r[0]; bf[2*p][1] = r[1];
                bf[2*p+1][0] = r[2]; bf[2*p+1][1] = r[3];
            }
#pragma unroll
            for (int mi = 0; mi < 4; mi++)
#pragma unroll
                for (int ni = 0; ni < 8; ni++)
                    mma_f16(acc[mi][ni], af[mi], bf[ni]);
        }
    }

    float* Cf = (float*)Cv;
    __half* Ch = (__half*)Cv;
#pragma unroll
    for (int mi = 0; mi < 4; mi++){
        int r0 = bm + mw + mi*16 + grp;
#pragma unroll
        for (int ni = 0; ni < 8; ni++){
            int col = bn + nw + ni*8 + 2*q4;
            float bx = bias[col], by = bias[col+1];
            float a0 = acc[mi][ni][0] + bx, a1 = acc[mi][ni][1] + by;
            float a2 = acc[mi][ni][2] + bx, a3 = acc[mi][ni][3] + by;
            if (mode & 1){
                a0 = gelu_exact(a0); a1 = gelu_exact(a1);
                a2 = gelu_exact(a2); a3 = gelu_exact(a3);
            }
            if (mode & 2){
                *(__half2*)&Ch[(size_t)r0*N + col]     = __floats2half2_rn(a0, a1);
                *(__half2*)&Ch[(size_t)(r0+8)*N + col] = __floats2half2_rn(a2, a3);
            } else {
                *(float2*)&Cf[(size_t)r0*N + col]     = make_float2(a0, a1);
                *(float2*)&Cf[(size_t)(r0+8)*N + col] = make_float2(a2, a3);
            }
        }
    }
}

// ---------------------------------------------------------------------------
// Weight transpose to fp16 + bias pack
// ---------------------------------------------------------------------------
__global__ __launch_bounds__(256)
void transpose_h(const float* __restrict__ in, __half* __restrict__ out,
                 int R, int C, size_t outStride)
{
    __shared__ float tile[32][33];
    const float* src = in  + (size_t)blockIdx.z * R * C;
    __half*      dst = out + (size_t)blockIdx.z * outStride;
    int r0 = blockIdx.y*32, c0 = blockIdx.x*32;
    int tx = threadIdx.x & 31, ty = threadIdx.x >> 5;
#pragma unroll
    for (int i = 0; i < 4; i++)
        tile[ty + i*8][tx] = src[(size_t)(r0 + ty + i*8)*C + c0 + tx];
    __syncthreads();
#pragma unroll
    for (int i = 0; i < 4; i++)
        dst[(size_t)(c0 + ty + i*8)*R + r0 + tx] = __float2half(tile[tx][ty + i*8]);
}

__global__ __launch_bounds__(256)
void pack_qkv_bias(const float* __restrict__ bq, const float* __restrict__ bk,
                   const float* __restrict__ bv, float* __restrict__ o)
{
    int l = blockIdx.x, t = threadIdx.x;
    for (int i = t; i < HID; i += 256){
        o[l*3*HID + i]         = bq[l*HID + i];
        o[l*3*HID + HID + i]   = bk[l*HID + i];
        o[l*3*HID + 2*HID + i] = bv[l*HID + i];
    }
}

// ---------------------------------------------------------------------------
// Warp-per-row LayerNorm kernels; emit fp32 + fp16 shadow
// ---------------------------------------------------------------------------
__global__ __launch_bounds__(256)
void embed_ln_kernel(const float* __restrict__ emb, const float* __restrict__ pos,
                     const float* __restrict__ tok, const float* __restrict__ gam,
                     const float* __restrict__ bet, float* __restrict__ h,
                     __half* __restrict__ h16)
{
    int w = threadIdx.x >> 5, lane = threadIdx.x & 31;
    int r = blockIdx.x*8 + w;
    int s = r & (SS-1);
    const float* er = emb + (size_t)r*HID;
    const float* pr = pos + (size_t)(s+1)*HID;

    float x[24];
    float sum = 0.f;
#pragma unroll
    for (int i = 0; i < 6; i++){
        int c = i*128 + lane*4;
        float4 e = *(const float4*)&er[c];
        float4 p = *(const float4*)&pr[c];
        float4 tk = *(const float4*)&tok[c];
        x[i*4+0] = e.x + p.x + tk.x;
        x[i*4+1] = e.y + p.y + tk.y;
        x[i*4+2] = e.z + p.z + tk.z;
        x[i*4+3] = e.w + p.w + tk.w;
        sum += x[i*4+0] + x[i*4+1] + x[i*4+2] + x[i*4+3];
    }
    float mean = wred_sum(sum) * (1.f/HID);
    float vs = 0.f;
#pragma unroll
    for (int i = 0; i < 24; i++){ float d = x[i] - mean; vs += d*d; }
    float inv = rsqrtf(wred_sum(vs) * (1.f/HID) + 1e-12f);

    float* hr = h + (size_t)r*HID;
    __half* h16r = h16 + (size_t)r*HID;
#pragma unroll
    for (int i = 0; i < 6; i++){
        int c = i*128 + lane*4;
        float4 g = *(const float4*)&gam[c];
        float4 b = *(const float4*)&bet[c];
        float4 o;
        o.x = (x[i*4+0] - mean)*inv*g.x + b.x;
        o.y = (x[i*4+1] - mean)*inv*g.y + b.y;
        o.z = (x[i*4+2] - mean)*inv*g.z + b.z;
        o.w = (x[i*4+3] - mean)*inv*g.w + b.w;
        *(float4*)&hr[c] = o;
        *(__half2*)&h16r[c]   = __floats2half2_rn(o.x, o.y);
        *(__half2*)&h16r[c+2] = __floats2half2_rn(o.z, o.w);
    }
}

__global__ __launch_bounds__(256)
void add_ln_kernel(const float* __restrict__ hin, const float* __restrict__ tin,
                   const float* __restrict__ gam, const float* __restrict__ bet,
                   float* __restrict__ hout, __half* __restrict__ h16)
{
    int w = threadIdx.x >> 5, lane = threadIdx.x & 31;
    int r = blockIdx.x*8 + w;
    const float* ar = hin + (size_t)r*HID;
    const float* br = tin + (size_t)r*HID;

    float x[24];
    float sum = 0.f;
#pragma unroll
    for (int i = 0; i < 6; i++){
        int c = i*128 + lane*4;
        float4 a = *(const float4*)&ar[c];
        float4 b = *(const float4*)&br[c];
        x[i*4+0] = a.x + b.x; x[i*4+1] = a.y + b.y;
        x[i*4+2] = a.z + b.z; x[i*4+3] = a.w + b.w;
        sum += x[i*4+0] + x[i*4+1] + x[i*4+2] + x[i*4+3];
    }
    float mean = wred_sum(sum) * (1.f/HID);
    float vs = 0.f;
#pragma unroll
    for (int i = 0; i < 24; i++){ float d = x[i] - mean; vs += d*d; }
    float inv = rsqrtf(wred_sum(vs) * (1.f/HID) + 1e-12f);

    float* hr = hout + (size_t)r*HID;
    __half* h16r = h16 + (size_t)r*HID;
#pragma unroll
    for (int i = 0; i < 6; i++){
        int c = i*128 + lane*4;
        float4 g = *(const float4*)&gam[c];
        float4 b = *(const float4*)&bet[c];
        float4 o;
        o.x = (x[i*4+0] - mean)*inv*g.x + b.x;
        o.y = (x[i*4+1] - mean)*inv*g.y + b.y;
        o.z = (x[i*4+2] - mean)*inv*g.z + b.z;
        o.w = (x[i*4+3] - mean)*inv*g.w + b.w;
        *(float4*)&hr[c] = o;
        *(__half2*)&h16r[c]   = __floats2half2_rn(o.x, o.y);
        *(__half2*)&h16r[c+2] = __floats2half2_rn(o.z, o.w);
    }
}

__global__ __launch_bounds__(256)
void final_kernel(const float* __restrict__ h, const float* __restrict__ Wp,
                  const float* __restrict__ bp, float* __restrict__ out)
{
    int w = threadIdx.x >> 5, lane = threadIdx.x & 31;
    int r = blockIdx.x*8 + w;
    const float* hr = h + (size_t)r*HID;
    float sum = 0.f;
#pragma unroll
    for (int i = 0; i < 6; i++){
        int c = i*128 + lane*4;
        float4 a = *(const float4*)&hr[c];
        float4 b = *(const float4*)&Wp[c];
        sum += a.x*b.x + a.y*b.y + a.z*b.z + a.w*b.w;
    }
    sum = wred_sum(sum);
    if (lane == 0) out[r] = 1.f / (1.f + expf(-(sum + bp[0])));
}

// ---------------------------------------------------------------------------
// fp16 tensor-core sliding-window attention.
// qkv16: [ROWS][2304] halves (q|k|v). One block per (b, head, 32-query tile).
// sQ half[32][72], sKV half[320][72], sS float[32][328], sP half[32][328].
// ---------------------------------------------------------------------------
#define QT    32
#define KW    320
#define KVSH  72      // halves
#define SSTR  328     // floats
#define SPSTR 328     // halves
#define SQ_B   0
#define SKV_B  (QT*KVSH*2)                    // 4608
#define SS_B   (SKV_B + KW*KVSH*2)            // 50688
#define SP_B   (SS_B + QT*SSTR*4)             // 92672
#define ATT_SMEM (SP_B + QT*SPSTR*2)          // 113664

__global__ __launch_bounds__(256)
void attn_kernel(const __half* __restrict__ qkv16, const int* __restrict__ km,
                 __half* __restrict__ ag16)
{
    int qt   = blockIdx.x;
    int head = blockIdx.y;
    int b    = blockIdx.z;
    int q0   = qt * QT;
    int kbase = q0 - AW;

    extern __shared__ char smraw[];
    __half* sQ  = (__half*)(smraw + SQ_B);
    __half* sKV = (__half*)(smraw + SKV_B);
    float*  sS  = (float*)(smraw + SS_B);
    __half* sP  = (__half*)(smraw + SP_B);
    uint32_t skv_b = smem_u32(sKV);

    int t = threadIdx.x;
    int wid = t >> 5, lane = t & 31;
    int grp = lane >> 2, q4 = lane & 3;
    const size_t rstr = 3*HID;   // 2304 halves
    const __half* base_b = qkv16 + (size_t)b*SS*rstr;

    // ---- load Q (scaled by 0.125, exact in fp16) ----
    {
        int row = t >> 3, seg = t & 7;
        uint4 qv4 = *(const uint4*)&base_b[(size_t)(q0 + row)*rstr + head*HD + seg*8];
        __half2 sc = __half2half2(__float2half(0.125f));
        __half2* q2 = (__half2*)&qv4;
        q2[0] = __hmul2(q2[0], sc); q2[1] = __hmul2(q2[1], sc);
        q2[2] = __hmul2(q2[2], sc); q2[3] = __hmul2(q2[3], sc);
        *(uint4*)&sQ[row*KVSH + seg*8] = qv4;
    }

    // ---- load K window via cp.async (zero-fill outside [0,S)) ----
    {
        const __half* ksrc = base_b + HID + head*HD;
#pragma unroll
        for (int i = 0; i < 10; i++){
            int idx = i*256 + t;              // 0..2559
            int row = idx >> 3, seg = idx & 7;
            int jg = kbase + row;
            uint32_t nb = (jg >= 0 && jg < SS) ? 16u : 0u;
            int jc = jg < 0 ? 0 : (jg >= SS ? SS-1 : jg);
            CP_ASYNC16Z(skv_b + row*(KVSH*2) + seg*16, ksrc + (size_t)jc*rstr + seg*8, nb);
        }
        CP_COMMIT();
    }
    asm volatile("cp.async.wait_group 0;" ::: "memory");
    __syncthreads();

    // ---- QK^T (fp16): warp w handles keys [w*40, w*40+40) ----
    {
        float acc[2][5][4];
#pragma unroll
        for (int mi = 0; mi < 2; mi++)
#pragma unroll
            for (int nt = 0; nt < 5; nt++)
#pragma unroll
                for (int r = 0; r < 4; r++) acc[mi][nt][r] = 0.f;

#pragma unroll
        for (int ks = 0; ks < 4; ks++){
            int k0 = ks*16;
            uint32_t af[2][4];
#pragma unroll
            for (int mi = 0; mi < 2; mi++){
                int bb = (mi*16 + grp)*KVSH + k0 + 2*q4;
                af[mi][0] = *(const uint32_t*)&sQ[bb];
                af[mi][1] = *(const uint32_t*)&sQ[bb + 8*KVSH];
                af[mi][2] = *(const uint32_t*)&sQ[bb + 8];
                af[mi][3] = *(const uint32_t*)&sQ[bb + 8*KVSH + 8];
            }
#pragma unroll
            for (int nt = 0; nt < 5; nt++){
                int n0 = wid*40 + nt*8;
                uint32_t bf[2];
                int bb = (n0 + grp)*KVSH + k0 + 2*q4;
                bf[0] = *(const uint32_t*)&sKV[bb];
                bf[1] = *(const uint32_t*)&sKV[bb + 8];
                mma_f16(acc[0][nt], af[0], bf);
                mma_f16(acc[1][nt], af[1], bf);
            }
        }
#pragma unroll
        for (int mi = 0; mi < 2; mi++){
            int r0 = mi*16 + grp;
#pragma unroll
            for (int nt = 0; nt < 5; nt++){
                int col = wid*40 + nt*8 + 2*q4;
                *(float2*)&sS[r0*SSTR + col]     = make_float2(acc[mi][nt][0], acc[mi][nt][1]);
                *(float2*)&sS[(r0+8)*SSTR + col] = make_float2(acc[mi][nt][2], acc[mi][nt][3]);
            }
        }
    }
    __syncthreads();

    // ---- kick off V load (overlaps softmax) ----
    {
        const __half* vsrc = base_b + 2*HID + head*HD;
#pragma unroll
        for (int i = 0; i < 10; i++){
            int idx = i*256 + t;
            int row = idx >> 3, seg = idx & 7;
            int jg = kbase + row;
            uint32_t nb = (jg >= 0 && jg < SS) ? 16u : 0u;
            int jc = jg < 0 ? 0 : (jg >= SS ? SS-1 : jg);
            CP_ASYNC16Z(skv_b + row*(KVSH*2) + seg*16, vsrc + (size_t)jc*rstr + seg*8, nb);
        }
        CP_COMMIT();
    }

    // ---- masked softmax: warp w rows w*4..w*4+3; emit fp16 P ----
    {
#pragma unroll
        for (int rr = 0; rr < 4; rr++){
            int qr = wid*4 + rr;
            int qi = q0 + qr;
            float mx = -1e30f;
            for (int j = lane; j < KW; j += 32){
                int jg = kbase + j;
                bool ok = (jg >= 0) && (jg < SS) && (jg >= qi - AW) && (jg <= qi + AW)
                          && (km[b*SS + jg] != 0);
                float sc = ok ? sS[qr*SSTR + j] : -1e30f;
                sS[qr*SSTR + j] = sc;
                mx = fmaxf(mx, sc);
            }
#pragma unroll
            for (int o = 16; o > 0; o >>= 1) mx = fmaxf(mx, __shfl_xor_sync(~0u, mx, o));
            float sum = 0.f;
            for (int j = lane; j < KW; j += 32){
                float p = __expf(sS[qr*SSTR + j] - mx);
                sS[qr*SSTR + j] = p; sum += p;
            }
#pragma unroll
            for (int o = 16; o > 0; o >>= 1) sum += __shfl_xor_sync(~0u, sum, o);
            float inv = 1.f / sum;
            for (int j = lane; j < KW; j += 32)
                sP[qr*SPSTR + j] = __float2half(sS[qr*SSTR + j] * inv);
        }
    }
    asm volatile("cp.async.wait_group 0;" ::: "memory");
    __syncthreads();

    // ---- P @ V (fp16): warp w handles dims [w*8, w*8+8) ----
    {
        int n0 = wid*8;
        float acc[2][4];
#pragma unroll
        for (int mi = 0; mi < 2; mi++)
#pragma unroll
            for (int r = 0; r < 4; r++) acc[mi][r] = 0.f;

#pragma unroll 5
        for (int ks = 0; ks < 20; ks++){
            int k0 = ks*16;
            uint32_t af[2][4], bf[2];
#pragma unroll
            for (int mi = 0; mi < 2; mi++){
                int bb = (mi*16 + grp)*SPSTR + k0 + 2*q4;
                af[mi][0] = *(const uint32_t*)&sP[bb];
                af[mi][1] = *(const uint32_t*)&sP[bb + 8*SPSTR];
                af[mi][2] = *(const uint32_t*)&sP[bb + 8];
                af[mi][3] = *(const uint32_t*)&sP[bb + 8*SPSTR + 8];
            }
            int kk = k0 + 2*q4;
            __half2 b0 = __halves2half2(sKV[(kk  )*KVSH + n0 + grp], sKV[(kk+1)*KVSH + n0 + grp]);
            __half2 b1 = __halves2half2(sKV[(kk+8)*KVSH + n0 + grp], sKV[(kk+9)*KVSH + n0 + grp]);
            bf[0] = *(uint32_t*)&b0;
            bf[1] = *(uint32_t*)&b1;
            mma_f16(acc[0], af[0], bf);
            mma_f16(acc[1], af[1], bf);
        }
#pragma unroll
        for (int mi = 0; mi < 2; mi++){
            int r0 = q0 + mi*16 + grp;
            int col = head*HD + n0 + 2*q4;
            *(__half2*)&ag16[((size_t)(b*SS + r0))*HID + col]     = __floats2half2_rn(acc[mi][0], acc[mi][1]);
            *(__half2*)&ag16[((size_t)(b*SS + r0 + 8))*HID + col] = __floats2half2_rn(acc[mi][2], acc[mi][3]);
        }
    }
}

// ---------------------------------------------------------------------------
// Host launcher
// ---------------------------------------------------------------------------
extern "C" void kernel_launch(void* const* d_in, const int* in_sizes, int n_in,
                              void* d_out, int out_size)
{
    (void)in_sizes; (void)n_in;
    const float* emb   = (const float*)d_in[0];
    const int*   amask = (const int*)  d_in[1];
    const float* pos   = (const float*)d_in[2];
    const float* tok   = (const float*)d_in[3];
    const float* eg    = (const float*)d_in[4];
    const float* eb    = (const float*)d_in[5];
    const float* Wq    = (const float*)d_in[6];
    const float* bq    = (const float*)d_in[7];
    const float* Wk    = (const float*)d_in[8];
    const float* bk    = (const float*)d_in[9];
    const float* Wv    = (const float*)d_in[10];
    const float* bv    = (const float*)d_in[11];
    const float* Wo    = (const float*)d_in[12];
    const float* bo    = (const float*)d_in[13];
    const float* ln1g  = (const float*)d_in[14];
    const float* ln1b  = (const float*)d_in[15];
    const float* Wi    = (const float*)d_in[16];
    const float* bi    = (const float*)d_in[17];
    const float* Wf    = (const float*)d_in[18];
    const float* bf    = (const float*)d_in[19];
    const float* ln2g  = (const float*)d_in[20];
    const float* ln2b  = (const float*)d_in[21];
    const float* Wp    = (const float*)d_in[22];
    const float* bp    = (const float*)d_in[23];

    float* scratch = nullptr;
    cudaGetSymbolAddress((void**)&scratch, g_scratch);
    float*  h     = scratch;                               // ACT floats
    float*  tmp   = scratch + 1*(size_t)ACT;               // ACT floats (fp32 GEMM out)
    __half* qkv16 = (__half*)(scratch + 2*(size_t)ACT);    // ROWS*2304 halves = 1.5*ACT floats
    __half* h16   = (__half*)(scratch + 4*(size_t)ACT);
    __half* a16   = (__half*)(scratch + 4*(size_t)ACT + ACT/2);
    __half* ffn16 = (__half*)(scratch + 5*(size_t)ACT);
    __half* WqkvT = (__half*)(scratch + 7*(size_t)ACT);
    __half* WoT   = WqkvT + 3*(size_t)WT_SM;
    __half* WiT   = WoT   + (size_t)WT_SM;
    __half* WfT   = WiT   + (size_t)WT_LG;
    float*  bqkv  = (float*)(WfT + (size_t)WT_LG);

    cudaFuncSetAttribute(gemm_tc, cudaFuncAttributeMaxDynamicSharedMemorySize, GEMM_SMEM);
    cudaFuncSetAttribute(attn_kernel, cudaFuncAttributeMaxDynamicSharedMemorySize, ATT_SMEM);

    const size_t LSTR = (size_t)3*HID*HID;

    transpose_h<<<dim3(HID/32, HID/32, NL), 256>>>(Wq, WqkvT,                     HID, HID, LSTR);
    transpose_h<<<dim3(HID/32, HID/32, NL), 256>>>(Wk, WqkvT + (size_t)HID*HID,   HID, HID, LSTR);
    transpose_h<<<dim3(HID/32, HID/32, NL), 256>>>(Wv, WqkvT + (size_t)2*HID*HID, HID, HID, LSTR);
    transpose_h<<<dim3(HID/32, HID/32, NL), 256>>>(Wo, WoT, HID, HID, (size_t)HID*HID);
    transpose_h<<<dim3(4*HID/32, HID/32, NL), 256>>>(Wi, WiT, HID, 4*HID, (size_t)4*HID*HID);
    transpose_h<<<dim3(HID/32, 4*HID/32, NL), 256>>>(Wf, WfT, 4*HID, HID, (size_t)4*HID*HID);
    pack_qkv_bias<<<NL, 256>>>(bq, bk, bv, bqkv);

    embed_ln_kernel<<<ROWS/8, 256>>>(emb, pos, tok, eg, eb, h, h16);

    dim3 gqkv(3*HID/GBN, ROWS/GBM);
    dim3 g768(HID/GBN, ROWS/GBM);
    dim3 g3072(4*HID/GBN, ROWS/GBM);
    dim3 gattn(SS/QT, NH, BB);

    for (int l = 0; l < NL; l++) {
        const size_t wofs  = (size_t)l * HID * HID;
        const size_t bofs  = (size_t)l * HID;
        const size_t wlofs = (size_t)l * HID * 4*HID;
        const size_t blofs = (size_t)l * 4*HID;

        gemm_tc<<<gqkv, 128, GEMM_SMEM>>>(h16, WqkvT + l*LSTR, bqkv + l*3*HID, qkv16, HID, 3*HID, 2);

        attn_kernel<<<gattn, 256, ATT_SMEM>>>(qkv16, amask, a16);

        gemm_tc<<<g768, 128, GEMM_SMEM>>>(a16, WoT + wofs, bo + bofs, tmp, HID, HID, 0);
        add_ln_kernel<<<ROWS/8, 256>>>(h, tmp, ln1g + bofs, ln1b + bofs, h, h16);

        gemm_tc<<<g3072, 128, GEMM_SMEM>>>(h16, WiT + wlofs, bi + blofs, ffn16, HID, 4*HID, 3);
        gemm_tc<<<g768, 128, GEMM_SMEM>>>(ffn16, WfT + wlofs, bf + bofs, tmp, 4*HID, HID, 0);
        add_ln_kernel<<<ROWS/8, 256>>>(h, tmp, ln2g + bofs, ln2b + bofs, h, h16);
    }

    final_kernel<<<ROWS/8, 256>>>(h, Wp, bp, (float*)d_out);
    (void)out_size;
}

// round 10
// speedup vs baseline: 6.0762x; 1.0332x over previous
#include <cuda_runtime.h>
#include <cuda_fp16.h>
#include <math.h>
#include <stdint.h>

// Problem constants
#define BB   2
#define SS   4096
#define HID  768
#define NL   4
#define NH   12
#define HD   64
#define AW   128
#define ROWS (BB*SS)      // 8192

// ---------------------------------------------------------------------------
// Scratch
// ---------------------------------------------------------------------------
#define ACT (ROWS*HID)
#define WT_SM (NL*HID*HID)
#define WT_LG (NL*HID*4*HID)
__device__ float g_scratch[9*(size_t)ACT + 4*(size_t)WT_SM + 2*(size_t)WT_LG];

// ---------------------------------------------------------------------------
// helpers
// ---------------------------------------------------------------------------
__device__ __forceinline__ uint32_t smem_u32(const void* p){
    uint32_t a;
    asm("{ .reg .u64 t; cvta.to.shared.u64 t, %1; cvt.u32.u64 %0, t; }" : "=r"(a) : "l"(p));
    return a;
}
#define CP_ASYNC16(dst,src)      asm volatile("cp.async.cg.shared.global [%0], [%1], 16;" :: "r"(dst), "l"(src))
#define CP_ASYNC16Z(dst,src,nb)  asm volatile("cp.async.cg.shared.global [%0], [%1], 16, %2;" :: "r"(dst), "l"(src), "r"(nb))
#define CP_COMMIT() asm volatile("cp.async.commit_group;" ::: "memory")
#define LDSM4(r, a) \
    asm volatile("ldmatrix.sync.aligned.m8n8.x4.shared.b16 {%0,%1,%2,%3}, [%4];" \
        : "=r"((r)[0]),"=r"((r)[1]),"=r"((r)[2]),"=r"((r)[3]) : "r"(a))
#define LDSM2T(r, a) \
    asm volatile("ldmatrix.sync.aligned.m8n8.x2.trans.shared.b16 {%0,%1}, [%2];" \
        : "=r"((r)[0]),"=r"((r)[1]) : "r"(a))

__device__ __forceinline__ void mma_f16(float* d, const uint32_t* a, const uint32_t* b){
    asm volatile("mma.sync.aligned.m16n8k16.row.col.f32.f16.f16.f32 "
        "{%0,%1,%2,%3}, {%4,%5,%6,%7}, {%8,%9}, {%0,%1,%2,%3};"
        : "+f"(d[0]),"+f"(d[1]),"+f"(d[2]),"+f"(d[3])
        : "r"(a[0]),"r"(a[1]),"r"(a[2]),"r"(a[3]), "r"(b[0]),"r"(b[1]));
}
__device__ __forceinline__ float gelu_exact(float x){
    return 0.5f * x * (1.f + erff(x * 0.70710678118654752f));
}
__device__ __forceinline__ float wred_sum(float v){
#pragma unroll
    for (int o = 16; o > 0; o >>= 1) v += __shfl_xor_sync(~0u, v, o);
    return v;
}

// ---------------------------------------------------------------------------
// fp16 mma.sync GEMM with ldmatrix fragment loads.
// mode bits: 1 = gelu, 2 = fp16 output, 4 = qkv bias select (bias/bK/bV by bn)
// ---------------------------------------------------------------------------
#define GBM 128
#define GBN 128
#define GBK 32
#define NSTG 3
#define LDAB 20
#define STG  (2*GBM*LDAB*4)
#define GEMM_SMEM (NSTG*STG)

__device__ __forceinline__ void load_chunk16(const __half* __restrict__ A, const __half* __restrict__ BT,
                                             int K, int bm, int bn, int c, uint32_t stage)
{
    int t = threadIdx.x;
    const __half* asrc = A  + (size_t)bm*K + (size_t)c*GBK;
    const __half* bsrc = BT + (size_t)bn*K + (size_t)c*GBK;
#pragma unroll
    for (int i = 0; i < 4; i++){
        int idx = i*128 + t;
        int row = idx >> 2, seg = idx & 3;
        CP_ASYNC16(stage + row*80 + seg*16, asrc + (size_t)row*K + seg*8);
    }
#pragma unroll
    for (int i = 0; i < 4; i++){
        int idx = i*128 + t;
        int row = idx >> 2, seg = idx & 3;
        CP_ASYNC16(stage + GBM*80 + row*80 + seg*16, bsrc + (size_t)row*K + seg*8);
    }
    CP_COMMIT();
}

__global__ __launch_bounds__(128, 2)
void gemm_tc(const __half* __restrict__ A, const __half* __restrict__ BT,
             const float* __restrict__ bias, const float* __restrict__ bK,
             const float* __restrict__ bV, void* __restrict__ Cv,
             int K, int N, int mode)
{
    extern __shared__ char smem[];
    int t = threadIdx.x;
    int wid = t >> 5, lane = t & 31;
    int grp = lane >> 2, q4 = lane & 3;
    int mw = (wid & 1) * 64, nw = (wid >> 1) * 64;
    int bm = blockIdx.y * GBM, bn = blockIdx.x * GBN;

    int lm = lane >> 3, lr = lane & 7;
    uint32_t aoff = (uint32_t)(((lm & 1)*8 + lr)*80 + (lm >> 1)*16);
    uint32_t boff = (uint32_t)(((lm >> 1)*8 + lr)*80 + (lm & 1)*16);

    float acc[4][8][4];
#pragma unroll
    for (int mi = 0; mi < 4; mi++)
#pragma unroll
        for (int ni = 0; ni < 8; ni++)
#pragma unroll
            for (int r = 0; r < 4; r++) acc[mi][ni][r] = 0.f;

    uint32_t sb = smem_u32(smem);
    const int NC = K / GBK;

    load_chunk16(A, BT, K, bm, bn, 0, sb);
    load_chunk16(A, BT, K, bm, bn, 1, sb + STG);

    for (int c = 0; c < NC; c++){
        int slot = c % NSTG;
        if (c + 1 < NC) { asm volatile("cp.async.wait_group 1;" ::: "memory"); }
        else            { asm volatile("cp.async.wait_group 0;" ::: "memory"); }
        __syncthreads();
        if (c + 2 < NC)
            load_chunk16(A, BT, K, bm, bn, c + 2, sb + ((c+2)%NSTG)*STG);

        uint32_t As_b = sb + slot*STG;
        uint32_t Bs_b = As_b + GBM*80;
#pragma unroll
        for (int ks = 0; ks < 2; ks++){
            uint32_t kb = ks*32;
            uint32_t af[4][4], bf[8][2];
#pragma unroll
            for (int mi = 0; mi < 4; mi++)
                LDSM4(af[mi], As_b + (mw + mi*16)*80 + aoff + kb);
#pragma unroll
            for (int p = 0; p < 4; p++){
                uint32_t r[4];
                LDSM4(r, Bs_b + (nw + p*16)*80 + boff + kb);
                bf[2*p][0] = r[0]; bf[2*p][1] = r[1];
                bf[2*p+1][0] = r[2]; bf[2*p+1][1] = r[3];
            }
#pragma unroll
            for (int mi = 0; mi < 4; mi++)
#pragma unroll
                for (int ni = 0; ni < 8; ni++)
                    mma_f16(acc[mi][ni], af[mi], bf[ni]);
        }
    }

    // bias select for fused qkv GEMM (tile never straddles a 768 boundary)
    const float* bp = bias;
    int coff = 0;
    if (mode & 4){
        int sel = bn / HID;
        bp = (sel == 0) ? bias : (sel == 1 ? bK : bV);
        coff = sel * HID;
    }

    float* Cf = (float*)Cv;
    __half* Ch = (__half*)Cv;
#pragma unroll
    for (int mi = 0; mi < 4; mi++){
        int r0 = bm + mw + mi*16 + grp;
#pragma unroll
        for (int ni = 0; ni < 8; ni++){
            int col = bn + nw + ni*8 + 2*q4;
            float bx = bp[col - coff], by = bp[col + 1 - coff];
            float a0 = acc[mi][ni][0] + bx, a1 = acc[mi][ni][1] + by;
            float a2 = acc[mi][ni][2] + bx, a3 = acc[mi][ni][3] + by;
            if (mode & 1){
                a0 = gelu_exact(a0); a1 = gelu_exact(a1);
                a2 = gelu_exact(a2); a3 = gelu_exact(a3);
            }
            if (mode & 2){
                *(__half2*)&Ch[(size_t)r0*N + col]     = __floats2half2_rn(a0, a1);
                *(__half2*)&Ch[(size_t)(r0+8)*N + col] = __floats2half2_rn(a2, a3);
            } else {
                *(float2*)&Cf[(size_t)r0*N + col]     = make_float2(a0, a1);
                *(float2*)&Cf[(size_t)(r0+8)*N + col] = make_float2(a2, a3);
            }
        }
    }
}

// ---------------------------------------------------------------------------
// Weight transposes to fp16
// ---------------------------------------------------------------------------
__global__ __launch_bounds__(256)
void transpose_h(const float* __restrict__ in, __half* __restrict__ out,
                 int R, int C, size_t outStride)
{
    __shared__ float tile[32][33];
    const float* src = in  + (size_t)blockIdx.z * R * C;
    __half*      dst = out + (size_t)blockIdx.z * outStride;
    int r0 = blockIdx.y*32, c0 = blockIdx.x*32;
    int tx = threadIdx.x & 31, ty = threadIdx.x >> 5;
#pragma unroll
    for (int i = 0; i < 4; i++)
        tile[ty + i*8][tx] = src[(size_t)(r0 + ty + i*8)*C + c0 + tx];
    __syncthreads();
#pragma unroll
    for (int i = 0; i < 4; i++)
        dst[(size_t)(c0 + ty + i*8)*R + r0 + tx] = __float2half(tile[tx][ty + i*8]);
}

// batched q/k/v transpose: z = m*NL + l, out layer block = [WqT;WkT;WvT]
__global__ __launch_bounds__(256)
void transpose_qkv(const float* __restrict__ Wq, const float* __restrict__ Wk,
                   const float* __restrict__ Wv, __half* __restrict__ out)
{
    __shared__ float tile[32][33];
    int z = blockIdx.z;
    int m = z / NL, l = z % NL;
    const float* src = (m == 0 ? Wq : (m == 1 ? Wk : Wv)) + (size_t)l*HID*HID;
    __half* dst = out + (size_t)l*3*HID*HID + (size_t)m*HID*HID;
    int r0 = blockIdx.y*32, c0 = blockIdx.x*32;
    int tx = threadIdx.x & 31, ty = threadIdx.x >> 5;
#pragma unroll
    for (int i = 0; i < 4; i++)
        tile[ty + i*8][tx] = src[(size_t)(r0 + ty + i*8)*HID + c0 + tx];
    __syncthreads();
#pragma unroll
    for (int i = 0; i < 4; i++)
        dst[(size_t)(c0 + ty + i*8)*HID + r0 + tx] = __float2half(tile[tx][ty + i*8]);
}

// ---------------------------------------------------------------------------
// Warp-per-row LayerNorm kernels
// ---------------------------------------------------------------------------
__global__ __launch_bounds__(256)
void embed_ln_kernel(const float* __restrict__ emb, const float* __restrict__ pos,
                     const float* __restrict__ tok, const float* __restrict__ gam,
                     const float* __restrict__ bet, float* __restrict__ h,
                     __half* __restrict__ h16)
{
    int w = threadIdx.x >> 5, lane = threadIdx.x & 31;
    int r = blockIdx.x*8 + w;
    int s = r & (SS-1);
    const float* er = emb + (size_t)r*HID;
    const float* pr = pos + (size_t)(s+1)*HID;

    float x[24];
    float sum = 0.f;
#pragma unroll
    for (int i = 0; i < 6; i++){
        int c = i*128 + lane*4;
        float4 e = *(const float4*)&er[c];
        float4 p = *(const float4*)&pr[c];
        float4 tk = *(const float4*)&tok[c];
        x[i*4+0] = e.x + p.x + tk.x;
        x[i*4+1] = e.y + p.y + tk.y;
        x[i*4+2] = e.z + p.z + tk.z;
        x[i*4+3] = e.w + p.w + tk.w;
        sum += x[i*4+0] + x[i*4+1] + x[i*4+2] + x[i*4+3];
    }
    float mean = wred_sum(sum) * (1.f/HID);
    float vs = 0.f;
#pragma unroll
    for (int i = 0; i < 24; i++){ float d = x[i] - mean; vs += d*d; }
    float inv = rsqrtf(wred_sum(vs) * (1.f/HID) + 1e-12f);

    float* hr = h + (size_t)r*HID;
    __half* h16r = h16 + (size_t)r*HID;
#pragma unroll
    for (int i = 0; i < 6; i++){
        int c = i*128 + lane*4;
        float4 g = *(const float4*)&gam[c];
        float4 b = *(const float4*)&bet[c];
        float4 o;
        o.x = (x[i*4+0] - mean)*inv*g.x + b.x;
        o.y = (x[i*4+1] - mean)*inv*g.y + b.y;
        o.z = (x[i*4+2] - mean)*inv*g.z + b.z;
        o.w = (x[i*4+3] - mean)*inv*g.w + b.w;
        *(float4*)&hr[c] = o;
        *(__half2*)&h16r[c]   = __floats2half2_rn(o.x, o.y);
        *(__half2*)&h16r[c+2] = __floats2half2_rn(o.z, o.w);
    }
}

// residual h (fp32) + tin (fp16) -> LN -> h fp32 + h16
__global__ __launch_bounds__(256)
void add_ln_kernel(const float* __restrict__ hin, const __half* __restrict__ tin,
                   const float* __restrict__ gam, const float* __restrict__ bet,
                   float* __restrict__ hout, __half* __restrict__ h16)
{
    int w = threadIdx.x >> 5, lane = threadIdx.x & 31;
    int r = blockIdx.x*8 + w;
    const float* ar = hin + (size_t)r*HID;
    const __half* br = tin + (size_t)r*HID;

    float x[24];
    float sum = 0.f;
#pragma unroll
    for (int i = 0; i < 6; i++){
        int c = i*128 + lane*4;
        float4 a = *(const float4*)&ar[c];
        __half2 b0 = *(const __half2*)&br[c];
        __half2 b1 = *(const __half2*)&br[c+2];
        float2 f0 = __half22float2(b0), f1 = __half22float2(b1);
        x[i*4+0] = a.x + f0.x; x[i*4+1] = a.y + f0.y;
        x[i*4+2] = a.z + f1.x; x[i*4+3] = a.w + f1.y;
        sum += x[i*4+0] + x[i*4+1] + x[i*4+2] + x[i*4+3];
    }
    float mean = wred_sum(sum) * (1.f/HID);
    float vs = 0.f;
#pragma unroll
    for (int i = 0; i < 24; i++){ float d = x[i] - mean; vs += d*d; }
    float inv = rsqrtf(wred_sum(vs) * (1.f/HID) + 1e-12f);

    float* hr = hout + (size_t)r*HID;
    __half* h16r = h16 + (size_t)r*HID;
#pragma unroll
    for (int i = 0; i < 6; i++){
        int c = i*128 + lane*4;
        float4 g = *(const float4*)&gam[c];
        float4 b = *(const float4*)&bet[c];
        float4 o;
        o.x = (x[i*4+0] - mean)*inv*g.x + b.x;
        o.y = (x[i*4+1] - mean)*inv*g.y + b.y;
        o.z = (x[i*4+2] - mean)*inv*g.z + b.z;
        o.w = (x[i*4+3] - mean)*inv*g.w + b.w;
        *(float4*)&hr[c] = o;
        *(__half2*)&h16r[c]   = __floats2half2_rn(o.x, o.y);
        *(__half2*)&h16r[c+2] = __floats2half2_rn(o.z, o.w);
    }
}

__global__ __launch_bounds__(256)
void final_kernel(const float* __restrict__ h, const float* __restrict__ Wp,
                  const float* __restrict__ bp, float* __restrict__ out)
{
    int w = threadIdx.x >> 5, lane = threadIdx.x & 31;
    int r = blockIdx.x*8 + w;
    const float* hr = h + (size_t)r*HID;
    float sum = 0.f;
#pragma unroll
    for (int i = 0; i < 6; i++){
        int c = i*128 + lane*4;
        float4 a = *(const float4*)&hr[c];
        float4 b = *(const float4*)&Wp[c];
        sum += a.x*b.x + a.y*b.y + a.z*b.z + a.w*b.w;
    }
    sum = wred_sum(sum);
    if (lane == 0) out[r] = 1.f / (1.f + expf(-(sum + bp[0])));
}

// ---------------------------------------------------------------------------
// fp16 tensor-core sliding-window attention.
// ---------------------------------------------------------------------------
#define QT    32
#define KW    320
#define KVSH  72      // halves
#define SSTR  328     // floats
#define SPSTR 328     // halves
#define SQ_B   0
#define SKV_B  (QT*KVSH*2)                    // 4608
#define SS_B   (SKV_B + KW*KVSH*2)            // 50688
#define SP_B   (SS_B + QT*SSTR*4)             // 92672
#define SM_B   (SP_B + QT*SPSTR*2)            // 113664
#define ATT_SMEM (SM_B + KW)                  // 113984

__global__ __launch_bounds__(256)
void attn_kernel(const __half* __restrict__ qkv16, const int* __restrict__ km,
                 __half* __restrict__ ag16)
{
    int qt   = blockIdx.x;
    int head = blockIdx.y;
    int b    = blockIdx.z;
    int q0   = qt * QT;
    int kbase = q0 - AW;

    extern __shared__ char smraw[];
    __half* sQ  = (__half*)(smraw + SQ_B);
    __half* sKV = (__half*)(smraw + SKV_B);
    float*  sS  = (float*)(smraw + SS_B);
    __half* sP  = (__half*)(smraw + SP_B);
    uint8_t* sM = (uint8_t*)(smraw + SM_B);
    uint32_t skv_b = smem_u32(sKV);

    int t = threadIdx.x;
    int wid = t >> 5, lane = t & 31;
    int grp = lane >> 2, q4 = lane & 3;
    const size_t rstr = 3*HID;
    const __half* base_b = qkv16 + (size_t)b*SS*rstr;

    // ---- load Q (scaled) ----
    {
        int row = t >> 3, seg = t & 7;
        uint4 qv4 = *(const uint4*)&base_b[(size_t)(q0 + row)*rstr + head*HD + seg*8];
        __half2 sc = __half2half2(__float2half(0.125f));
        __half2* q2 = (__half2*)&qv4;
        q2[0] = __hmul2(q2[0], sc); q2[1] = __hmul2(q2[1], sc);
        q2[2] = __hmul2(q2[2], sc); q2[3] = __hmul2(q2[3], sc);
        *(uint4*)&sQ[row*KVSH + seg*8] = qv4;
    }

    // ---- load K window via cp.async + key-mask preload ----
    {
        const __half* ksrc = base_b + HID + head*HD;
#pragma unroll
        for (int i = 0; i < 10; i++){
            int idx = i*256 + t;
            int row = idx >> 3, seg = idx & 7;
            int jg = kbase + row;
            uint32_t nb = (jg >= 0 && jg < SS) ? 16u : 0u;
            int jc = jg < 0 ? 0 : (jg >= SS ? SS-1 : jg);
            CP_ASYNC16Z(skv_b + row*(KVSH*2) + seg*16, ksrc + (size_t)jc*rstr + seg*8, nb);
        }
        CP_COMMIT();
        if (t < KW){
            int jg = kbase + t;
            sM[t] = (jg >= 0 && jg < SS && km[b*SS + jg] != 0) ? 1 : 0;
        }
        if (t >= 256-64 && t < 256){} // no-op keep
    }
    asm volatile("cp.async.wait_group 0;" ::: "memory");
    __syncthreads();

    // ---- QK^T (fp16) ----
    {
        float acc[2][5][4];
#pragma unroll
        for (int mi = 0; mi < 2; mi++)
#pragma unroll
            for (int nt = 0; nt < 5; nt++)
#pragma unroll
                for (int r = 0; r < 4; r++) acc[mi][nt][r] = 0.f;

#pragma unroll
        for (int ks = 0; ks < 4; ks++){
            int k0 = ks*16;
            uint32_t af[2][4];
#pragma unroll
            for (int mi = 0; mi < 2; mi++){
                int bb = (mi*16 + grp)*KVSH + k0 + 2*q4;
                af[mi][0] = *(const uint32_t*)&sQ[bb];
                af[mi][1] = *(const uint32_t*)&sQ[bb + 8*KVSH];
                af[mi][2] = *(const uint32_t*)&sQ[bb + 8];
                af[mi][3] = *(const uint32_t*)&sQ[bb + 8*KVSH + 8];
            }
#pragma unroll
            for (int nt = 0; nt < 5; nt++){
                int n0 = wid*40 + nt*8;
                uint32_t bf[2];
                int bb = (n0 + grp)*KVSH + k0 + 2*q4;
                bf[0] = *(const uint32_t*)&sKV[bb];
                bf[1] = *(const uint32_t*)&sKV[bb + 8];
                mma_f16(acc[0][nt], af[0], bf);
                mma_f16(acc[1][nt], af[1], bf);
            }
        }
#pragma unroll
        for (int mi = 0; mi < 2; mi++){
            int r0 = mi*16 + grp;
#pragma unroll
            for (int nt = 0; nt < 5; nt++){
                int col = wid*40 + nt*8 + 2*q4;
                *(float2*)&sS[r0*SSTR + col]     = make_float2(acc[mi][nt][0], acc[mi][nt][1]);
                *(float2*)&sS[(r0+8)*SSTR + col] = make_float2(acc[mi][nt][2], acc[mi][nt][3]);
            }
        }
    }
    __syncthreads();

    // ---- V load (overlaps softmax) ----
    {
        const __half* vsrc = base_b + 2*HID + head*HD;
#pragma unroll
        for (int i = 0; i < 10; i++){
            int idx = i*256 + t;
            int row = idx >> 3, seg = idx & 7;
            int jg = kbase + row;
            uint32_t nb = (jg >= 0 && jg < SS) ? 16u : 0u;
            int jc = jg < 0 ? 0 : (jg >= SS ? SS-1 : jg);
            CP_ASYNC16Z(skv_b + row*(KVSH*2) + seg*16, vsrc + (size_t)jc*rstr + seg*8, nb);
        }
        CP_COMMIT();
    }

    // ---- masked softmax (band test in local coords + smem key mask) ----
    {
#pragma unroll
        for (int rr = 0; rr < 4; rr++){
            int qr = wid*4 + rr;
            float mx = -1e30f;
            for (int j = lane; j < KW; j += 32){
                bool ok = (j >= qr) && (j <= qr + 2*AW) && sM[j];
                float sc = ok ? sS[qr*SSTR + j] : -1e30f;
                sS[qr*SSTR + j] = sc;
                mx = fmaxf(mx, sc);
            }
#pragma unroll
            for (int o = 16; o > 0; o >>= 1) mx = fmaxf(mx, __shfl_xor_sync(~0u, mx, o));
            float sum = 0.f;
            for (int j = lane; j < KW; j += 32){
                float p = __expf(sS[qr*SSTR + j] - mx);
                sS[qr*SSTR + j] = p; sum += p;
            }
#pragma unroll
            for (int o = 16; o > 0; o >>= 1) sum += __shfl_xor_sync(~0u, sum, o);
            float inv = 1.f / sum;
            for (int j = lane; j < KW; j += 32)
                sP[qr*SPSTR + j] = __float2half(sS[qr*SSTR + j] * inv);
        }
    }
    asm volatile("cp.async.wait_group 0;" ::: "memory");
    __syncthreads();

    // ---- P @ V (fp16), V B-fragments via ldmatrix.trans ----
    {
        int n0 = wid*8;
        float acc[2][4];
#pragma unroll
        for (int mi = 0; mi < 2; mi++)
#pragma unroll
            for (int r = 0; r < 4; r++) acc[mi][r] = 0.f;

#pragma unroll 5
        for (int ks = 0; ks < 20; ks++){
            int k0 = ks*16;
            uint32_t af[2][4], bf[2];
#pragma unroll
            for (int mi = 0; mi < 2; mi++){
                int bb = (mi*16 + grp)*SPSTR + k0 + 2*q4;
                af[mi][0] = *(const uint32_t*)&sP[bb];
                af[mi][1] = *(const uint32_t*)&sP[bb + 8*SPSTR];
                af[mi][2] = *(const uint32_t*)&sP[bb + 8];
                af[mi][3] = *(const uint32_t*)&sP[bb + 8*SPSTR + 8];
            }
            LDSM2T(bf, skv_b + (uint32_t)(k0 + (lane & 15))*(KVSH*2) + n0*2);
            mma_f16(acc[0], af[0], bf);
            mma_f16(acc[1], af[1], bf);
        }
#pragma unroll
        for (int mi = 0; mi < 2; mi++){
            int r0 = q0 + mi*16 + grp;
            int col = head*HD + n0 + 2*q4;
            *(__half2*)&ag16[((size_t)(b*SS + r0))*HID + col]     = __floats2half2_rn(acc[mi][0], acc[mi][1]);
            *(__half2*)&ag16[((size_t)(b*SS + r0 + 8))*HID + col] = __floats2half2_rn(acc[mi][2], acc[mi][3]);
        }
    }
}

// ---------------------------------------------------------------------------
// Host launcher
// ---------------------------------------------------------------------------
extern "C" void kernel_launch(void* const* d_in, const int* in_sizes, int n_in,
                              void* d_out, int out_size)
{
    (void)in_sizes; (void)n_in;
    const float* emb   = (const float*)d_in[0];
    const int*   amask = (const int*)  d_in[1];
    const float* pos   = (const float*)d_in[2];
    const float* tok   = (const float*)d_in[3];
    const float* eg    = (const float*)d_in[4];
    const float* eb    = (const float*)d_in[5];
    const float* Wq    = (const float*)d_in[6];
    const float* bq    = (const float*)d_in[7];
    const float* Wk    = (const float*)d_in[8];
    const float* bk    = (const float*)d_in[9];
    const float* Wv    = (const float*)d_in[10];
    const float* bv    = (const float*)d_in[11];
    const float* Wo    = (const float*)d_in[12];
    const float* bo    = (const float*)d_in[13];
    const float* ln1g  = (const float*)d_in[14];
    const float* ln1b  = (const float*)d_in[15];
    const float* Wi    = (const float*)d_in[16];
    const float* bi    = (const float*)d_in[17];
    const float* Wf    = (const float*)d_in[18];
    const float* bf    = (const float*)d_in[19];
    const float* ln2g  = (const float*)d_in[20];
    const float* ln2b  = (const float*)d_in[21];
    const float* Wp    = (const float*)d_in[22];
    const float* bp    = (const float*)d_in[23];

    float* scratch = nullptr;
    cudaGetSymbolAddress((void**)&scratch, g_scratch);
    float*  h     = scratch;                               // ACT floats
    __half* tmp16 = (__half*)(scratch + 1*(size_t)ACT);    // ACT halves
    __half* qkv16 = (__half*)(scratch + 2*(size_t)ACT);    // ROWS*2304 halves
    __half* h16   = (__half*)(scratch + 4*(size_t)ACT);
    __half* a16   = (__half*)(scratch + 4*(size_t)ACT + ACT/2);
    __half* ffn16 = (__half*)(scratch + 5*(size_t)ACT);
    __half* WqkvT = (__half*)(scratch + 7*(size_t)ACT);
    __half* WoT   = WqkvT + 3*(size_t)WT_SM;
    __half* WiT   = WoT   + (size_t)WT_SM;
    __half* WfT   = WiT   + (size_t)WT_LG;

    cudaFuncSetAttribute(gemm_tc, cudaFuncAttributeMaxDynamicSharedMemorySize, GEMM_SMEM);
    cudaFuncSetAttribute(attn_kernel, cudaFuncAttributeMaxDynamicSharedMemorySize, ATT_SMEM);

    const size_t LSTR = (size_t)3*HID*HID;

    // launch order: 0 embed, 1-4 transposes, 5 first gemm (ncu -s 5 captures it)
    embed_ln_kernel<<<ROWS/8, 256>>>(emb, pos, tok, eg, eb, h, h16);
    transpose_qkv<<<dim3(HID/32, HID/32, 3*NL), 256>>>(Wq, Wk, Wv, WqkvT);
    transpose_h<<<dim3(HID/32, HID/32, NL), 256>>>(Wo, WoT, HID, HID, (size_t)HID*HID);
    transpose_h<<<dim3(4*HID/32, HID/32, NL), 256>>>(Wi, WiT, HID, 4*HID, (size_t)4*HID*HID);
    transpose_h<<<dim3(HID/32, 4*HID/32, NL), 256>>>(Wf, WfT, 4*HID, HID, (size_t)4*HID*HID);

    dim3 gqkv(3*HID/GBN, ROWS/GBM);
    dim3 g768(HID/GBN, ROWS/GBM);
    dim3 g3072(4*HID/GBN, ROWS/GBM);
    dim3 gattn(SS/QT, NH, BB);

    for (int l = 0; l < NL; l++) {
        const size_t wofs  = (size_t)l * HID * HID;
        const size_t bofs  = (size_t)l * HID;
        const size_t wlofs = (size_t)l * HID * 4*HID;
        const size_t blofs = (size_t)l * 4*HID;

        gemm_tc<<<gqkv, 128, GEMM_SMEM>>>(h16, WqkvT + l*LSTR, bq + bofs, bk + bofs, bv + bofs,
                                          qkv16, HID, 3*HID, 2|4);

        attn_kernel<<<gattn, 256, ATT_SMEM>>>(qkv16, amask, a16);

        gemm_tc<<<g768, 128, GEMM_SMEM>>>(a16, WoT + wofs, bo + bofs, bo, bo, tmp16, HID, HID, 2);
        add_ln_kernel<<<ROWS/8, 256>>>(h, tmp16, ln1g + bofs, ln1b + bofs, h, h16);

        gemm_tc<<<g3072, 128, GEMM_SMEM>>>(h16, WiT + wlofs, bi + blofs, bi, bi, ffn16, HID, 4*HID, 3);
        gemm_tc<<<g768, 128, GEMM_SMEM>>>(ffn16, WfT + wlofs, bf + bofs, bf, bf, tmp16, 4*HID, HID, 2);
        add_ln_kernel<<<ROWS/8, 256>>>(h, tmp16, ln2g + bofs, ln2b + bofs, h, h16);
    }

    final_kernel<<<ROWS/8, 256>>>(h, Wp, bp, (float*)d_out);
    (void)out_size;
}

// round 11
// speedup vs baseline: 6.0929x; 1.0027x over previous
#include <cuda_runtime.h>
#include <cuda_fp16.h>
#include <math.h>
#include <stdint.h>

// Problem constants
#define BB   2
#define SS   4096
#define HID  768
#define NL   4
#define NH   12
#define HD   64
#define AW   128
#define ROWS (BB*SS)      // 8192

// ---------------------------------------------------------------------------
// Scratch
// ---------------------------------------------------------------------------
#define ACT (ROWS*HID)
#define WT_SM (NL*HID*HID)
#define WT_LG (NL*HID*4*HID)
__device__ float g_scratch[9*(size_t)ACT + 4*(size_t)WT_SM + 2*(size_t)WT_LG];

// ---------------------------------------------------------------------------
// helpers
// ---------------------------------------------------------------------------
__device__ __forceinline__ uint32_t smem_u32(const void* p){
    uint32_t a;
    asm("{ .reg .u64 t; cvta.to.shared.u64 t, %1; cvt.u32.u64 %0, t; }" : "=r"(a) : "l"(p));
    return a;
}
#define CP_ASYNC16(dst,src)      asm volatile("cp.async.cg.shared.global [%0], [%1], 16;" :: "r"(dst), "l"(src))
#define CP_ASYNC16Z(dst,src,nb)  asm volatile("cp.async.cg.shared.global [%0], [%1], 16, %2;" :: "r"(dst), "l"(src), "r"(nb))
#define CP_COMMIT() asm volatile("cp.async.commit_group;" ::: "memory")
#define LDSM4(r, a) \
    asm volatile("ldmatrix.sync.aligned.m8n8.x4.shared.b16 {%0,%1,%2,%3}, [%4];" \
        : "=r"((r)[0]),"=r"((r)[1]),"=r"((r)[2]),"=r"((r)[3]) : "r"(a))
#define LDSM2T(r, a) \
    asm volatile("ldmatrix.sync.aligned.m8n8.x2.trans.shared.b16 {%0,%1}, [%2];" \
        : "=r"((r)[0]),"=r"((r)[1]) : "r"(a))

__device__ __forceinline__ void mma_f16(float* d, const uint32_t* a, const uint32_t* b){
    asm volatile("mma.sync.aligned.m16n8k16.row.col.f32.f16.f16.f32 "
        "{%0,%1,%2,%3}, {%4,%5,%6,%7}, {%8,%9}, {%0,%1,%2,%3};"
        : "+f"(d[0]),"+f"(d[1]),"+f"(d[2]),"+f"(d[3])
        : "r"(a[0]),"r"(a[1]),"r"(a[2]),"r"(a[3]), "r"(b[0]),"r"(b[1]));
}
__device__ __forceinline__ float gelu_exact(float x){
    return 0.5f * x * (1.f + erff(x * 0.70710678118654752f));
}
__device__ __forceinline__ float wred_sum(float v){
#pragma unroll
    for (int o = 16; o > 0; o >>= 1) v += __shfl_xor_sync(~0u, v, o);
    return v;
}

// ---------------------------------------------------------------------------
// fp16 mma.sync GEMM 128x128 (qkv / Wi).
// mode bits: 1 = gelu, 2 = fp16 output, 4 = qkv bias select
// ---------------------------------------------------------------------------
#define GBM 128
#define GBN 128
#define GBK 32
#define NSTG 3
#define STG  (2*GBM*80)              // 20480
#define GEMM_SMEM (NSTG*STG)

__device__ __forceinline__ void load_chunk16(const __half* __restrict__ A, const __half* __restrict__ BT,
                                             int K, int bm, int bn, int c, uint32_t stage)
{
    int t = threadIdx.x;
    const __half* asrc = A  + (size_t)bm*K + (size_t)c*GBK;
    const __half* bsrc = BT + (size_t)bn*K + (size_t)c*GBK;
#pragma unroll
    for (int i = 0; i < 4; i++){
        int idx = i*128 + t;
        int row = idx >> 2, seg = idx & 3;
        CP_ASYNC16(stage + row*80 + seg*16, asrc + (size_t)row*K + seg*8);
    }
#pragma unroll
    for (int i = 0; i < 4; i++){
        int idx = i*128 + t;
        int row = idx >> 2, seg = idx & 3;
        CP_ASYNC16(stage + GBM*80 + row*80 + seg*16, bsrc + (size_t)row*K + seg*8);
    }
    CP_COMMIT();
}

__global__ __launch_bounds__(128, 2)
void gemm_tc(const __half* __restrict__ A, const __half* __restrict__ BT,
             const float* __restrict__ bias, const float* __restrict__ bK,
             const float* __restrict__ bV, void* __restrict__ Cv,
             int K, int N, int mode)
{
    extern __shared__ char smem[];
    int t = threadIdx.x;
    int wid = t >> 5, lane = t & 31;
    int grp = lane >> 2, q4 = lane & 3;
    int mw = (wid & 1) * 64, nw = (wid >> 1) * 64;
    int bm = blockIdx.y * GBM, bn = blockIdx.x * GBN;

    int lm = lane >> 3, lr = lane & 7;
    uint32_t aoff = (uint32_t)(((lm & 1)*8 + lr)*80 + (lm >> 1)*16);
    uint32_t boff = (uint32_t)(((lm >> 1)*8 + lr)*80 + (lm & 1)*16);

    float acc[4][8][4];
#pragma unroll
    for (int mi = 0; mi < 4; mi++)
#pragma unroll
        for (int ni = 0; ni < 8; ni++)
#pragma unroll
            for (int r = 0; r < 4; r++) acc[mi][ni][r] = 0.f;

    uint32_t sb = smem_u32(smem);
    const int NC = K / GBK;

    load_chunk16(A, BT, K, bm, bn, 0, sb);
    load_chunk16(A, BT, K, bm, bn, 1, sb + STG);

    for (int c = 0; c < NC; c++){
        int slot = c % NSTG;
        if (c + 1 < NC) { asm volatile("cp.async.wait_group 1;" ::: "memory"); }
        else            { asm volatile("cp.async.wait_group 0;" ::: "memory"); }
        __syncthreads();
        if (c + 2 < NC)
            load_chunk16(A, BT, K, bm, bn, c + 2, sb + ((c+2)%NSTG)*STG);

        uint32_t As_b = sb + slot*STG;
        uint32_t Bs_b = As_b + GBM*80;
#pragma unroll
        for (int ks = 0; ks < 2; ks++){
            uint32_t kb = ks*32;
            uint32_t af[4][4], bf[8][2];
#pragma unroll
            for (int mi = 0; mi < 4; mi++)
                LDSM4(af[mi], As_b + (mw + mi*16)*80 + aoff + kb);
#pragma unroll
            for (int p = 0; p < 4; p++){
                uint32_t r[4];
                LDSM4(r, Bs_b + (nw + p*16)*80 + boff + kb);
                bf[2*p][0] = r[0]; bf[2*p][1] = r[1];
                bf[2*p+1][0] = r[2]; bf[2*p+1][1] = r[3];
            }
#pragma unroll
            for (int mi = 0; mi < 4; mi++)
#pragma unroll
                for (int ni = 0; ni < 8; ni++)
                    mma_f16(acc[mi][ni], af[mi], bf[ni]);
        }
    }

    const float* bp = bias;
    int coff = 0;
    if (mode & 4){
        int sel = bn / HID;
        bp = (sel == 0) ? bias : (sel == 1 ? bK : bV);
        coff = sel * HID;
    }

    float* Cf = (float*)Cv;
    __half* Ch = (__half*)Cv;
#pragma unroll
    for (int mi = 0; mi < 4; mi++){
        int r0 = bm + mw + mi*16 + grp;
#pragma unroll
        for (int ni = 0; ni < 8; ni++){
            int col = bn + nw + ni*8 + 2*q4;
            float bx = bp[col - coff], by = bp[col + 1 - coff];
            float a0 = acc[mi][ni][0] + bx, a1 = acc[mi][ni][1] + by;
            float a2 = acc[mi][ni][2] + bx, a3 = acc[mi][ni][3] + by;
            if (mode & 1){
                a0 = gelu_exact(a0); a1 = gelu_exact(a1);
                a2 = gelu_exact(a2); a3 = gelu_exact(a3);
            }
            if (mode & 2){
                *(__half2*)&Ch[(size_t)r0*N + col]     = __floats2half2_rn(a0, a1);
                *(__half2*)&Ch[(size_t)(r0+8)*N + col] = __floats2half2_rn(a2, a3);
            } else {
                *(float2*)&Cf[(size_t)r0*N + col]     = make_float2(a0, a1);
                *(float2*)&Cf[(size_t)(r0+8)*N + col] = make_float2(a2, a3);
            }
        }
    }
}

// ---------------------------------------------------------------------------
// fp16 GEMM 128x64 tile, 3 CTAs/SM (for N=768 GEMMs: better wave packing).
// Warp tile 64x32. fp16 output only.
// ---------------------------------------------------------------------------
#define STG64 ((GBM + 64)*80)        // 15360
#define GEMM64_SMEM (NSTG*STG64)     // 46080

__device__ __forceinline__ void load_chunk64(const __half* __restrict__ A, const __half* __restrict__ BT,
                                             int K, int bm, int bn, int c, uint32_t stage)
{
    int t = threadIdx.x;
    const __half* asrc = A  + (size_t)bm*K + (size_t)c*GBK;
    const __half* bsrc = BT + (size_t)bn*K + (size_t)c*GBK;
#pragma unroll
    for (int i = 0; i < 4; i++){
        int idx = i*128 + t;
        int row = idx >> 2, seg = idx & 3;
        CP_ASYNC16(stage + row*80 + seg*16, asrc + (size_t)row*K + seg*8);
    }
#pragma unroll
    for (int i = 0; i < 2; i++){
        int idx = i*128 + t;               // 0..255
        int row = idx >> 2, seg = idx & 3;
        CP_ASYNC16(stage + GBM*80 + row*80 + seg*16, bsrc + (size_t)row*K + seg*8);
    }
    CP_COMMIT();
}

__global__ __launch_bounds__(128, 3)
void gemm_tc64(const __half* __restrict__ A, const __half* __restrict__ BT,
               const float* __restrict__ bias, __half* __restrict__ C,
               int K, int N, int mode)
{
    extern __shared__ char smem[];
    int t = threadIdx.x;
    int wid = t >> 5, lane = t & 31;
    int grp = lane >> 2, q4 = lane & 3;
    int mw = (wid & 1) * 64, nw = (wid >> 1) * 32;
    int bm = blockIdx.y * GBM, bn = blockIdx.x * 64;

    int lm = lane >> 3, lr = lane & 7;
    uint32_t aoff = (uint32_t)(((lm & 1)*8 + lr)*80 + (lm >> 1)*16);
    uint32_t boff = (uint32_t)(((lm >> 1)*8 + lr)*80 + (lm & 1)*16);

    float acc[4][4][4];
#pragma unroll
    for (int mi = 0; mi < 4; mi++)
#pragma unroll
        for (int ni = 0; ni < 4; ni++)
#pragma unroll
            for (int r = 0; r < 4; r++) acc[mi][ni][r] = 0.f;

    uint32_t sb = smem_u32(smem);
    const int NC = K / GBK;

    load_chunk64(A, BT, K, bm, bn, 0, sb);
    load_chunk64(A, BT, K, bm, bn, 1, sb + STG64);

    for (int c = 0; c < NC; c++){
        int slot = c % NSTG;
        if (c + 1 < NC) { asm volatile("cp.async.wait_group 1;" ::: "memory"); }
        else            { asm volatile("cp.async.wait_group 0;" ::: "memory"); }
        __syncthreads();
        if (c + 2 < NC)
            load_chunk64(A, BT, K, bm, bn, c + 2, sb + ((c+2)%NSTG)*STG64);

        uint32_t As_b = sb + slot*STG64;
        uint32_t Bs_b = As_b + GBM*80;
#pragma unroll
        for (int ks = 0; ks < 2; ks++){
            uint32_t kb = ks*32;
            uint32_t af[4][4], bf[4][2];
#pragma unroll
            for (int mi = 0; mi < 4; mi++)
                LDSM4(af[mi], As_b + (mw + mi*16)*80 + aoff + kb);
#pragma unroll
            for (int p = 0; p < 2; p++){
                uint32_t r[4];
                LDSM4(r, Bs_b + (nw + p*16)*80 + boff + kb);
                bf[2*p][0] = r[0]; bf[2*p][1] = r[1];
                bf[2*p+1][0] = r[2]; bf[2*p+1][1] = r[3];
            }
#pragma unroll
            for (int mi = 0; mi < 4; mi++)
#pragma unroll
                for (int ni = 0; ni < 4; ni++)
                    mma_f16(acc[mi][ni], af[mi], bf[ni]);
        }
    }

#pragma unroll
    for (int mi = 0; mi < 4; mi++){
        int r0 = bm + mw + mi*16 + grp;
#pragma unroll
        for (int ni = 0; ni < 4; ni++){
            int col = bn + nw + ni*8 + 2*q4;
            float bx = bias[col], by = bias[col+1];
            float a0 = acc[mi][ni][0] + bx, a1 = acc[mi][ni][1] + by;
            float a2 = acc[mi][ni][2] + bx, a3 = acc[mi][ni][3] + by;
            if (mode & 1){
                a0 = gelu_exact(a0); a1 = gelu_exact(a1);
                a2 = gelu_exact(a2); a3 = gelu_exact(a3);
            }
            *(__half2*)&C[(size_t)r0*N + col]     = __floats2half2_rn(a0, a1);
            *(__half2*)&C[(size_t)(r0+8)*N + col] = __floats2half2_rn(a2, a3);
        }
    }
}

// ---------------------------------------------------------------------------
// Weight transposes to fp16
// ---------------------------------------------------------------------------
__global__ __launch_bounds__(256)
void transpose_h(const float* __restrict__ in, __half* __restrict__ out,
                 int R, int C, size_t outStride)
{
    __shared__ float tile[32][33];
    const float* src = in  + (size_t)blockIdx.z * R * C;
    __half*      dst = out + (size_t)blockIdx.z * outStride;
    int r0 = blockIdx.y*32, c0 = blockIdx.x*32;
    int tx = threadIdx.x & 31, ty = threadIdx.x >> 5;
#pragma unroll
    for (int i = 0; i < 4; i++)
        tile[ty + i*8][tx] = src[(size_t)(r0 + ty + i*8)*C + c0 + tx];
    __syncthreads();
#pragma unroll
    for (int i = 0; i < 4; i++)
        dst[(size_t)(c0 + ty + i*8)*R + r0 + tx] = __float2half(tile[tx][ty + i*8]);
}

__global__ __launch_bounds__(256)
void transpose_qkv(const float* __restrict__ Wq, const float* __restrict__ Wk,
                   const float* __restrict__ Wv, __half* __restrict__ out)
{
    __shared__ float tile[32][33];
    int z = blockIdx.z;
    int m = z / NL, l = z % NL;
    const float* src = (m == 0 ? Wq : (m == 1 ? Wk : Wv)) + (size_t)l*HID*HID;
    __half* dst = out + (size_t)l*3*HID*HID + (size_t)m*HID*HID;
    int r0 = blockIdx.y*32, c0 = blockIdx.x*32;
    int tx = threadIdx.x & 31, ty = threadIdx.x >> 5;
#pragma unroll
    for (int i = 0; i < 4; i++)
        tile[ty + i*8][tx] = src[(size_t)(r0 + ty + i*8)*HID + c0 + tx];
    __syncthreads();
#pragma unroll
    for (int i = 0; i < 4; i++)
        dst[(size_t)(c0 + ty + i*8)*HID + r0 + tx] = __float2half(tile[tx][ty + i*8]);
}

// ---------------------------------------------------------------------------
// Warp-per-row LayerNorm kernels
// ---------------------------------------------------------------------------
__global__ __launch_bounds__(256)
void embed_ln_kernel(const float* __restrict__ emb, const float* __restrict__ pos,
                     const float* __restrict__ tok, const float* __restrict__ gam,
                     const float* __restrict__ bet, float* __restrict__ h,
                     __half* __restrict__ h16)
{
    int w = threadIdx.x >> 5, lane = threadIdx.x & 31;
    int r = blockIdx.x*8 + w;
    int s = r & (SS-1);
    const float* er = emb + (size_t)r*HID;
    const float* pr = pos + (size_t)(s+1)*HID;

    float x[24];
    float sum = 0.f;
#pragma unroll
    for (int i = 0; i < 6; i++){
        int c = i*128 + lane*4;
        float4 e = *(const float4*)&er[c];
        float4 p = *(const float4*)&pr[c];
        float4 tk = *(const float4*)&tok[c];
        x[i*4+0] = e.x + p.x + tk.x;
        x[i*4+1] = e.y + p.y + tk.y;
        x[i*4+2] = e.z + p.z + tk.z;
        x[i*4+3] = e.w + p.w + tk.w;
        sum += x[i*4+0] + x[i*4+1] + x[i*4+2] + x[i*4+3];
    }
    float mean = wred_sum(sum) * (1.f/HID);
    float vs = 0.f;
#pragma unroll
    for (int i = 0; i < 24; i++){ float d = x[i] - mean; vs += d*d; }
    float inv = rsqrtf(wred_sum(vs) * (1.f/HID) + 1e-12f);

    float* hr = h + (size_t)r*HID;
    __half* h16r = h16 + (size_t)r*HID;
#pragma unroll
    for (int i = 0; i < 6; i++){
        int c = i*128 + lane*4;
        float4 g = *(const float4*)&gam[c];
        float4 b = *(const float4*)&bet[c];
        float4 o;
        o.x = (x[i*4+0] - mean)*inv*g.x + b.x;
        o.y = (x[i*4+1] - mean)*inv*g.y + b.y;
        o.z = (x[i*4+2] - mean)*inv*g.z + b.z;
        o.w = (x[i*4+3] - mean)*inv*g.w + b.w;
        *(float4*)&hr[c] = o;
        *(__half2*)&h16r[c]   = __floats2half2_rn(o.x, o.y);
        *(__half2*)&h16r[c+2] = __floats2half2_rn(o.z, o.w);
    }
}

__global__ __launch_bounds__(256)
void add_ln_kernel(const float* __restrict__ hin, const __half* __restrict__ tin,
                   const float* __restrict__ gam, const float* __restrict__ bet,
                   float* __restrict__ hout, __half* __restrict__ h16)
{
    int w = threadIdx.x >> 5, lane = threadIdx.x & 31;
    int r = blockIdx.x*8 + w;
    const float* ar = hin + (size_t)r*HID;
    const __half* br = tin + (size_t)r*HID;

    float x[24];
    float sum = 0.f;
#pragma unroll
    for (int i = 0; i < 6; i++){
        int c = i*128 + lane*4;
        float4 a = *(const float4*)&ar[c];
        __half2 b0 = *(const __half2*)&br[c];
        __half2 b1 = *(const __half2*)&br[c+2];
        float2 f0 = __half22float2(b0), f1 = __half22float2(b1);
        x[i*4+0] = a.x + f0.x; x[i*4+1] = a.y + f0.y;
        x[i*4+2] = a.z + f1.x; x[i*4+3] = a.w + f1.y;
        sum += x[i*4+0] + x[i*4+1] + x[i*4+2] + x[i*4+3];
    }
    float mean = wred_sum(sum) * (1.f/HID);
    float vs = 0.f;
#pragma unroll
    for (int i = 0; i < 24; i++){ float d = x[i] - mean; vs += d*d; }
    float inv = rsqrtf(wred_sum(vs) * (1.f/HID) + 1e-12f);

    float* hr = hout + (size_t)r*HID;
    __half* h16r = h16 + (size_t)r*HID;
#pragma unroll
    for (int i = 0; i < 6; i++){
        int c = i*128 + lane*4;
        float4 g = *(const float4*)&gam[c];
        float4 b = *(const float4*)&bet[c];
        float4 o;
        o.x = (x[i*4+0] - mean)*inv*g.x + b.x;
        o.y = (x[i*4+1] - mean)*inv*g.y + b.y;
        o.z = (x[i*4+2] - mean)*inv*g.z + b.z;
        o.w = (x[i*4+3] - mean)*inv*g.w + b.w;
        *(float4*)&hr[c] = o;
        *(__half2*)&h16r[c]   = __floats2half2_rn(o.x, o.y);
        *(__half2*)&h16r[c+2] = __floats2half2_rn(o.z, o.w);
    }
}

__global__ __launch_bounds__(256)
void final_kernel(const float* __restrict__ h, const float* __restrict__ Wp,
                  const float* __restrict__ bp, float* __restrict__ out)
{
    int w = threadIdx.x >> 5, lane = threadIdx.x & 31;
    int r = blockIdx.x*8 + w;
    const float* hr = h + (size_t)r*HID;
    float sum = 0.f;
#pragma unroll
    for (int i = 0; i < 6; i++){
        int c = i*128 + lane*4;
        float4 a = *(const float4*)&hr[c];
        float4 b = *(const float4*)&Wp[c];
        sum += a.x*b.x + a.y*b.y + a.z*b.z + a.w*b.w;
    }
    sum = wred_sum(sum);
    if (lane == 0) out[r] = 1.f / (1.f + expf(-(sum + bp[0])));
}

// ---------------------------------------------------------------------------
// fp16 tensor-core sliding-window attention.
// ---------------------------------------------------------------------------
#define QT    32
#define KW    320
#define KVSH  72
#define SSTR  328
#define SPSTR 328
#define SQ_B   0
#define SKV_B  (QT*KVSH*2)
#define SS_B   (SKV_B + KW*KVSH*2)
#define SP_B   (SS_B + QT*SSTR*4)
#define SM_B   (SP_B + QT*SPSTR*2)
#define ATT_SMEM (SM_B + KW)

__global__ __launch_bounds__(256)
void attn_kernel(const __half* __restrict__ qkv16, const int* __restrict__ km,
                 __half* __restrict__ ag16)
{
    int qt   = blockIdx.x;
    int head = blockIdx.y;
    int b    = blockIdx.z;
    int q0   = qt * QT;
    int kbase = q0 - AW;

    extern __shared__ char smraw[];
    __half* sQ  = (__half*)(smraw + SQ_B);
    __half* sKV = (__half*)(smraw + SKV_B);
    float*  sS  = (float*)(smraw + SS_B);
    __half* sP  = (__half*)(smraw + SP_B);
    uint8_t* sM = (uint8_t*)(smraw + SM_B);
    uint32_t skv_b = smem_u32(sKV);

    int t = threadIdx.x;
    int wid = t >> 5, lane = t & 31;
    int grp = lane >> 2, q4 = lane & 3;
    const size_t rstr = 3*HID;
    const __half* base_b = qkv16 + (size_t)b*SS*rstr;

    {
        int row = t >> 3, seg = t & 7;
        uint4 qv4 = *(const uint4*)&base_b[(size_t)(q0 + row)*rstr + head*HD + seg*8];
        __half2 sc = __half2half2(__float2half(0.125f));
        __half2* q2 = (__half2*)&qv4;
        q2[0] = __hmul2(q2[0], sc); q2[1] = __hmul2(q2[1], sc);
        q2[2] = __hmul2(q2[2], sc); q2[3] = __hmul2(q2[3], sc);
        *(uint4*)&sQ[row*KVSH + seg*8] = qv4;
    }

    {
        const __half* ksrc = base_b + HID + head*HD;
#pragma unroll
        for (int i = 0; i < 10; i++){
            int idx = i*256 + t;
            int row = idx >> 3, seg = idx & 7;
            int jg = kbase + row;
            uint32_t nb = (jg >= 0 && jg < SS) ? 16u : 0u;
            int jc = jg < 0 ? 0 : (jg >= SS ? SS-1 : jg);
            CP_ASYNC16Z(skv_b + row*(KVSH*2) + seg*16, ksrc + (size_t)jc*rstr + seg*8, nb);
        }
        CP_COMMIT();
        if (t < KW){
            int jg = kbase + t;
            sM[t] = (jg >= 0 && jg < SS && km[b*SS + jg] != 0) ? 1 : 0;
        }
    }
    asm volatile("cp.async.wait_group 0;" ::: "memory");
    __syncthreads();

    {
        float acc[2][5][4];
#pragma unroll
        for (int mi = 0; mi < 2; mi++)
#pragma unroll
            for (int nt = 0; nt < 5; nt++)
#pragma unroll
                for (int r = 0; r < 4; r++) acc[mi][nt][r] = 0.f;

#pragma unroll
        for (int ks = 0; ks < 4; ks++){
            int k0 = ks*16;
            uint32_t af[2][4];
#pragma unroll
            for (int mi = 0; mi < 2; mi++){
                int bb = (mi*16 + grp)*KVSH + k0 + 2*q4;
                af[mi][0] = *(const uint32_t*)&sQ[bb];
                af[mi][1] = *(const uint32_t*)&sQ[bb + 8*KVSH];
                af[mi][2] = *(const uint32_t*)&sQ[bb + 8];
                af[mi][3] = *(const uint32_t*)&sQ[bb + 8*KVSH + 8];
            }
#pragma unroll
            for (int nt = 0; nt < 5; nt++){
                int n0 = wid*40 + nt*8;
                uint32_t bf[2];
                int bb = (n0 + grp)*KVSH + k0 + 2*q4;
                bf[0] = *(const uint32_t*)&sKV[bb];
                bf[1] = *(const uint32_t*)&sKV[bb + 8];
                mma_f16(acc[0][nt], af[0], bf);
                mma_f16(acc[1][nt], af[1], bf);
            }
        }
#pragma unroll
        for (int mi = 0; mi < 2; mi++){
            int r0 = mi*16 + grp;
#pragma unroll
            for (int nt = 0; nt < 5; nt++){
                int col = wid*40 + nt*8 + 2*q4;
                *(float2*)&sS[r0*SSTR + col]     = make_float2(acc[mi][nt][0], acc[mi][nt][1]);
                *(float2*)&sS[(r0+8)*SSTR + col] = make_float2(acc[mi][nt][2], acc[mi][nt][3]);
            }
        }
    }
    __syncthreads();

    {
        const __half* vsrc = base_b + 2*HID + head*HD;
#pragma unroll
        for (int i = 0; i < 10; i++){
            int idx = i*256 + t;
            int row = idx >> 3, seg = idx & 7;
            int jg = kbase + row;
            uint32_t nb = (jg >= 0 && jg < SS) ? 16u : 0u;
            int jc = jg < 0 ? 0 : (jg >= SS ? SS-1 : jg);
            CP_ASYNC16Z(skv_b + row*(KVSH*2) + seg*16, vsrc + (size_t)jc*rstr + seg*8, nb);
        }
        CP_COMMIT();
    }

    {
#pragma unroll
        for (int rr = 0; rr < 4; rr++){
            int qr = wid*4 + rr;
            float mx = -1e30f;
            for (int j = lane; j < KW; j += 32){
                bool ok = (j >= qr) && (j <= qr + 2*AW) && sM[j];
                float sc = ok ? sS[qr*SSTR + j] : -1e30f;
                sS[qr*SSTR + j] = sc;
                mx = fmaxf(mx, sc);
            }
#pragma unroll
            for (int o = 16; o > 0; o >>= 1) mx = fmaxf(mx, __shfl_xor_sync(~0u, mx, o));
            float sum = 0.f;
            for (int j = lane; j < KW; j += 32){
                float p = __expf(sS[qr*SSTR + j] - mx);
                sS[qr*SSTR + j] = p; sum += p;
            }
#pragma unroll
            for (int o = 16; o > 0; o >>= 1) sum += __shfl_xor_sync(~0u, sum, o);
            float inv = 1.f / sum;
            for (int j = lane; j < KW; j += 32)
                sP[qr*SPSTR + j] = __float2half(sS[qr*SSTR + j] * inv);
        }
    }
    asm volatile("cp.async.wait_group 0;" ::: "memory");
    __syncthreads();

    {
        int n0 = wid*8;
        float acc[2][4];
#pragma unroll
        for (int mi = 0; mi < 2; mi++)
#pragma unroll
            for (int r = 0; r < 4; r++) acc[mi][r] = 0.f;

#pragma unroll 5
        for (int ks = 0; ks < 20; ks++){
            int k0 = ks*16;
            uint32_t af[2][4], bf[2];
#pragma unroll
            for (int mi = 0; mi < 2; mi++){
                int bb = (mi*16 + grp)*SPSTR + k0 + 2*q4;
                af[mi][0] = *(const uint32_t*)&sP[bb];
                af[mi][1] = *(const uint32_t*)&sP[bb + 8*SPSTR];
                af[mi][2] = *(const uint32_t*)&sP[bb + 8];
                af[mi][3] = *(const uint32_t*)&sP[bb + 8*SPSTR + 8];
            }
            LDSM2T(bf, skv_b + (uint32_t)(k0 + (lane & 15))*(KVSH*2) + n0*2);
            mma_f16(acc[0], af[0], bf);
            mma_f16(acc[1], af[1], bf);
        }
#pragma unroll
        for (int mi = 0; mi < 2; mi++){
            int r0 = q0 + mi*16 + grp;
            int col = head*HD + n0 + 2*q4;
            *(__half2*)&ag16[((size_t)(b*SS + r0))*HID + col]     = __floats2half2_rn(acc[mi][0], acc[mi][1]);
            *(__half2*)&ag16[((size_t)(b*SS + r0 + 8))*HID + col] = __floats2half2_rn(acc[mi][2], acc[mi][3]);
        }
    }
}

// ---------------------------------------------------------------------------
// Host launcher
// ---------------------------------------------------------------------------
extern "C" void kernel_launch(void* const* d_in, const int* in_sizes, int n_in,
                              void* d_out, int out_size)
{
    (void)in_sizes; (void)n_in;
    const float* emb   = (const float*)d_in[0];
    const int*   amask = (const int*)  d_in[1];
    const float* pos   = (const float*)d_in[2];
    const float* tok   = (const float*)d_in[3];
    const float* eg    = (const float*)d_in[4];
    const float* eb    = (const float*)d_in[5];
    const float* Wq    = (const float*)d_in[6];
    const float* bq    = (const float*)d_in[7];
    const float* Wk    = (const float*)d_in[8];
    const float* bk    = (const float*)d_in[9];
    const float* Wv    = (const float*)d_in[10];
    const float* bv    = (const float*)d_in[11];
    const float* Wo    = (const float*)d_in[12];
    const float* bo    = (const float*)d_in[13];
    const float* ln1g  = (const float*)d_in[14];
    const float* ln1b  = (const float*)d_in[15];
    const float* Wi    = (const float*)d_in[16];
    const float* bi    = (const float*)d_in[17];
    const float* Wf    = (const float*)d_in[18];
    const float* bf    = (const float*)d_in[19];
    const float* ln2g  = (const float*)d_in[20];
    const float* ln2b  = (const float*)d_in[21];
    const float* Wp    = (const float*)d_in[22];
    const float* bp    = (const float*)d_in[23];

    float* scratch = nullptr;
    cudaGetSymbolAddress((void**)&scratch, g_scratch);
    float*  h     = scratch;
    __half* tmp16 = (__half*)(scratch + 1*(size_t)ACT);
    __half* qkv16 = (__half*)(scratch + 2*(size_t)ACT);
    __half* h16   = (__half*)(scratch + 4*(size_t)ACT);
    __half* a16   = (__half*)(scratch + 4*(size_t)ACT + ACT/2);
    __half* ffn16 = (__half*)(scratch + 5*(size_t)ACT);
    __half* WqkvT = (__half*)(scratch + 7*(size_t)ACT);
    __half* WoT   = WqkvT + 3*(size_t)WT_SM;
    __half* WiT   = WoT   + (size_t)WT_SM;
    __half* WfT   = WiT   + (size_t)WT_LG;

    cudaFuncSetAttribute(gemm_tc, cudaFuncAttributeMaxDynamicSharedMemorySize, GEMM_SMEM);
    cudaFuncSetAttribute(gemm_tc64, cudaFuncAttributeMaxDynamicSharedMemorySize, GEMM64_SMEM);
    cudaFuncSetAttribute(attn_kernel, cudaFuncAttributeMaxDynamicSharedMemorySize, ATT_SMEM);

    const size_t LSTR = (size_t)3*HID*HID;

    embed_ln_kernel<<<ROWS/8, 256>>>(emb, pos, tok, eg, eb, h, h16);
    transpose_qkv<<<dim3(HID/32, HID/32, 3*NL), 256>>>(Wq, Wk, Wv, WqkvT);
    transpose_h<<<dim3(HID/32, HID/32, NL), 256>>>(Wo, WoT, HID, HID, (size_t)HID*HID);
    transpose_h<<<dim3(4*HID/32, HID/32, NL), 256>>>(Wi, WiT, HID, 4*HID, (size_t)4*HID*HID);
    transpose_h<<<dim3(HID/32, 4*HID/32, NL), 256>>>(Wf, WfT, 4*HID, HID, (size_t)4*HID*HID);

    dim3 gqkv(3*HID/GBN, ROWS/GBM);    // (18, 64)
    dim3 g768n64(HID/64, ROWS/GBM);    // (12, 64) for gemm_tc64
    dim3 g3072(4*HID/GBN, ROWS/GBM);   // (24, 64)
    dim3 gattn(SS/QT, NH, BB);

    for (int l = 0; l < NL; l++) {
        const size_t wofs  = (size_t)l * HID * HID;
        const size_t bofs  = (size_t)l * HID;
        const size_t wlofs = (size_t)l * HID * 4*HID;
        const size_t blofs = (size_t)l * 4*HID;

        gemm_tc<<<gqkv, 128, GEMM_SMEM>>>(h16, WqkvT + l*LSTR, bq + bofs, bk + bofs, bv + bofs,
                                          qkv16, HID, 3*HID, 2|4);

        attn_kernel<<<gattn, 256, ATT_SMEM>>>(qkv16, amask, a16);

        gemm_tc64<<<g768n64, 128, GEMM64_SMEM>>>(a16, WoT + wofs, bo + bofs, tmp16, HID, HID, 2);
        add_ln_kernel<<<ROWS/8, 256>>>(h, tmp16, ln1g + bofs, ln1b + bofs, h, h16);

        gemm_tc<<<g3072, 128, GEMM_SMEM>>>(h16, WiT + wlofs, bi + blofs, bi, bi, ffn16, HID, 4*HID, 3);
        gemm_tc64<<<g768n64, 128, GEMM64_SMEM>>>(ffn16, WfT + wlofs, bf + bofs, tmp16, 4*HID, HID, 2);
        add_ln_kernel<<<ROWS/8, 256>>>(h, tmp16, ln2g + bofs, ln2b + bofs, h, h16);
    }

    final_kernel<<<ROWS/8, 256>>>(h, Wp, bp, (float*)d_out);
    (void)out_size;
}